// round 4
// baseline (speedup 1.0000x reference)
#include <cuda_runtime.h>
#include <cstdint>

static const int NN = 50000;
static const int NE = 600000;

// ---------------- scratch (no allocations; referenced only from device code) ----------------
__device__ float g_h0[NN * 128];
__device__ float g_h1[NN * 128];
__device__ float g_y[NN * 128];
__device__ float g_invdeg[NN];
__device__ int   g_count[NN];
__device__ int   g_offs[NN + 1];
__device__ int   g_cursor[NN];
__device__ int   g_srcs[NE];
__device__ int   g_is64;   // 1 if edge_index stored as int64, else int32

__device__ __forceinline__ const float* sel_in(int SEL, const float* ext) {
    if (SEL == 1) return g_h0;
    if (SEL == 2) return g_h1;
    if (SEL == 3) return g_y;
    return ext;
}
__device__ __forceinline__ float* sel_out(int SEL, float* ext) {
    if (SEL == 1) return g_h0;
    if (SEL == 2) return g_h1;
    if (SEL == 3) return g_y;
    return ext;
}

// read edge index e (0..2*NE-1) robustly under either storage dtype
__device__ __forceinline__ int edge_at(const void* ei, int i) {
    if (g_is64) {
        long long v = ((const long long*)ei)[i];
        return (int)v;
    }
    return ((const int*)ei)[i];
}

// ---------------- dtype probe ----------------
__global__ void detect_kernel(const void* ei) {
    // assume int64; if any value out of [0, NN), it's really int32
    if (blockIdx.x == 0 && threadIdx.x == 0) g_is64 = 1;
    __threadfence();
    int i = blockIdx.x * blockDim.x + threadIdx.x;
    if (i < 2 * NE) {
        long long v = ((const long long*)ei)[i];
        if (v < 0 || v >= NN) atomicExch(&g_is64, 0);
    }
}

// ---------------- CSR build ----------------
__global__ void zero_count_kernel() {
    int i = blockIdx.x * blockDim.x + threadIdx.x;
    if (i < NN) g_count[i] = 0;
}

__global__ void hist_kernel(const void* ei) {
    int i = blockIdx.x * blockDim.x + threadIdx.x;
    if (i < NE) {
        int d = edge_at(ei, NE + i);           // dst = edge_index[1][i]
        d = min(max(d, 0), NN - 1);            // safety clamp
        atomicAdd(&g_count[d], 1);
    }
}

__global__ void scan_kernel() {
    __shared__ int partial[1024];
    const int T = 1024;
    int t = threadIdx.x;
    const int chunk = (NN + T - 1) / T;  // 49
    int lo = t * chunk;
    int hi = min(lo + chunk, NN);
    int s = 0;
    for (int i = lo; i < hi; i++) s += g_count[i];
    partial[t] = s;
    __syncthreads();
    for (int d = 1; d < T; d <<= 1) {
        int v = partial[t];
        int u = (t >= d) ? partial[t - d] : 0;
        __syncthreads();
        partial[t] = v + u;
        __syncthreads();
    }
    int base = (t == 0) ? 0 : partial[t - 1];
    for (int i = lo; i < hi; i++) {
        int c = g_count[i];
        g_offs[i]   = base;
        g_cursor[i] = base;
        g_invdeg[i] = 1.0f / fmaxf((float)c, 1.0f);
        base += c;
    }
    if (t == T - 1) g_offs[NN] = base;
}

__global__ void fill_kernel(const void* ei) {
    int i = blockIdx.x * blockDim.x + threadIdx.x;
    if (i < NE) {
        int s = edge_at(ei, i);                // src = edge_index[0][i]
        int d = edge_at(ei, NE + i);           // dst = edge_index[1][i]
        s = min(max(s, 0), NN - 1);
        d = min(max(d, 0), NN - 1);
        int p = atomicAdd(&g_cursor[d], 1);
        g_srcs[p] = s;
    }
}

// ---------------- SGEMM: C[M,BN] = A[M,128] @ W[128,BN] (+bias) ----------------
template <int BN, int ASEL, int CSEL>
__global__ __launch_bounds__(BN * 2) void sgemm_kernel(
    const float* __restrict__ Aext, const float* __restrict__ W,
    const float* __restrict__ bias, float* __restrict__ Cext, int M)
{
    const float* A = sel_in(ASEL, Aext);
    float*       C = sel_out(CSEL, Cext);

    const int K = 128, BM = 128, BK = 8, TM = 8, TN = 8;
    const int TXG = BN / TN;        // 16 (BN=128) or 8 (BN=64)
    const int THREADS = TXG * 16;   // 256 or 128
    __shared__ float As[BK][BM];    // transposed A tile
    __shared__ float Ws[BK][BN];

    int tid = threadIdx.x;
    int tx = tid % TXG;
    int ty = tid / TXG;
    int row0 = blockIdx.x * BM;

    float acc[TM][TN];
#pragma unroll
    for (int i = 0; i < TM; i++)
#pragma unroll
        for (int j = 0; j < TN; j++) acc[i][j] = 0.0f;

    for (int k0 = 0; k0 < K; k0 += BK) {
#pragma unroll
        for (int i = tid; i < BM * BK / 4; i += THREADS) {
            int m  = i / (BK / 4);
            int kf = i % (BK / 4);
            float4 v = make_float4(0.f, 0.f, 0.f, 0.f);
            int gr = row0 + m;
            if (gr < M) v = *(const float4*)(A + (size_t)gr * K + k0 + kf * 4);
            As[kf * 4 + 0][m] = v.x;
            As[kf * 4 + 1][m] = v.y;
            As[kf * 4 + 2][m] = v.z;
            As[kf * 4 + 3][m] = v.w;
        }
#pragma unroll
        for (int i = tid; i < BK * BN / 4; i += THREADS) {
            int kk = i / (BN / 4);
            int nf = i % (BN / 4);
            *(float4*)&Ws[kk][nf * 4] =
                *(const float4*)(W + (size_t)(k0 + kk) * BN + nf * 4);
        }
        __syncthreads();

#pragma unroll
        for (int kk = 0; kk < BK; kk++) {
            float a[TM], b[TN];
#pragma unroll
            for (int i = 0; i < TM; i++) a[i] = As[kk][ty * TM + i];
#pragma unroll
            for (int j = 0; j < TN; j++) b[j] = Ws[kk][tx * TN + j];
#pragma unroll
            for (int i = 0; i < TM; i++)
#pragma unroll
                for (int j = 0; j < TN; j++)
                    acc[i][j] = fmaf(a[i], b[j], acc[i][j]);
        }
        __syncthreads();
    }

#pragma unroll
    for (int i = 0; i < TM; i++) {
        int gr = row0 + ty * TM + i;
        if (gr < M) {
#pragma unroll
            for (int j = 0; j < TN; j += 4) {
                int c = tx * TN + j;
                float4 v;
                v.x = acc[i][j + 0];
                v.y = acc[i][j + 1];
                v.z = acc[i][j + 2];
                v.w = acc[i][j + 3];
                if (bias) {
                    v.x += bias[c + 0]; v.y += bias[c + 1];
                    v.z += bias[c + 2]; v.w += bias[c + 3];
                }
                *(float4*)(C + (size_t)gr * BN + c) = v;
            }
        }
    }
}

// ---------------- fused aggregate: out = maybe_relu(out + inv_deg * sum_{e: dst=n} g_y[src_e]) ----------------
template <int D, bool RELU, int OSEL>
__global__ void aggregate_kernel(float* __restrict__ Oext)
{
    float* out = sel_out(OSEL, Oext);
    const float4* yv = (const float4*)g_y;

    const int CH  = D / 4;     // float4 chunks per row: 32 or 16
    const int NPW = 32 / CH;   // nodes per warp: 1 or 2
    int gt   = blockIdx.x * blockDim.x + threadIdx.x;
    int warp = gt >> 5;
    int lane = gt & 31;
    int node = warp * NPW + lane / CH;
    int c    = lane % CH;
    if (node >= NN) return;

    int s = g_offs[node], e = g_offs[node + 1];
    float4 acc = make_float4(0.f, 0.f, 0.f, 0.f);
    int i = s;
    for (; i + 1 < e; i += 2) {
        int s0 = g_srcs[i], s1 = g_srcs[i + 1];
        float4 v0 = yv[(size_t)s0 * CH + c];
        float4 v1 = yv[(size_t)s1 * CH + c];
        acc.x += v0.x + v1.x; acc.y += v0.y + v1.y;
        acc.z += v0.z + v1.z; acc.w += v0.w + v1.w;
    }
    if (i < e) {
        int s0 = g_srcs[i];
        float4 v0 = yv[(size_t)s0 * CH + c];
        acc.x += v0.x; acc.y += v0.y; acc.z += v0.z; acc.w += v0.w;
    }
    float w = g_invdeg[node];
    float4* op = (float4*)out + (size_t)node * CH + c;
    float4 o = *op;
    o.x += w * acc.x; o.y += w * acc.y; o.z += w * acc.z; o.w += w * acc.w;
    if (RELU) {
        o.x = fmaxf(o.x, 0.f); o.y = fmaxf(o.y, 0.f);
        o.z = fmaxf(o.z, 0.f); o.w = fmaxf(o.w, 0.f);
    }
    *op = o;
}

// ---------------- launch ----------------
extern "C" void kernel_launch(void* const* d_in, const int* in_sizes, int n_in,
                              void* d_out, int out_size)
{
    const float* x   = (const float*)d_in[0];
    const void*  ei  = d_in[1];               // int32 or int64; probed on device
    const float* Ws0 = (const float*)d_in[2];
    const float* Wn0 = (const float*)d_in[3];
    const float* b0  = (const float*)d_in[4];
    const float* Ws1 = (const float*)d_in[5];
    const float* Wn1 = (const float*)d_in[6];
    const float* b1  = (const float*)d_in[7];
    const float* Ws2 = (const float*)d_in[8];
    const float* Wn2 = (const float*)d_in[9];
    const float* b2  = (const float*)d_in[10];
    float* out = (float*)d_out;

    const int tb = 256;
    detect_kernel<<<(2 * NE + tb - 1) / tb, tb>>>(ei);
    zero_count_kernel<<<(NN + tb - 1) / tb, tb>>>();
    hist_kernel<<<(NE + tb - 1) / tb, tb>>>(ei);
    scan_kernel<<<1, 1024>>>();
    fill_kernel<<<(NE + tb - 1) / tb, tb>>>(ei);

    const int gblocks = (NN + 127) / 128;  // 391

    // layer 0: g_h0 = relu(x@Ws0 + b0 + inv_deg*agg((x@Wn0)[src]))
    sgemm_kernel<128, 0, 1><<<gblocks, 256>>>(x, Ws0, b0, nullptr, NN);
    sgemm_kernel<128, 0, 3><<<gblocks, 256>>>(x, Wn0, nullptr, nullptr, NN);
    aggregate_kernel<128, true, 1><<<(NN * 32 + 255) / 256, 256>>>(nullptr);

    // layer 1: g_h1
    sgemm_kernel<128, 1, 2><<<gblocks, 256>>>(nullptr, Ws1, b1, nullptr, NN);
    sgemm_kernel<128, 1, 3><<<gblocks, 256>>>(nullptr, Wn1, nullptr, nullptr, NN);
    aggregate_kernel<128, true, 2><<<(NN * 32 + 255) / 256, 256>>>(nullptr);

    // layer 2 (BN=64, no relu) -> d_out
    sgemm_kernel<64, 2, 0><<<gblocks, 128>>>(nullptr, Ws2, b2, out, NN);
    sgemm_kernel<64, 2, 3><<<gblocks, 128>>>(nullptr, Wn2, nullptr, nullptr, NN);
    aggregate_kernel<64, false, 0><<<(NN * 16 + 255) / 256, 256>>>(out);
}

// round 5
// speedup vs baseline: 1.0881x; 1.0881x over previous
#include <cuda_runtime.h>
#include <cstdint>

static const int NN = 50000;
static const int NE = 600000;

// ---------------- scratch (no allocations; referenced only from device code) ----------------
__device__ float g_h0[NN * 128];
__device__ float g_h1[NN * 128];
__device__ float g_y[NN * 128];
__device__ float g_invdeg[NN];
__device__ int   g_count[NN];
__device__ int   g_offs[NN + 1];
__device__ int   g_cursor[NN];
__device__ int   g_srcs[NE];
__device__ int   g_is64;          // 1 if edge_index stored as int64, else int32
__device__ int   g_bsum[128];     // block partial sums for scan
__device__ int   g_bbase[128];    // exclusive block bases

__device__ __forceinline__ const float* sel_in(int SEL, const float* ext) {
    if (SEL == 1) return g_h0;
    if (SEL == 2) return g_h1;
    if (SEL == 3) return g_y;
    return ext;
}
__device__ __forceinline__ float* sel_out(int SEL, float* ext) {
    if (SEL == 1) return g_h0;
    if (SEL == 2) return g_h1;
    if (SEL == 3) return g_y;
    return ext;
}

__device__ __forceinline__ int edge_at(const void* ei, int i) {
    if (g_is64) return (int)((const long long*)ei)[i];
    return ((const int*)ei)[i];
}

// ---------------- dtype probe (race-free: init in separate kernel) ----------------
__global__ void init_flag_kernel() { g_is64 = 1; }

__global__ void detect_kernel(const void* ei) {
    int i = blockIdx.x * blockDim.x + threadIdx.x;
    if (i < 2 * NE) {
        long long v = ((const long long*)ei)[i];
        if (v < 0 || v >= NN) atomicExch(&g_is64, 0);
    }
}

// ---------------- CSR build ----------------
__global__ void zero_count_kernel() {
    int i = blockIdx.x * blockDim.x + threadIdx.x;
    if (i < NN) g_count[i] = 0;
}

__global__ void hist_kernel(const void* ei) {
    int i = blockIdx.x * blockDim.x + threadIdx.x;
    if (i < NE) {
        int d = edge_at(ei, NE + i);
        d = min(max(d, 0), NN - 1);
        atomicAdd(&g_count[d], 1);
    }
}

// hierarchical scan: SEG=512 counts per block, 256 threads (2 counts/thread), 98 blocks
static const int SCAN_SEG = 512;
static const int SCAN_THR = 256;
static const int SCAN_NB  = (NN + SCAN_SEG - 1) / SCAN_SEG;  // 98

__global__ void scan1_kernel() {   // block partial sums
    __shared__ int red[SCAN_THR];
    int b = blockIdx.x, t = threadIdx.x;
    int base = b * SCAN_SEG;
    int i0 = base + 2 * t, i1 = i0 + 1;
    int s = 0;
    if (i0 < NN) s += g_count[i0];
    if (i1 < NN) s += g_count[i1];
    red[t] = s;
    __syncthreads();
    for (int d = SCAN_THR / 2; d > 0; d >>= 1) {
        if (t < d) red[t] += red[t + d];
        __syncthreads();
    }
    if (t == 0) g_bsum[b] = red[0];
}

__global__ void scan2_kernel() {   // exclusive scan of 98 block sums (1 block)
    __shared__ int sh[128];
    int t = threadIdx.x;
    sh[t] = (t < SCAN_NB) ? g_bsum[t] : 0;
    __syncthreads();
    for (int d = 1; d < 128; d <<= 1) {
        int v = sh[t];
        int u = (t >= d) ? sh[t - d] : 0;
        __syncthreads();
        sh[t] = v + u;
        __syncthreads();
    }
    if (t < SCAN_NB) g_bbase[t] = sh[t] - g_bsum[t];  // exclusive
    if (t == 127) g_offs[NN] = sh[127];               // total edges
}

__global__ void scan3_kernel() {   // local prefix + write offs/cursor/invdeg
    __shared__ int sh[SCAN_THR];
    int b = blockIdx.x, t = threadIdx.x;
    int base = b * SCAN_SEG;
    int i0 = base + 2 * t, i1 = i0 + 1;
    int c0 = (i0 < NN) ? g_count[i0] : 0;
    int c1 = (i1 < NN) ? g_count[i1] : 0;
    int s = c0 + c1;
    sh[t] = s;
    __syncthreads();
    for (int d = 1; d < SCAN_THR; d <<= 1) {
        int v = sh[t];
        int u = (t >= d) ? sh[t - d] : 0;
        __syncthreads();
        sh[t] = v + u;
        __syncthreads();
    }
    int tb = g_bbase[b] + sh[t] - s;   // exclusive base for i0
    if (i0 < NN) {
        g_offs[i0]   = tb;
        g_cursor[i0] = tb;
        g_invdeg[i0] = 1.0f / fmaxf((float)c0, 1.0f);
    }
    if (i1 < NN) {
        g_offs[i1]   = tb + c0;
        g_cursor[i1] = tb + c0;
        g_invdeg[i1] = 1.0f / fmaxf((float)c1, 1.0f);
    }
}

__global__ void fill_kernel(const void* ei) {
    int i = blockIdx.x * blockDim.x + threadIdx.x;
    if (i < NE) {
        int s = edge_at(ei, i);
        int d = edge_at(ei, NE + i);
        s = min(max(s, 0), NN - 1);
        d = min(max(d, 0), NN - 1);
        int p = atomicAdd(&g_cursor[d], 1);
        g_srcs[p] = s;
    }
}

// ---------------- SGEMM: C[M,BN] = A[M,128] @ W[128,BN] (+bias), f32x2 packed FMA ----------------
template <int BN, int ASEL, int CSEL>
__global__ __launch_bounds__(BN * 2) void sgemm_kernel(
    const float* __restrict__ Aext, const float* __restrict__ W,
    const float* __restrict__ bias, float* __restrict__ Cext, int M)
{
    const float* A = sel_in(ASEL, Aext);
    float*       C = sel_out(CSEL, Cext);

    const int K = 128, BM = 128, BK = 8, TM = 8, TN = 8;
    const int TXG = BN / TN;        // 16 (BN=128) or 8 (BN=64)
    const int THREADS = TXG * 16;   // 256 or 128
    __shared__ float As[BK][BM];    // transposed A tile
    __shared__ float Ws[BK][BN];

    int tid = threadIdx.x;
    int tx = tid % TXG;
    int ty = tid / TXG;
    int row0 = blockIdx.x * BM;

    unsigned long long acc[TM][TN / 2];
#pragma unroll
    for (int i = 0; i < TM; i++)
#pragma unroll
        for (int j = 0; j < TN / 2; j++) acc[i][j] = 0ull;

    for (int k0 = 0; k0 < K; k0 += BK) {
#pragma unroll
        for (int i = tid; i < BM * BK / 4; i += THREADS) {
            int m  = i / (BK / 4);
            int kf = i % (BK / 4);
            float4 v = make_float4(0.f, 0.f, 0.f, 0.f);
            int gr = row0 + m;
            if (gr < M) v = *(const float4*)(A + (size_t)gr * K + k0 + kf * 4);
            As[kf * 4 + 0][m] = v.x;
            As[kf * 4 + 1][m] = v.y;
            As[kf * 4 + 2][m] = v.z;
            As[kf * 4 + 3][m] = v.w;
        }
#pragma unroll
        for (int i = tid; i < BK * BN / 4; i += THREADS) {
            int kk = i / (BN / 4);
            int nf = i % (BN / 4);
            *(float4*)&Ws[kk][nf * 4] =
                *(const float4*)(W + (size_t)(k0 + kk) * BN + nf * 4);
        }
        __syncthreads();

#pragma unroll
        for (int kk = 0; kk < BK; kk++) {
            float a[TM];
#pragma unroll
            for (int i = 0; i < TM; i++) a[i] = As[kk][ty * TM + i];
            unsigned long long b2[TN / 2];
#pragma unroll
            for (int j = 0; j < TN / 2; j++)
                b2[j] = *(const unsigned long long*)&Ws[kk][tx * TN + 2 * j];
#pragma unroll
            for (int i = 0; i < TM; i++) {
                unsigned long long a2;
                asm("mov.b64 %0, {%1, %1};" : "=l"(a2) : "f"(a[i]));
#pragma unroll
                for (int j = 0; j < TN / 2; j++)
                    asm("fma.rn.f32x2 %0, %1, %2, %0;"
                        : "+l"(acc[i][j]) : "l"(a2), "l"(b2[j]));
            }
        }
        __syncthreads();
    }

#pragma unroll
    for (int i = 0; i < TM; i++) {
        int gr = row0 + ty * TM + i;
        if (gr < M) {
#pragma unroll
            for (int j = 0; j < TN / 2; j++) {
                float lo, hi;
                asm("mov.b64 {%0, %1}, %2;" : "=f"(lo), "=f"(hi) : "l"(acc[i][j]));
                int c = tx * TN + 2 * j;
                if (bias) { lo += bias[c]; hi += bias[c + 1]; }
                float2 v; v.x = lo; v.y = hi;
                *(float2*)(C + (size_t)gr * BN + c) = v;
            }
        }
    }
}

// ---------------- fused aggregate: out = maybe_relu(out + inv_deg * sum_{e: dst=n} g_y[src_e]) ----------------
template <int D, bool RELU, int OSEL>
__global__ void aggregate_kernel(float* __restrict__ Oext)
{
    float* out = sel_out(OSEL, Oext);
    const float4* yv = (const float4*)g_y;

    const int CH  = D / 4;     // float4 chunks per row: 32 or 16
    const int NPW = 32 / CH;   // nodes per warp: 1 or 2
    int gt   = blockIdx.x * blockDim.x + threadIdx.x;
    int warp = gt >> 5;
    int lane = gt & 31;
    int node = warp * NPW + lane / CH;
    int c    = lane % CH;
    if (node >= NN) return;

    int s = g_offs[node], e = g_offs[node + 1];
    float4 acc = make_float4(0.f, 0.f, 0.f, 0.f);
    int i = s;
    for (; i + 1 < e; i += 2) {
        int s0 = g_srcs[i], s1 = g_srcs[i + 1];
        float4 v0 = yv[(size_t)s0 * CH + c];
        float4 v1 = yv[(size_t)s1 * CH + c];
        acc.x += v0.x + v1.x; acc.y += v0.y + v1.y;
        acc.z += v0.z + v1.z; acc.w += v0.w + v1.w;
    }
    if (i < e) {
        int s0 = g_srcs[i];
        float4 v0 = yv[(size_t)s0 * CH + c];
        acc.x += v0.x; acc.y += v0.y; acc.z += v0.z; acc.w += v0.w;
    }
    float w = g_invdeg[node];
    float4* op = (float4*)out + (size_t)node * CH + c;
    float4 o = *op;
    o.x += w * acc.x; o.y += w * acc.y; o.z += w * acc.z; o.w += w * acc.w;
    if (RELU) {
        o.x = fmaxf(o.x, 0.f); o.y = fmaxf(o.y, 0.f);
        o.z = fmaxf(o.z, 0.f); o.w = fmaxf(o.w, 0.f);
    }
    *op = o;
}

// ---------------- launch ----------------
extern "C" void kernel_launch(void* const* d_in, const int* in_sizes, int n_in,
                              void* d_out, int out_size)
{
    const float* x   = (const float*)d_in[0];
    const void*  ei  = d_in[1];
    const float* Ws0 = (const float*)d_in[2];
    const float* Wn0 = (const float*)d_in[3];
    const float* b0  = (const float*)d_in[4];
    const float* Ws1 = (const float*)d_in[5];
    const float* Wn1 = (const float*)d_in[6];
    const float* b1  = (const float*)d_in[7];
    const float* Ws2 = (const float*)d_in[8];
    const float* Wn2 = (const float*)d_in[9];
    const float* b2  = (const float*)d_in[10];
    float* out = (float*)d_out;

    const int tb = 256;
    init_flag_kernel<<<1, 1>>>();
    detect_kernel<<<(2 * NE + tb - 1) / tb, tb>>>(ei);
    zero_count_kernel<<<(NN + tb - 1) / tb, tb>>>();
    hist_kernel<<<(NE + tb - 1) / tb, tb>>>(ei);
    scan1_kernel<<<SCAN_NB, SCAN_THR>>>();
    scan2_kernel<<<1, 128>>>();
    scan3_kernel<<<SCAN_NB, SCAN_THR>>>();
    fill_kernel<<<(NE + tb - 1) / tb, tb>>>(ei);

    const int gblocks = (NN + 127) / 128;  // 391

    // layer 0: g_h0 = relu(x@Ws0 + b0 + inv_deg*agg((x@Wn0)[src]))
    sgemm_kernel<128, 0, 1><<<gblocks, 256>>>(x, Ws0, b0, nullptr, NN);
    sgemm_kernel<128, 0, 3><<<gblocks, 256>>>(x, Wn0, nullptr, nullptr, NN);
    aggregate_kernel<128, true, 1><<<(NN * 32 + 255) / 256, 256>>>(nullptr);

    // layer 1: g_h1
    sgemm_kernel<128, 1, 2><<<gblocks, 256>>>(nullptr, Ws1, b1, nullptr, NN);
    sgemm_kernel<128, 1, 3><<<gblocks, 256>>>(nullptr, Wn1, nullptr, nullptr, NN);
    aggregate_kernel<128, true, 2><<<(NN * 32 + 255) / 256, 256>>>(nullptr);

    // layer 2 (BN=64, no relu) -> d_out
    sgemm_kernel<64, 2, 0><<<gblocks, 128>>>(nullptr, Ws2, b2, out, NN);
    sgemm_kernel<64, 2, 3><<<gblocks, 128>>>(nullptr, Wn2, nullptr, nullptr, NN);
    aggregate_kernel<64, false, 0><<<(NN * 16 + 255) / 256, 256>>>(out);
}

// round 7
// speedup vs baseline: 1.2706x; 1.1677x over previous
#include <cuda_runtime.h>
#include <cuda_bf16.h>
#include <cstdint>

static const int NN = 50000;
static const int NE = 600000;

// ---------------- scratch ----------------
__device__ float g_h0[NN * 128];
__device__ float g_h1[NN * 128];
__device__ float g_y[NN * 128];
__device__ float g_invdeg[NN];
__device__ int   g_count[NN];
__device__ int   g_offs[NN + 1];
__device__ int   g_cursor[NN];
__device__ int   g_srcs[NE];
__device__ int   g_is64;
__device__ int   g_bsum[128];
__device__ int   g_bbase[128];

__device__ __forceinline__ const float* sel_in(int SEL, const float* ext) {
    if (SEL == 1) return g_h0;
    if (SEL == 2) return g_h1;
    if (SEL == 3) return g_y;
    return ext;
}
__device__ __forceinline__ float* sel_out(int SEL, float* ext) {
    if (SEL == 1) return g_h0;
    if (SEL == 2) return g_h1;
    if (SEL == 3) return g_y;
    return ext;
}
__device__ __forceinline__ int edge_at(const void* ei, int i) {
    if (g_is64) return (int)((const long long*)ei)[i];
    return ((const int*)ei)[i];
}

__device__ __forceinline__ uint32_t smem_u32(const void* p) {
    uint32_t a;
    asm("{ .reg .u64 t; cvta.to.shared.u64 t, %1; cvt.u32.u64 %0, t; }" : "=r"(a) : "l"(p));
    return a;
}
__device__ __forceinline__ void ldsm_x4(uint32_t* r, uint32_t addr) {
    asm volatile("ldmatrix.sync.aligned.m8n8.x4.shared.b16 {%0,%1,%2,%3}, [%4];"
                 : "=r"(r[0]), "=r"(r[1]), "=r"(r[2]), "=r"(r[3]) : "r"(addr));
}
__device__ __forceinline__ void ldsm_x2(uint32_t* r, uint32_t addr) {
    asm volatile("ldmatrix.sync.aligned.m8n8.x2.shared.b16 {%0,%1}, [%2];"
                 : "=r"(r[0]), "=r"(r[1]) : "r"(addr));
}
__device__ __forceinline__ void mma_bf16(float* c, const uint32_t* a, const uint32_t* b) {
    asm volatile(
        "mma.sync.aligned.m16n8k16.row.col.f32.bf16.bf16.f32 "
        "{%0,%1,%2,%3}, {%4,%5,%6,%7}, {%8,%9}, {%0,%1,%2,%3};"
        : "+f"(c[0]), "+f"(c[1]), "+f"(c[2]), "+f"(c[3])
        : "r"(a[0]), "r"(a[1]), "r"(a[2]), "r"(a[3]), "r"(b[0]), "r"(b[1]));
}

// ---------------- dtype probe ----------------
__global__ void init_flag_kernel() { g_is64 = 1; }
__global__ void detect_kernel(const void* ei) {
    int i = blockIdx.x * blockDim.x + threadIdx.x;
    if (i < 2 * NE) {
        long long v = ((const long long*)ei)[i];
        if (v < 0 || v >= NN) atomicExch(&g_is64, 0);
    }
}

// ---------------- CSR build ----------------
__global__ void zero_count_kernel() {
    int i = blockIdx.x * blockDim.x + threadIdx.x;
    if (i < NN) g_count[i] = 0;
}
__global__ void hist_kernel(const void* ei) {
    int i = blockIdx.x * blockDim.x + threadIdx.x;
    if (i < NE) {
        int d = edge_at(ei, NE + i);
        d = min(max(d, 0), NN - 1);
        atomicAdd(&g_count[d], 1);
    }
}

static const int SCAN_SEG = 512;
static const int SCAN_THR = 256;
static const int SCAN_NB  = (NN + SCAN_SEG - 1) / SCAN_SEG;  // 98

__global__ void scan1_kernel() {
    __shared__ int red[SCAN_THR];
    int b = blockIdx.x, t = threadIdx.x;
    int i0 = b * SCAN_SEG + 2 * t, i1 = i0 + 1;
    int s = 0;
    if (i0 < NN) s += g_count[i0];
    if (i1 < NN) s += g_count[i1];
    red[t] = s;
    __syncthreads();
    for (int d = SCAN_THR / 2; d > 0; d >>= 1) {
        if (t < d) red[t] += red[t + d];
        __syncthreads();
    }
    if (t == 0) g_bsum[b] = red[0];
}
__global__ void scan2_kernel() {
    __shared__ int sh[128];
    int t = threadIdx.x;
    sh[t] = (t < SCAN_NB) ? g_bsum[t] : 0;
    __syncthreads();
    for (int d = 1; d < 128; d <<= 1) {
        int v = sh[t];
        int u = (t >= d) ? sh[t - d] : 0;
        __syncthreads();
        sh[t] = v + u;
        __syncthreads();
    }
    if (t < SCAN_NB) g_bbase[t] = sh[t] - g_bsum[t];
    if (t == 127) g_offs[NN] = sh[127];
}
__global__ void scan3_kernel() {
    __shared__ int sh[SCAN_THR];
    int b = blockIdx.x, t = threadIdx.x;
    int i0 = b * SCAN_SEG + 2 * t, i1 = i0 + 1;
    int c0 = (i0 < NN) ? g_count[i0] : 0;
    int c1 = (i1 < NN) ? g_count[i1] : 0;
    int s = c0 + c1;
    sh[t] = s;
    __syncthreads();
    for (int d = 1; d < SCAN_THR; d <<= 1) {
        int v = sh[t];
        int u = (t >= d) ? sh[t - d] : 0;
        __syncthreads();
        sh[t] = v + u;
        __syncthreads();
    }
    int tb = g_bbase[b] + sh[t] - s;
    if (i0 < NN) { g_offs[i0] = tb;      g_cursor[i0] = tb;      g_invdeg[i0] = 1.0f / fmaxf((float)c0, 1.0f); }
    if (i1 < NN) { g_offs[i1] = tb + c0; g_cursor[i1] = tb + c0; g_invdeg[i1] = 1.0f / fmaxf((float)c1, 1.0f); }
}
__global__ void fill_kernel(const void* ei) {
    int i = blockIdx.x * blockDim.x + threadIdx.x;
    if (i < NE) {
        int s = edge_at(ei, i);
        int d = edge_at(ei, NE + i);
        s = min(max(s, 0), NN - 1);
        d = min(max(d, 0), NN - 1);
        int p = atomicAdd(&g_cursor[d], 1);
        g_srcs[p] = s;
    }
}

// ---------------- split-bf16 HMMA GEMM: C[M,BN] = A[M,128] @ W[128,BN] (+bias) ----------------
// portable mma.sync path (compute_103-safe). 3 products: hi*hi + hi*lo + lo*hi, f32 accum.
template <int BN, int ASEL, int CSEL>
__global__ __launch_bounds__(256, 1) void sgemm_mma_kernel(
    const float* __restrict__ Aext, const float* __restrict__ W,
    const float* __restrict__ bias, float* __restrict__ Cext, int M)
{
    const float* A = sel_in(ASEL, Aext);
    float*       C = sel_out(CSEL, Cext);

    const int LDE  = 136;          // padded bf16 elems per row
    const int ROWB = LDE * 2;      // 272 bytes (4-bank shift per row -> conflict-free LDSM)
    extern __shared__ char smem[];
    const int OFF_AHI = 0;
    const int OFF_ALO = OFF_AHI + 128 * ROWB;
    const int OFF_BHI = OFF_ALO + 128 * ROWB;
    const int OFF_BLO = OFF_BHI + BN * ROWB;

    uint32_t sb = smem_u32(smem);
    int tid = threadIdx.x, wid = tid >> 5, lane = tid & 31;
    int row0 = blockIdx.x * 128;

    // ---- convert A tile (128x128 f32 -> hi/lo bf16, padded rows) ----
    {
        int row = tid >> 1, half = tid & 1;
        int gr = row0 + row;
        const float4* a4 = (const float4*)(A + (size_t)gr * 128 + half * 64);
        char* ph = smem + OFF_AHI + row * ROWB;
        char* pl = smem + OFF_ALO + row * ROWB;
#pragma unroll
        for (int j = 0; j < 16; j++) {
            float4 v = (gr < M) ? a4[j] : make_float4(0.f, 0.f, 0.f, 0.f);
            int c0 = half * 64 + j * 4;
            __nv_bfloat16 h0 = __float2bfloat16(v.x), h1 = __float2bfloat16(v.y);
            __nv_bfloat16 h2 = __float2bfloat16(v.z), h3 = __float2bfloat16(v.w);
            __nv_bfloat16 l0 = __float2bfloat16(v.x - __bfloat162float(h0));
            __nv_bfloat16 l1 = __float2bfloat16(v.y - __bfloat162float(h1));
            __nv_bfloat16 l2 = __float2bfloat16(v.z - __bfloat162float(h2));
            __nv_bfloat16 l3 = __float2bfloat16(v.w - __bfloat162float(h3));
            __nv_bfloat162 p;
            p.x = h0; p.y = h1; *(__nv_bfloat162*)(ph + c0 * 2) = p;
            p.x = h2; p.y = h3; *(__nv_bfloat162*)(ph + (c0 + 2) * 2) = p;
            p.x = l0; p.y = l1; *(__nv_bfloat162*)(pl + c0 * 2) = p;
            p.x = l2; p.y = l3; *(__nv_bfloat162*)(pl + (c0 + 2) * 2) = p;
        }
    }
    // ---- convert/transpose W (128 x BN f32) -> B[n][k] hi/lo ----
    {
        const int NTH = 256 / BN;    // 2 (BN=128) or 4 (BN=64)
        const int KR  = 128 / NTH;
        int n  = tid % BN;
        int ks = (tid / BN) * KR;
        char* ph = smem + OFF_BHI + n * ROWB;
        char* pl = smem + OFF_BLO + n * ROWB;
#pragma unroll 4
        for (int k = ks; k < ks + KR; k += 2) {
            float v0 = W[(size_t)k * BN + n];
            float v1 = W[(size_t)(k + 1) * BN + n];
            __nv_bfloat16 h0 = __float2bfloat16(v0), h1 = __float2bfloat16(v1);
            __nv_bfloat16 l0 = __float2bfloat16(v0 - __bfloat162float(h0));
            __nv_bfloat16 l1 = __float2bfloat16(v1 - __bfloat162float(h1));
            __nv_bfloat162 p;
            p.x = h0; p.y = h1; *(__nv_bfloat162*)(ph + k * 2) = p;
            p.x = l0; p.y = l1; *(__nv_bfloat162*)(pl + k * 2) = p;
        }
    }
    __syncthreads();

    const int WN = BN / 2;       // warp n-extent: 64 or 32
    const int NT = WN / 8;       // 8 or 4 n-tiles
    int wm = wid & 3, wn = wid >> 2;
    int mrow = wm * 32;
    int ncol = wn * WN;

    float acc[2][NT][4];
#pragma unroll
    for (int mt = 0; mt < 2; mt++)
#pragma unroll
        for (int nt = 0; nt < NT; nt++)
#pragma unroll
            for (int q = 0; q < 4; q++) acc[mt][nt][q] = 0.f;

    // ldmatrix lane address bases
    uint32_t aHi = sb + OFF_AHI + (mrow + (lane & 15)) * ROWB + (lane >> 4) * 16;
    uint32_t aLo = sb + OFF_ALO + (mrow + (lane & 15)) * ROWB + (lane >> 4) * 16;
    uint32_t bHiA = sb + OFF_BHI + (ncol + (lane & 7)) * ROWB + ((lane >> 3) & 1) * 16;
    uint32_t bLoA = sb + OFF_BLO + (ncol + (lane & 7)) * ROWB + ((lane >> 3) & 1) * 16;

#pragma unroll
    for (int ks = 0; ks < 8; ks++) {
        uint32_t ko = ks * 32;   // 16 bf16 = 32 bytes
        uint32_t ah[2][4], al[2][4];
        ldsm_x4(ah[0], aHi + ko);
        ldsm_x4(ah[1], aHi + 16 * ROWB + ko);
        ldsm_x4(al[0], aLo + ko);
        ldsm_x4(al[1], aLo + 16 * ROWB + ko);
        uint32_t bh[NT][2], bl[NT][2];
#pragma unroll
        for (int nt = 0; nt < NT; nt++) {
            ldsm_x2(bh[nt], bHiA + nt * 8 * ROWB + ko);
            ldsm_x2(bl[nt], bLoA + nt * 8 * ROWB + ko);
        }
#pragma unroll
        for (int mt = 0; mt < 2; mt++)
#pragma unroll
            for (int nt = 0; nt < NT; nt++) {
                mma_bf16(acc[mt][nt], ah[mt], bh[nt]);
                mma_bf16(acc[mt][nt], ah[mt], bl[nt]);
                mma_bf16(acc[mt][nt], al[mt], bh[nt]);
            }
    }

    // ---- epilogue: fragment -> global (float2 stores, +bias) ----
#pragma unroll
    for (int mt = 0; mt < 2; mt++) {
        int r0g = row0 + mrow + mt * 16 + (lane >> 2);
        int r1g = r0g + 8;
#pragma unroll
        for (int nt = 0; nt < NT; nt++) {
            int cc = ncol + nt * 8 + (lane & 3) * 2;
            float bx = bias ? bias[cc] : 0.f;
            float by = bias ? bias[cc + 1] : 0.f;
            if (r0g < M) {
                float2 v; v.x = acc[mt][nt][0] + bx; v.y = acc[mt][nt][1] + by;
                *(float2*)(C + (size_t)r0g * BN + cc) = v;
            }
            if (r1g < M) {
                float2 v; v.x = acc[mt][nt][2] + bx; v.y = acc[mt][nt][3] + by;
                *(float2*)(C + (size_t)r1g * BN + cc) = v;
            }
        }
    }
}

// ---------------- fused aggregate ----------------
template <int D, bool RELU, int OSEL>
__global__ void aggregate_kernel(float* __restrict__ Oext)
{
    float* out = sel_out(OSEL, Oext);
    const float4* yv = (const float4*)g_y;

    const int CH  = D / 4;
    const int NPW = 32 / CH;
    int gt   = blockIdx.x * blockDim.x + threadIdx.x;
    int warp = gt >> 5;
    int lane = gt & 31;
    int node = warp * NPW + lane / CH;
    int c    = lane % CH;
    if (node >= NN) return;

    int s = g_offs[node], e = g_offs[node + 1];
    float4 acc = make_float4(0.f, 0.f, 0.f, 0.f);
    int i = s;
    for (; i + 1 < e; i += 2) {
        int s0 = g_srcs[i], s1 = g_srcs[i + 1];
        float4 v0 = yv[(size_t)s0 * CH + c];
        float4 v1 = yv[(size_t)s1 * CH + c];
        acc.x += v0.x + v1.x; acc.y += v0.y + v1.y;
        acc.z += v0.z + v1.z; acc.w += v0.w + v1.w;
    }
    if (i < e) {
        int s0 = g_srcs[i];
        float4 v0 = yv[(size_t)s0 * CH + c];
        acc.x += v0.x; acc.y += v0.y; acc.z += v0.z; acc.w += v0.w;
    }
    float w = g_invdeg[node];
    float4* op = (float4*)out + (size_t)node * CH + c;
    float4 o = *op;
    o.x += w * acc.x; o.y += w * acc.y; o.z += w * acc.z; o.w += w * acc.w;
    if (RELU) {
        o.x = fmaxf(o.x, 0.f); o.y = fmaxf(o.y, 0.f);
        o.z = fmaxf(o.z, 0.f); o.w = fmaxf(o.w, 0.f);
    }
    *op = o;
}

// ---------------- launch ----------------
extern "C" void kernel_launch(void* const* d_in, const int* in_sizes, int n_in,
                              void* d_out, int out_size)
{
    const float* x   = (const float*)d_in[0];
    const void*  ei  = d_in[1];
    const float* Ws0 = (const float*)d_in[2];
    const float* Wn0 = (const float*)d_in[3];
    const float* b0  = (const float*)d_in[4];
    const float* Ws1 = (const float*)d_in[5];
    const float* Wn1 = (const float*)d_in[6];
    const float* b1  = (const float*)d_in[7];
    const float* Ws2 = (const float*)d_in[8];
    const float* Wn2 = (const float*)d_in[9];
    const float* b2  = (const float*)d_in[10];
    float* out = (float*)d_out;

    const int ROWB  = 136 * 2;
    const int SM128 = (128 * ROWB) * 2 + (128 * ROWB) * 2;  // 139264
    const int SM64  = (128 * ROWB) * 2 + (64  * ROWB) * 2;  // 104448
    cudaFuncSetAttribute(sgemm_mma_kernel<128, 0, 1>, cudaFuncAttributeMaxDynamicSharedMemorySize, SM128);
    cudaFuncSetAttribute(sgemm_mma_kernel<128, 0, 3>, cudaFuncAttributeMaxDynamicSharedMemorySize, SM128);
    cudaFuncSetAttribute(sgemm_mma_kernel<128, 1, 2>, cudaFuncAttributeMaxDynamicSharedMemorySize, SM128);
    cudaFuncSetAttribute(sgemm_mma_kernel<128, 1, 3>, cudaFuncAttributeMaxDynamicSharedMemorySize, SM128);
    cudaFuncSetAttribute(sgemm_mma_kernel<64, 2, 0>,  cudaFuncAttributeMaxDynamicSharedMemorySize, SM64);
    cudaFuncSetAttribute(sgemm_mma_kernel<64, 2, 3>,  cudaFuncAttributeMaxDynamicSharedMemorySize, SM64);

    const int tb = 256;
    const int gblocks = (NN + 127) / 128;  // 391

    init_flag_kernel<<<1, 1>>>();
    detect_kernel<<<(2 * NE + tb - 1) / tb, tb>>>(ei);
    zero_count_kernel<<<(NN + tb - 1) / tb, tb>>>();

    // 4th launch = the big HMMA GEMM (ncu captures this one)
    sgemm_mma_kernel<128, 0, 1><<<gblocks, 256, SM128>>>(x, Ws0, b0, nullptr, NN);

    hist_kernel<<<(NE + tb - 1) / tb, tb>>>(ei);
    scan1_kernel<<<SCAN_NB, SCAN_THR>>>();
    scan2_kernel<<<1, 128>>>();
    scan3_kernel<<<SCAN_NB, SCAN_THR>>>();
    fill_kernel<<<(NE + tb - 1) / tb, tb>>>(ei);

    sgemm_mma_kernel<128, 0, 3><<<gblocks, 256, SM128>>>(x, Wn0, nullptr, nullptr, NN);
    aggregate_kernel<128, true, 1><<<(NN * 32 + 255) / 256, 256>>>(nullptr);

    sgemm_mma_kernel<128, 1, 2><<<gblocks, 256, SM128>>>(nullptr, Ws1, b1, nullptr, NN);
    sgemm_mma_kernel<128, 1, 3><<<gblocks, 256, SM128>>>(nullptr, Wn1, nullptr, nullptr, NN);
    aggregate_kernel<128, true, 2><<<(NN * 32 + 255) / 256, 256>>>(nullptr);

    sgemm_mma_kernel<64, 2, 0><<<gblocks, 256, SM64>>>(nullptr, Ws2, b2, out, NN);
    sgemm_mma_kernel<64, 2, 3><<<gblocks, 256, SM64>>>(nullptr, Wn2, nullptr, nullptr, NN);
    aggregate_kernel<64, false, 0><<<(NN * 16 + 255) / 256, 256>>>(out);
}

// round 8
// speedup vs baseline: 3.6999x; 2.9120x over previous
#include <cuda_runtime.h>
#include <cuda_bf16.h>
#include <cstdint>

static const int NN = 50000;
static const int NE = 600000;

// ---------------- scratch ----------------
__device__ float g_h0[NN * 128];
__device__ float g_h1[NN * 128];
__device__ float g_y[NN * 128];
__device__ float g_invdeg[NN];
__device__ int   g_count[NN];
__device__ int   g_offs[NN + 1];
__device__ int   g_cursor[NN];
__device__ int   g_srcs[NE];
__device__ int   g_is64;
__device__ int   g_bsum[128];
__device__ int   g_bbase[128];

__device__ __forceinline__ const float* sel_in(int SEL, const float* ext) {
    if (SEL == 1) return g_h0;
    if (SEL == 2) return g_h1;
    if (SEL == 3) return g_y;
    return ext;
}
__device__ __forceinline__ float* sel_out(int SEL, float* ext) {
    if (SEL == 1) return g_h0;
    if (SEL == 2) return g_h1;
    if (SEL == 3) return g_y;
    return ext;
}
__device__ __forceinline__ int edge_at(const void* ei, int i) {
    if (g_is64) return (int)((const long long*)ei)[i];
    return ((const int*)ei)[i];
}

__device__ __forceinline__ uint32_t smem_u32(const void* p) {
    uint32_t a;
    asm("{ .reg .u64 t; cvta.to.shared.u64 t, %1; cvt.u32.u64 %0, t; }" : "=r"(a) : "l"(p));
    return a;
}
__device__ __forceinline__ void ldsm_x4(uint32_t* r, uint32_t addr) {
    asm volatile("ldmatrix.sync.aligned.m8n8.x4.shared.b16 {%0,%1,%2,%3}, [%4];"
                 : "=r"(r[0]), "=r"(r[1]), "=r"(r[2]), "=r"(r[3]) : "r"(addr));
}
__device__ __forceinline__ void ldsm_x2(uint32_t* r, uint32_t addr) {
    asm volatile("ldmatrix.sync.aligned.m8n8.x2.shared.b16 {%0,%1}, [%2];"
                 : "=r"(r[0]), "=r"(r[1]) : "r"(addr));
}
__device__ __forceinline__ void mma_bf16(float* c, const uint32_t* a, const uint32_t* b) {
    asm volatile(
        "mma.sync.aligned.m16n8k16.row.col.f32.bf16.bf16.f32 "
        "{%0,%1,%2,%3}, {%4,%5,%6,%7}, {%8,%9}, {%0,%1,%2,%3};"
        : "+f"(c[0]), "+f"(c[1]), "+f"(c[2]), "+f"(c[3])
        : "r"(a[0]), "r"(a[1]), "r"(a[2]), "r"(a[3]), "r"(b[0]), "r"(b[1]));
}

// ---------------- dtype probe ----------------
__global__ void init_flag_kernel() { g_is64 = 1; }
// block-or + single plain store: NO single-address atomic storm
__global__ void detect_kernel(const void* ei) {
    int i = blockIdx.x * blockDim.x + threadIdx.x;
    int bad = 0;
    if (i < 2 * NE) {
        long long v = ((const long long*)ei)[i];
        bad = (v < 0 || v >= NN) ? 1 : 0;
    }
    if (__syncthreads_or(bad)) {
        if (threadIdx.x == 0) g_is64 = 0;
    }
}

// ---------------- CSR build ----------------
__global__ void zero_count_kernel() {
    int i = blockIdx.x * blockDim.x + threadIdx.x;
    if (i < NN) g_count[i] = 0;
}
__global__ void hist_kernel(const void* ei) {
    int i = blockIdx.x * blockDim.x + threadIdx.x;
    if (i < NE) {
        int d = edge_at(ei, NE + i);
        d = min(max(d, 0), NN - 1);
        atomicAdd(&g_count[d], 1);
    }
}

static const int SCAN_SEG = 512;
static const int SCAN_THR = 256;
static const int SCAN_NB  = (NN + SCAN_SEG - 1) / SCAN_SEG;  // 98

__global__ void scan1_kernel() {
    __shared__ int red[SCAN_THR];
    int b = blockIdx.x, t = threadIdx.x;
    int i0 = b * SCAN_SEG + 2 * t, i1 = i0 + 1;
    int s = 0;
    if (i0 < NN) s += g_count[i0];
    if (i1 < NN) s += g_count[i1];
    red[t] = s;
    __syncthreads();
    for (int d = SCAN_THR / 2; d > 0; d >>= 1) {
        if (t < d) red[t] += red[t + d];
        __syncthreads();
    }
    if (t == 0) g_bsum[b] = red[0];
}
__global__ void scan2_kernel() {
    __shared__ int sh[128];
    int t = threadIdx.x;
    sh[t] = (t < SCAN_NB) ? g_bsum[t] : 0;
    __syncthreads();
    for (int d = 1; d < 128; d <<= 1) {
        int v = sh[t];
        int u = (t >= d) ? sh[t - d] : 0;
        __syncthreads();
        sh[t] = v + u;
        __syncthreads();
    }
    if (t < SCAN_NB) g_bbase[t] = sh[t] - g_bsum[t];
    if (t == 127) g_offs[NN] = sh[127];
}
__global__ void scan3_kernel() {
    __shared__ int sh[SCAN_THR];
    int b = blockIdx.x, t = threadIdx.x;
    int i0 = b * SCAN_SEG + 2 * t, i1 = i0 + 1;
    int c0 = (i0 < NN) ? g_count[i0] : 0;
    int c1 = (i1 < NN) ? g_count[i1] : 0;
    int s = c0 + c1;
    sh[t] = s;
    __syncthreads();
    for (int d = 1; d < SCAN_THR; d <<= 1) {
        int v = sh[t];
        int u = (t >= d) ? sh[t - d] : 0;
        __syncthreads();
        sh[t] = v + u;
        __syncthreads();
    }
    int tb = g_bbase[b] + sh[t] - s;
    if (i0 < NN) { g_offs[i0] = tb;      g_cursor[i0] = tb;      g_invdeg[i0] = 1.0f / fmaxf((float)c0, 1.0f); }
    if (i1 < NN) { g_offs[i1] = tb + c0; g_cursor[i1] = tb + c0; g_invdeg[i1] = 1.0f / fmaxf((float)c1, 1.0f); }
}
__global__ void fill_kernel(const void* ei) {
    int i = blockIdx.x * blockDim.x + threadIdx.x;
    if (i < NE) {
        int s = edge_at(ei, i);
        int d = edge_at(ei, NE + i);
        s = min(max(s, 0), NN - 1);
        d = min(max(d, 0), NN - 1);
        int p = atomicAdd(&g_cursor[d], 1);
        g_srcs[p] = s;
    }
}

// ---------------- split-bf16 HMMA GEMM: C[M,BN] = A[M,128] @ W[128,BN] (+bias) ----------------
template <int BN, int ASEL, int CSEL>
__global__ __launch_bounds__(256, 1) void sgemm_mma_kernel(
    const float* __restrict__ Aext, const float* __restrict__ W,
    const float* __restrict__ bias, float* __restrict__ Cext, int M)
{
    const float* A = sel_in(ASEL, Aext);
    float*       C = sel_out(CSEL, Cext);

    const int LDE  = 136;
    const int ROWB = LDE * 2;      // 272 bytes
    extern __shared__ char smem[];
    const int OFF_AHI = 0;
    const int OFF_ALO = OFF_AHI + 128 * ROWB;
    const int OFF_BHI = OFF_ALO + 128 * ROWB;
    const int OFF_BLO = OFF_BHI + BN * ROWB;

    uint32_t sb = smem_u32(smem);
    int tid = threadIdx.x, wid = tid >> 5, lane = tid & 31;
    int row0 = blockIdx.x * 128;

    // ---- convert A tile ----
    {
        int row = tid >> 1, half = tid & 1;
        int gr = row0 + row;
        const float4* a4 = (const float4*)(A + (size_t)gr * 128 + half * 64);
        char* ph = smem + OFF_AHI + row * ROWB;
        char* pl = smem + OFF_ALO + row * ROWB;
#pragma unroll
        for (int j = 0; j < 16; j++) {
            float4 v = (gr < M) ? a4[j] : make_float4(0.f, 0.f, 0.f, 0.f);
            int c0 = half * 64 + j * 4;
            __nv_bfloat16 h0 = __float2bfloat16(v.x), h1 = __float2bfloat16(v.y);
            __nv_bfloat16 h2 = __float2bfloat16(v.z), h3 = __float2bfloat16(v.w);
            __nv_bfloat16 l0 = __float2bfloat16(v.x - __bfloat162float(h0));
            __nv_bfloat16 l1 = __float2bfloat16(v.y - __bfloat162float(h1));
            __nv_bfloat16 l2 = __float2bfloat16(v.z - __bfloat162float(h2));
            __nv_bfloat16 l3 = __float2bfloat16(v.w - __bfloat162float(h3));
            __nv_bfloat162 p;
            p.x = h0; p.y = h1; *(__nv_bfloat162*)(ph + c0 * 2) = p;
            p.x = h2; p.y = h3; *(__nv_bfloat162*)(ph + (c0 + 2) * 2) = p;
            p.x = l0; p.y = l1; *(__nv_bfloat162*)(pl + c0 * 2) = p;
            p.x = l2; p.y = l3; *(__nv_bfloat162*)(pl + (c0 + 2) * 2) = p;
        }
    }
    // ---- convert/transpose W ----
    {
        const int NTH = 256 / BN;
        const int KR  = 128 / NTH;
        int n  = tid % BN;
        int ks = (tid / BN) * KR;
        char* ph = smem + OFF_BHI + n * ROWB;
        char* pl = smem + OFF_BLO + n * ROWB;
#pragma unroll 4
        for (int k = ks; k < ks + KR; k += 2) {
            float v0 = W[(size_t)k * BN + n];
            float v1 = W[(size_t)(k + 1) * BN + n];
            __nv_bfloat16 h0 = __float2bfloat16(v0), h1 = __float2bfloat16(v1);
            __nv_bfloat16 l0 = __float2bfloat16(v0 - __bfloat162float(h0));
            __nv_bfloat16 l1 = __float2bfloat16(v1 - __bfloat162float(h1));
            __nv_bfloat162 p;
            p.x = h0; p.y = h1; *(__nv_bfloat162*)(ph + k * 2) = p;
            p.x = l0; p.y = l1; *(__nv_bfloat162*)(pl + k * 2) = p;
        }
    }
    __syncthreads();

    const int WN = BN / 2;
    const int NT = WN / 8;
    int wm = wid & 3, wn = wid >> 2;
    int mrow = wm * 32;
    int ncol = wn * WN;

    float acc[2][NT][4];
#pragma unroll
    for (int mt = 0; mt < 2; mt++)
#pragma unroll
        for (int nt = 0; nt < NT; nt++)
#pragma unroll
            for (int q = 0; q < 4; q++) acc[mt][nt][q] = 0.f;

    uint32_t aHi = sb + OFF_AHI + (mrow + (lane & 15)) * ROWB + (lane >> 4) * 16;
    uint32_t aLo = sb + OFF_ALO + (mrow + (lane & 15)) * ROWB + (lane >> 4) * 16;
    uint32_t bHiA = sb + OFF_BHI + (ncol + (lane & 7)) * ROWB + ((lane >> 3) & 1) * 16;
    uint32_t bLoA = sb + OFF_BLO + (ncol + (lane & 7)) * ROWB + ((lane >> 3) & 1) * 16;

#pragma unroll
    for (int ks = 0; ks < 8; ks++) {
        uint32_t ko = ks * 32;
        uint32_t ah[2][4], al[2][4];
        ldsm_x4(ah[0], aHi + ko);
        ldsm_x4(ah[1], aHi + 16 * ROWB + ko);
        ldsm_x4(al[0], aLo + ko);
        ldsm_x4(al[1], aLo + 16 * ROWB + ko);
        uint32_t bh[NT][2], bl[NT][2];
#pragma unroll
        for (int nt = 0; nt < NT; nt++) {
            ldsm_x2(bh[nt], bHiA + nt * 8 * ROWB + ko);
            ldsm_x2(bl[nt], bLoA + nt * 8 * ROWB + ko);
        }
#pragma unroll
        for (int mt = 0; mt < 2; mt++)
#pragma unroll
            for (int nt = 0; nt < NT; nt++) {
                mma_bf16(acc[mt][nt], ah[mt], bh[nt]);
                mma_bf16(acc[mt][nt], ah[mt], bl[nt]);
                mma_bf16(acc[mt][nt], al[mt], bh[nt]);
            }
    }

#pragma unroll
    for (int mt = 0; mt < 2; mt++) {
        int r0g = row0 + mrow + mt * 16 + (lane >> 2);
        int r1g = r0g + 8;
#pragma unroll
        for (int nt = 0; nt < NT; nt++) {
            int cc = ncol + nt * 8 + (lane & 3) * 2;
            float bx = bias ? bias[cc] : 0.f;
            float by = bias ? bias[cc + 1] : 0.f;
            if (r0g < M) {
                float2 v; v.x = acc[mt][nt][0] + bx; v.y = acc[mt][nt][1] + by;
                *(float2*)(C + (size_t)r0g * BN + cc) = v;
            }
            if (r1g < M) {
                float2 v; v.x = acc[mt][nt][2] + bx; v.y = acc[mt][nt][3] + by;
                *(float2*)(C + (size_t)r1g * BN + cc) = v;
            }
        }
    }
}

// ---------------- fused aggregate ----------------
template <int D, bool RELU, int OSEL>
__global__ void aggregate_kernel(float* __restrict__ Oext)
{
    float* out = sel_out(OSEL, Oext);
    const float4* yv = (const float4*)g_y;

    const int CH  = D / 4;
    const int NPW = 32 / CH;
    int gt   = blockIdx.x * blockDim.x + threadIdx.x;
    int warp = gt >> 5;
    int lane = gt & 31;
    int node = warp * NPW + lane / CH;
    int c    = lane % CH;
    if (node >= NN) return;

    int s = g_offs[node], e = g_offs[node + 1];
    float4 acc = make_float4(0.f, 0.f, 0.f, 0.f);
    int i = s;
    for (; i + 1 < e; i += 2) {
        int s0 = g_srcs[i], s1 = g_srcs[i + 1];
        float4 v0 = yv[(size_t)s0 * CH + c];
        float4 v1 = yv[(size_t)s1 * CH + c];
        acc.x += v0.x + v1.x; acc.y += v0.y + v1.y;
        acc.z += v0.z + v1.z; acc.w += v0.w + v1.w;
    }
    if (i < e) {
        int s0 = g_srcs[i];
        float4 v0 = yv[(size_t)s0 * CH + c];
        acc.x += v0.x; acc.y += v0.y; acc.z += v0.z; acc.w += v0.w;
    }
    float w = g_invdeg[node];
    float4* op = (float4*)out + (size_t)node * CH + c;
    float4 o = *op;
    o.x += w * acc.x; o.y += w * acc.y; o.z += w * acc.z; o.w += w * acc.w;
    if (RELU) {
        o.x = fmaxf(o.x, 0.f); o.y = fmaxf(o.y, 0.f);
        o.z = fmaxf(o.z, 0.f); o.w = fmaxf(o.w, 0.f);
    }
    *op = o;
}

// ---------------- launch ----------------
extern "C" void kernel_launch(void* const* d_in, const int* in_sizes, int n_in,
                              void* d_out, int out_size)
{
    const float* x   = (const float*)d_in[0];
    const void*  ei  = d_in[1];
    const float* Ws0 = (const float*)d_in[2];
    const float* Wn0 = (const float*)d_in[3];
    const float* b0  = (const float*)d_in[4];
    const float* Ws1 = (const float*)d_in[5];
    const float* Wn1 = (const float*)d_in[6];
    const float* b1  = (const float*)d_in[7];
    const float* Ws2 = (const float*)d_in[8];
    const float* Wn2 = (const float*)d_in[9];
    const float* b2  = (const float*)d_in[10];
    float* out = (float*)d_out;

    const int ROWB  = 136 * 2;
    const int SM128 = (128 * ROWB) * 2 + (128 * ROWB) * 2;  // 139264
    const int SM64  = (128 * ROWB) * 2 + (64  * ROWB) * 2;  // 104448
    cudaFuncSetAttribute(sgemm_mma_kernel<128, 0, 1>, cudaFuncAttributeMaxDynamicSharedMemorySize, SM128);
    cudaFuncSetAttribute(sgemm_mma_kernel<128, 0, 3>, cudaFuncAttributeMaxDynamicSharedMemorySize, SM128);
    cudaFuncSetAttribute(sgemm_mma_kernel<128, 1, 2>, cudaFuncAttributeMaxDynamicSharedMemorySize, SM128);
    cudaFuncSetAttribute(sgemm_mma_kernel<128, 1, 3>, cudaFuncAttributeMaxDynamicSharedMemorySize, SM128);
    cudaFuncSetAttribute(sgemm_mma_kernel<64, 2, 0>,  cudaFuncAttributeMaxDynamicSharedMemorySize, SM64);
    cudaFuncSetAttribute(sgemm_mma_kernel<64, 2, 3>,  cudaFuncAttributeMaxDynamicSharedMemorySize, SM64);

    const int tb = 256;
    const int gblocks = (NN + 127) / 128;  // 391

    init_flag_kernel<<<1, 1>>>();
    detect_kernel<<<(2 * NE + tb - 1) / tb, tb>>>(ei);
    zero_count_kernel<<<(NN + tb - 1) / tb, tb>>>();

    sgemm_mma_kernel<128, 0, 1><<<gblocks, 256, SM128>>>(x, Ws0, b0, nullptr, NN);

    hist_kernel<<<(NE + tb - 1) / tb, tb>>>(ei);
    scan1_kernel<<<SCAN_NB, SCAN_THR>>>();
    scan2_kernel<<<1, 128>>>();
    scan3_kernel<<<SCAN_NB, SCAN_THR>>>();
    fill_kernel<<<(NE + tb - 1) / tb, tb>>>(ei);

    sgemm_mma_kernel<128, 0, 3><<<gblocks, 256, SM128>>>(x, Wn0, nullptr, nullptr, NN);
    aggregate_kernel<128, true, 1><<<(NN * 32 + 255) / 256, 256>>>(nullptr);

    sgemm_mma_kernel<128, 1, 2><<<gblocks, 256, SM128>>>(nullptr, Ws1, b1, nullptr, NN);
    sgemm_mma_kernel<128, 1, 3><<<gblocks, 256, SM128>>>(nullptr, Wn1, nullptr, nullptr, NN);
    aggregate_kernel<128, true, 2><<<(NN * 32 + 255) / 256, 256>>>(nullptr);

    sgemm_mma_kernel<64, 2, 0><<<gblocks, 256, SM64>>>(nullptr, Ws2, b2, out, NN);
    sgemm_mma_kernel<64, 2, 3><<<gblocks, 256, SM64>>>(nullptr, Wn2, nullptr, nullptr, NN);
    aggregate_kernel<64, false, 0><<<(NN * 16 + 255) / 256, 256>>>(out);
}

// round 9
// speedup vs baseline: 4.2972x; 1.1614x over previous
#include <cuda_runtime.h>
#include <cuda_bf16.h>
#include <cstdint>

static const int NN = 50000;
static const int NE = 600000;

// ---------------- scratch ----------------
__device__ float g_h0[NN * 128];
__device__ float g_h1[NN * 128];
__device__ float g_y[NN * 128];
__device__ __nv_bfloat16 g_ahi[NN * 128];
__device__ __nv_bfloat16 g_alo[NN * 128];
__device__ float g_invdeg[NN];
__device__ int   g_count[NN];
__device__ int   g_offs[NN + 1];
__device__ int   g_cursor[NN];
__device__ int   g_srcs[NE];
__device__ int   g_is64;
__device__ int   g_bsum[128];
__device__ int   g_bbase[128];

__device__ __forceinline__ float* sel_out(int SEL, float* ext) {
    if (SEL == 1) return g_h0;
    if (SEL == 2) return g_h1;
    if (SEL == 3) return g_y;
    return ext;
}
__device__ __forceinline__ int edge_at(const void* ei, int i) {
    if (g_is64) return (int)((const long long*)ei)[i];
    return ((const int*)ei)[i];
}

__device__ __forceinline__ uint32_t smem_u32(const void* p) {
    uint32_t a;
    asm("{ .reg .u64 t; cvta.to.shared.u64 t, %1; cvt.u32.u64 %0, t; }" : "=r"(a) : "l"(p));
    return a;
}
__device__ __forceinline__ void ldsm_x4(uint32_t* r, uint32_t addr) {
    asm volatile("ldmatrix.sync.aligned.m8n8.x4.shared.b16 {%0,%1,%2,%3}, [%4];"
                 : "=r"(r[0]), "=r"(r[1]), "=r"(r[2]), "=r"(r[3]) : "r"(addr));
}
__device__ __forceinline__ void mma_bf16(float* c, const uint32_t* a, const uint32_t* b) {
    asm volatile(
        "mma.sync.aligned.m16n8k16.row.col.f32.bf16.bf16.f32 "
        "{%0,%1,%2,%3}, {%4,%5,%6,%7}, {%8,%9}, {%0,%1,%2,%3};"
        : "+f"(c[0]), "+f"(c[1]), "+f"(c[2]), "+f"(c[3])
        : "r"(a[0]), "r"(a[1]), "r"(a[2]), "r"(a[3]), "r"(b[0]), "r"(b[1]));
}
__device__ __forceinline__ void split_bf16(float v, __nv_bfloat16& h, __nv_bfloat16& l) {
    h = __float2bfloat16(v);
    l = __float2bfloat16(v - __bfloat162float(h));
}

// ---------------- dtype probe ----------------
__global__ void init_flag_kernel() { g_is64 = 1; }
__global__ void detect_kernel(const void* ei) {
    int i = blockIdx.x * blockDim.x + threadIdx.x;
    int bad = 0;
    if (i < 2 * NE) {
        long long v = ((const long long*)ei)[i];
        bad = (v < 0 || v >= NN) ? 1 : 0;
    }
    if (__syncthreads_or(bad)) {
        if (threadIdx.x == 0) g_is64 = 0;
    }
}

// ---------------- conv: f32 x -> bf16 hi/lo ----------------
__global__ void conv_x_kernel(const float* __restrict__ x) {
    int i = blockIdx.x * blockDim.x + threadIdx.x;   // over NN*64 float2
    if (i < NN * 64) {
        float2 v = ((const float2*)x)[i];
        __nv_bfloat16 h0, l0, h1, l1;
        split_bf16(v.x, h0, l0);
        split_bf16(v.y, h1, l1);
        __nv_bfloat162 ph; ph.x = h0; ph.y = h1;
        __nv_bfloat162 pl; pl.x = l0; pl.y = l1;
        ((__nv_bfloat162*)g_ahi)[i] = ph;
        ((__nv_bfloat162*)g_alo)[i] = pl;
    }
}

// ---------------- CSR build ----------------
__global__ void zero_count_kernel() {
    int i = blockIdx.x * blockDim.x + threadIdx.x;
    if (i < NN) g_count[i] = 0;
}
__global__ void hist_kernel(const void* ei) {
    int i = blockIdx.x * blockDim.x + threadIdx.x;
    if (i < NE) {
        int d = edge_at(ei, NE + i);
        d = min(max(d, 0), NN - 1);
        atomicAdd(&g_count[d], 1);
    }
}

static const int SCAN_SEG = 512;
static const int SCAN_THR = 256;
static const int SCAN_NB  = (NN + SCAN_SEG - 1) / SCAN_SEG;  // 98

__global__ void scan1_kernel() {
    __shared__ int red[SCAN_THR];
    int b = blockIdx.x, t = threadIdx.x;
    int i0 = b * SCAN_SEG + 2 * t, i1 = i0 + 1;
    int s = 0;
    if (i0 < NN) s += g_count[i0];
    if (i1 < NN) s += g_count[i1];
    red[t] = s;
    __syncthreads();
    for (int d = SCAN_THR / 2; d > 0; d >>= 1) {
        if (t < d) red[t] += red[t + d];
        __syncthreads();
    }
    if (t == 0) g_bsum[b] = red[0];
}
__global__ void scan2_kernel() {
    __shared__ int sh[128];
    int t = threadIdx.x;
    sh[t] = (t < SCAN_NB) ? g_bsum[t] : 0;
    __syncthreads();
    for (int d = 1; d < 128; d <<= 1) {
        int v = sh[t];
        int u = (t >= d) ? sh[t - d] : 0;
        __syncthreads();
        sh[t] = v + u;
        __syncthreads();
    }
    if (t < SCAN_NB) g_bbase[t] = sh[t] - g_bsum[t];
    if (t == 127) g_offs[NN] = sh[127];
}
__global__ void scan3_kernel() {
    __shared__ int sh[SCAN_THR];
    int b = blockIdx.x, t = threadIdx.x;
    int i0 = b * SCAN_SEG + 2 * t, i1 = i0 + 1;
    int c0 = (i0 < NN) ? g_count[i0] : 0;
    int c1 = (i1 < NN) ? g_count[i1] : 0;
    int s = c0 + c1;
    sh[t] = s;
    __syncthreads();
    for (int d = 1; d < SCAN_THR; d <<= 1) {
        int v = sh[t];
        int u = (t >= d) ? sh[t - d] : 0;
        __syncthreads();
        sh[t] = v + u;
        __syncthreads();
    }
    int tb = g_bbase[b] + sh[t] - s;
    if (i0 < NN) { g_offs[i0] = tb;      g_cursor[i0] = tb;      g_invdeg[i0] = 1.0f / fmaxf((float)c0, 1.0f); }
    if (i1 < NN) { g_offs[i1] = tb + c0; g_cursor[i1] = tb + c0; g_invdeg[i1] = 1.0f / fmaxf((float)c1, 1.0f); }
}
__global__ void fill_kernel(const void* ei) {
    int i = blockIdx.x * blockDim.x + threadIdx.x;
    if (i < NE) {
        int s = edge_at(ei, i);
        int d = edge_at(ei, NE + i);
        s = min(max(s, 0), NN - 1);
        d = min(max(d, 0), NN - 1);
        int p = atomicAdd(&g_cursor[d], 1);
        g_srcs[p] = s;
    }
}

// ---------------- split-bf16 HMMA GEMM, 128x64 tile, 2 CTA/SM ----------------
// C[M, BNT](cols col0..col0+63) = A[M,128] @ W[128,BNT][:, col0:col0+64] (+bias)
// A pre-converted in g_ahi/g_alo. Grid (391, BNT/64).
template <int BNT, int CSEL>
__global__ __launch_bounds__(256, 2) void sgemm_mma_kernel(
    const float* __restrict__ W, const float* __restrict__ bias,
    float* __restrict__ Cext, int M)
{
    float* C = sel_out(CSEL, Cext);

    const int ROWB = 272;            // 136 bf16 per padded row
    extern __shared__ char smem[];
    const int OFF_AHI = 0;
    const int OFF_ALO = OFF_AHI + 128 * ROWB;   // 34816
    const int OFF_BHI = OFF_ALO + 128 * ROWB;   // 69632
    const int OFF_BLO = OFF_BHI + 64 * ROWB;    // 87040  (total 104448)

    uint32_t sb = smem_u32(smem);
    int tid = threadIdx.x, wid = tid >> 5, lane = tid & 31;
    int row0 = blockIdx.x * 128;
    int col0 = blockIdx.y * 64;

    // ---- load pre-converted A tile (16B chunks) ----
    {
        const uint4 z = make_uint4(0u, 0u, 0u, 0u);
#pragma unroll
        for (int i = tid; i < 128 * 16; i += 256) {
            int row = i >> 4, ch = i & 15;
            int gr = row0 + row;
            uint4 vh = z, vl = z;
            if (gr < M) {
                vh = *(const uint4*)(g_ahi + (size_t)gr * 128 + ch * 8);
                vl = *(const uint4*)(g_alo + (size_t)gr * 128 + ch * 8);
            }
            *(uint4*)(smem + OFF_AHI + row * ROWB + ch * 16) = vh;
            *(uint4*)(smem + OFF_ALO + row * ROWB + ch * 16) = vl;
        }
    }
    // ---- convert/transpose W slice [128, 64] -> B[n][k] hi/lo ----
    {
        int n   = tid & 63;
        int kb  = (tid >> 6) * 32;
        char* ph = smem + OFF_BHI + n * ROWB;
        char* pl = smem + OFF_BLO + n * ROWB;
#pragma unroll 4
        for (int k = kb; k < kb + 32; k += 2) {
            float v0 = W[(size_t)k * BNT + col0 + n];
            float v1 = W[(size_t)(k + 1) * BNT + col0 + n];
            __nv_bfloat16 h0, l0, h1, l1;
            split_bf16(v0, h0, l0);
            split_bf16(v1, h1, l1);
            __nv_bfloat162 p;
            p.x = h0; p.y = h1; *(__nv_bfloat162*)(ph + k * 2) = p;
            p.x = l0; p.y = l1; *(__nv_bfloat162*)(pl + k * 2) = p;
        }
    }
    __syncthreads();

    // warp layout: wm in 0..3 (32 rows each), wn in 0..1 (32 cols each)
    int wm = wid & 3, wn = wid >> 2;
    int mrow = wm * 32;
    int ncol = wn * 32;

    float acc[2][4][4];
#pragma unroll
    for (int mt = 0; mt < 2; mt++)
#pragma unroll
        for (int nt = 0; nt < 4; nt++)
#pragma unroll
            for (int q = 0; q < 4; q++) acc[mt][nt][q] = 0.f;

    // A ldsm base: lanes 0-15 rows, lanes 16-31 same rows col+8
    uint32_t aHi = sb + OFF_AHI + (mrow + (lane & 15)) * ROWB + (lane >> 4) * 16;
    uint32_t aLo = sb + OFF_ALO + (mrow + (lane & 15)) * ROWB + (lane >> 4) * 16;
    // B paired-x4 base: groups of 8 lanes -> {nt_even k0, nt_even k8, nt_odd k0, nt_odd k8}
    uint32_t nadd = ((lane >> 4) & 1) * 8;
    uint32_t cadd = ((lane >> 3) & 1) * 16;
    uint32_t bHiA = sb + OFF_BHI + (ncol + nadd + (lane & 7)) * ROWB + cadd;
    uint32_t bLoA = sb + OFF_BLO + (ncol + nadd + (lane & 7)) * ROWB + cadd;

#pragma unroll
    for (int ks = 0; ks < 8; ks++) {
        uint32_t ko = ks * 32;
        uint32_t ah[2][4], al[2][4];
        ldsm_x4(ah[0], aHi + ko);
        ldsm_x4(ah[1], aHi + 16 * ROWB + ko);
        ldsm_x4(al[0], aLo + ko);
        ldsm_x4(al[1], aLo + 16 * ROWB + ko);
        uint32_t bh[2][4], bl[2][4];       // [pair]{nt_even b0,b1, nt_odd b0,b1}
        ldsm_x4(bh[0], bHiA + ko);
        ldsm_x4(bh[1], bHiA + 16 * ROWB + ko);
        ldsm_x4(bl[0], bLoA + ko);
        ldsm_x4(bl[1], bLoA + 16 * ROWB + ko);
#pragma unroll
        for (int mt = 0; mt < 2; mt++)
#pragma unroll
            for (int p = 0; p < 2; p++)
#pragma unroll
                for (int h = 0; h < 2; h++) {
                    float* a = acc[mt][2 * p + h];
                    mma_bf16(a, ah[mt], &bh[p][h * 2]);
                    mma_bf16(a, ah[mt], &bl[p][h * 2]);
                    mma_bf16(a, al[mt], &bh[p][h * 2]);
                }
    }

    // ---- epilogue ----
#pragma unroll
    for (int mt = 0; mt < 2; mt++) {
        int r0g = row0 + mrow + mt * 16 + (lane >> 2);
        int r1g = r0g + 8;
#pragma unroll
        for (int nt = 0; nt < 4; nt++) {
            int cc = col0 + ncol + nt * 8 + (lane & 3) * 2;
            float bx = bias ? bias[cc] : 0.f;
            float by = bias ? bias[cc + 1] : 0.f;
            if (r0g < M) {
                float2 v; v.x = acc[mt][nt][0] + bx; v.y = acc[mt][nt][1] + by;
                *(float2*)(C + (size_t)r0g * BNT + cc) = v;
            }
            if (r1g < M) {
                float2 v; v.x = acc[mt][nt][2] + bx; v.y = acc[mt][nt][3] + by;
                *(float2*)(C + (size_t)r1g * BNT + cc) = v;
            }
        }
    }
}

// ---------------- fused aggregate (+ optional bf16 hi/lo emit for next layer) ----------------
template <int D, bool RELU, int OSEL, bool WB16>
__global__ void aggregate_kernel(float* __restrict__ Oext)
{
    float* out = sel_out(OSEL, Oext);
    const float4* yv = (const float4*)g_y;

    const int CH  = D / 4;
    const int NPW = 32 / CH;
    int gt   = blockIdx.x * blockDim.x + threadIdx.x;
    int warp = gt >> 5;
    int lane = gt & 31;
    int node = warp * NPW + lane / CH;
    int c    = lane % CH;
    if (node >= NN) return;

    int s = g_offs[node], e = g_offs[node + 1];
    float4 acc = make_float4(0.f, 0.f, 0.f, 0.f);
    int i = s;
    for (; i + 1 < e; i += 2) {
        int s0 = g_srcs[i], s1 = g_srcs[i + 1];
        float4 v0 = yv[(size_t)s0 * CH + c];
        float4 v1 = yv[(size_t)s1 * CH + c];
        acc.x += v0.x + v1.x; acc.y += v0.y + v1.y;
        acc.z += v0.z + v1.z; acc.w += v0.w + v1.w;
    }
    if (i < e) {
        int s0 = g_srcs[i];
        float4 v0 = yv[(size_t)s0 * CH + c];
        acc.x += v0.x; acc.y += v0.y; acc.z += v0.z; acc.w += v0.w;
    }
    float w = g_invdeg[node];
    float4* op = (float4*)out + (size_t)node * CH + c;
    float4 o = *op;
    o.x += w * acc.x; o.y += w * acc.y; o.z += w * acc.z; o.w += w * acc.w;
    if (RELU) {
        o.x = fmaxf(o.x, 0.f); o.y = fmaxf(o.y, 0.f);
        o.z = fmaxf(o.z, 0.f); o.w = fmaxf(o.w, 0.f);
    }
    *op = o;
    if (WB16) {
        __nv_bfloat16 h0, l0, h1, l1, h2, l2, h3, l3;
        split_bf16(o.x, h0, l0); split_bf16(o.y, h1, l1);
        split_bf16(o.z, h2, l2); split_bf16(o.w, h3, l3);
        __nv_bfloat162* ph = (__nv_bfloat162*)g_ahi + (size_t)node * (D / 2) + c * 2;
        __nv_bfloat162* pl = (__nv_bfloat162*)g_alo + (size_t)node * (D / 2) + c * 2;
        __nv_bfloat162 p;
        p.x = h0; p.y = h1; ph[0] = p;
        p.x = h2; p.y = h3; ph[1] = p;
        p.x = l0; p.y = l1; pl[0] = p;
        p.x = l2; p.y = l3; pl[1] = p;
    }
}

// ---------------- launch ----------------
extern "C" void kernel_launch(void* const* d_in, const int* in_sizes, int n_in,
                              void* d_out, int out_size)
{
    const float* x   = (const float*)d_in[0];
    const void*  ei  = d_in[1];
    const float* Ws0 = (const float*)d_in[2];
    const float* Wn0 = (const float*)d_in[3];
    const float* b0  = (const float*)d_in[4];
    const float* Ws1 = (const float*)d_in[5];
    const float* Wn1 = (const float*)d_in[6];
    const float* b1  = (const float*)d_in[7];
    const float* Ws2 = (const float*)d_in[8];
    const float* Wn2 = (const float*)d_in[9];
    const float* b2  = (const float*)d_in[10];
    float* out = (float*)d_out;

    const int SMEM = 104448;
    cudaFuncSetAttribute(sgemm_mma_kernel<128, 1>, cudaFuncAttributeMaxDynamicSharedMemorySize, SMEM);
    cudaFuncSetAttribute(sgemm_mma_kernel<128, 2>, cudaFuncAttributeMaxDynamicSharedMemorySize, SMEM);
    cudaFuncSetAttribute(sgemm_mma_kernel<128, 3>, cudaFuncAttributeMaxDynamicSharedMemorySize, SMEM);
    cudaFuncSetAttribute(sgemm_mma_kernel<64, 0>,  cudaFuncAttributeMaxDynamicSharedMemorySize, SMEM);
    cudaFuncSetAttribute(sgemm_mma_kernel<64, 3>,  cudaFuncAttributeMaxDynamicSharedMemorySize, SMEM);

    const int tb = 256;
    const dim3 g2(391, 2), g1(391, 1);

    init_flag_kernel<<<1, 1>>>();
    detect_kernel<<<(2 * NE + tb - 1) / tb, tb>>>(ei);
    conv_x_kernel<<<(NN * 64 + tb - 1) / tb, tb>>>(x);

    // 4th launch = big HMMA GEMM (ncu captures this one)
    sgemm_mma_kernel<128, 1><<<g2, 256, SMEM>>>(Ws0, b0, nullptr, NN);

    zero_count_kernel<<<(NN + tb - 1) / tb, tb>>>();
    hist_kernel<<<(NE + tb - 1) / tb, tb>>>(ei);
    scan1_kernel<<<SCAN_NB, SCAN_THR>>>();
    scan2_kernel<<<1, 128>>>();
    scan3_kernel<<<SCAN_NB, SCAN_THR>>>();
    fill_kernel<<<(NE + tb - 1) / tb, tb>>>(ei);

    sgemm_mma_kernel<128, 3><<<g2, 256, SMEM>>>(Wn0, nullptr, nullptr, NN);
    aggregate_kernel<128, true, 1, true><<<(NN * 32 + 255) / 256, 256>>>(nullptr);

    sgemm_mma_kernel<128, 2><<<g2, 256, SMEM>>>(Ws1, b1, nullptr, NN);
    sgemm_mma_kernel<128, 3><<<g2, 256, SMEM>>>(Wn1, nullptr, nullptr, NN);
    aggregate_kernel<128, true, 2, true><<<(NN * 32 + 255) / 256, 256>>>(nullptr);

    sgemm_mma_kernel<64, 0><<<g1, 256, SMEM>>>(Ws2, b2, out, NN);
    sgemm_mma_kernel<64, 3><<<g1, 256, SMEM>>>(Wn2, nullptr, nullptr, NN);
    aggregate_kernel<64, false, 0, false><<<(NN * 16 + 255) / 256, 256>>>(out);
}

// round 10
// speedup vs baseline: 4.5385x; 1.0561x over previous
#include <cuda_runtime.h>
#include <cuda_bf16.h>
#include <cstdint>

static const int NN = 50000;
static const int NE = 600000;
static const int NRB = 3128;                 // ceil(50048/16) 16-row blocks
static const int NFRAG = NRB * 256;          // uint4 fragment groups per buffer

// ---------------- scratch ----------------
__device__ float g_h0[NN * 128];
__device__ float g_h1[NN * 128];
__device__ float g_y[NN * 128];
__device__ uint4 g_afh[NFRAG];               // A fragments, hi bf16
__device__ uint4 g_afl[NFRAG];               // A fragments, lo bf16
__device__ float g_invdeg[NN];
__device__ int   g_count[NN];
__device__ int   g_offs[NN + 1];
__device__ int   g_cursor[NN];
__device__ int   g_srcs[NE];
__device__ int   g_is64;
__device__ int   g_bsum[128];
__device__ int   g_bbase[128];

__device__ __forceinline__ const float* sel_in(int SEL, const float* ext) {
    if (SEL == 1) return g_h0;
    if (SEL == 2) return g_h1;
    return ext;
}
__device__ __forceinline__ float* sel_out(int SEL, float* ext) {
    if (SEL == 1) return g_h0;
    if (SEL == 2) return g_h1;
    if (SEL == 3) return g_y;
    return ext;
}
__device__ __forceinline__ int edge_at(const void* ei, int i) {
    if (g_is64) return (int)((const long long*)ei)[i];
    return ((const int*)ei)[i];
}

__device__ __forceinline__ uint32_t smem_u32(const void* p) {
    uint32_t a;
    asm("{ .reg .u64 t; cvta.to.shared.u64 t, %1; cvt.u32.u64 %0, t; }" : "=r"(a) : "l"(p));
    return a;
}
__device__ __forceinline__ void ldsm_x4(uint32_t* r, uint32_t addr) {
    asm volatile("ldmatrix.sync.aligned.m8n8.x4.shared.b16 {%0,%1,%2,%3}, [%4];"
                 : "=r"(r[0]), "=r"(r[1]), "=r"(r[2]), "=r"(r[3]) : "r"(addr));
}
__device__ __forceinline__ void mma_bf16(float* c, const uint32_t* a, const uint32_t* b) {
    asm volatile(
        "mma.sync.aligned.m16n8k16.row.col.f32.bf16.bf16.f32 "
        "{%0,%1,%2,%3}, {%4,%5,%6,%7}, {%8,%9}, {%0,%1,%2,%3};"
        : "+f"(c[0]), "+f"(c[1]), "+f"(c[2]), "+f"(c[3])
        : "r"(a[0]), "r"(a[1]), "r"(a[2]), "r"(a[3]), "r"(b[0]), "r"(b[1]));
}
__device__ __forceinline__ void split_bf16(float v, __nv_bfloat16& h, __nv_bfloat16& l) {
    h = __float2bfloat16(v);
    l = __float2bfloat16(v - __bfloat162float(h));
}
// pack two f32 into (hi-word, lo-word) bf16x2
__device__ __forceinline__ void pack2(float a, float b, uint32_t& hw, uint32_t& lw) {
    __nv_bfloat16 ha, la, hb, lb;
    split_bf16(a, ha, la);
    split_bf16(b, hb, lb);
    __nv_bfloat162 ph; ph.x = ha; ph.y = hb;
    __nv_bfloat162 pl; pl.x = la; pl.y = lb;
    hw = *(uint32_t*)&ph;
    lw = *(uint32_t*)&pl;
}

// ---------------- dtype probe ----------------
__global__ void init_flag_kernel() { g_is64 = 1; }
__global__ void detect_kernel(const void* ei) {
    int i = blockIdx.x * blockDim.x + threadIdx.x;
    int bad = 0;
    if (i < 2 * NE) {
        long long v = ((const long long*)ei)[i];
        bad = (v < 0 || v >= NN) ? 1 : 0;
    }
    if (__syncthreads_or(bad)) {
        if (threadIdx.x == 0) g_is64 = 0;
    }
}

// ---------------- conv: f32 matrix [NN,128] -> mma A-fragment layout (hi/lo) ----------------
// fragment group i: rb=i>>8, ks=(i>>5)&7, lane=i&31
//   w0=(r0,cp0) w1=(r1,cp0) w2=(r0,cp1) w3=(r1,cp1); r0=rb*16+(lane>>2), r1=r0+8,
//   cp0=ks*8+(lane&3), cp1=cp0+4   (cp = column pair index, 2 cols per word)
template <int SSEL>
__global__ void conv_frag_kernel(const float* __restrict__ ext) {
    const float2* src = (const float2*)sel_in(SSEL, ext);
    int i = blockIdx.x * 256 + threadIdx.x;
    int rb = i >> 8, ks = (i >> 5) & 7, lane = i & 31;
    int r0 = rb * 16 + (lane >> 2), r1 = r0 + 8;
    int cp0 = ks * 8 + (lane & 3), cp1 = cp0 + 4;
    const float2 z = make_float2(0.f, 0.f);
    float2 v00 = (r0 < NN) ? src[(size_t)r0 * 64 + cp0] : z;
    float2 v10 = (r1 < NN) ? src[(size_t)r1 * 64 + cp0] : z;
    float2 v01 = (r0 < NN) ? src[(size_t)r0 * 64 + cp1] : z;
    float2 v11 = (r1 < NN) ? src[(size_t)r1 * 64 + cp1] : z;
    uint4 h, l;
    pack2(v00.x, v00.y, h.x, l.x);
    pack2(v10.x, v10.y, h.y, l.y);
    pack2(v01.x, v01.y, h.z, l.z);
    pack2(v11.x, v11.y, h.w, l.w);
    g_afh[i] = h;
    g_afl[i] = l;
}

// ---------------- CSR build ----------------
__global__ void zero_count_kernel() {
    int i = blockIdx.x * blockDim.x + threadIdx.x;
    if (i < NN) g_count[i] = 0;
}
__global__ void hist_kernel(const void* ei) {
    int i = blockIdx.x * blockDim.x + threadIdx.x;
    if (i < NE) {
        int d = edge_at(ei, NE + i);
        d = min(max(d, 0), NN - 1);
        atomicAdd(&g_count[d], 1);
    }
}

static const int SCAN_SEG = 512;
static const int SCAN_THR = 256;
static const int SCAN_NB  = (NN + SCAN_SEG - 1) / SCAN_SEG;  // 98

__global__ void scan1_kernel() {
    __shared__ int red[SCAN_THR];
    int b = blockIdx.x, t = threadIdx.x;
    int i0 = b * SCAN_SEG + 2 * t, i1 = i0 + 1;
    int s = 0;
    if (i0 < NN) s += g_count[i0];
    if (i1 < NN) s += g_count[i1];
    red[t] = s;
    __syncthreads();
    for (int d = SCAN_THR / 2; d > 0; d >>= 1) {
        if (t < d) red[t] += red[t + d];
        __syncthreads();
    }
    if (t == 0) g_bsum[b] = red[0];
}
__global__ void scan2_kernel() {
    __shared__ int sh[128];
    int t = threadIdx.x;
    sh[t] = (t < SCAN_NB) ? g_bsum[t] : 0;
    __syncthreads();
    for (int d = 1; d < 128; d <<= 1) {
        int v = sh[t];
        int u = (t >= d) ? sh[t - d] : 0;
        __syncthreads();
        sh[t] = v + u;
        __syncthreads();
    }
    if (t < SCAN_NB) g_bbase[t] = sh[t] - g_bsum[t];
    if (t == 127) g_offs[NN] = sh[127];
}
__global__ void scan3_kernel() {
    __shared__ int sh[SCAN_THR];
    int b = blockIdx.x, t = threadIdx.x;
    int i0 = b * SCAN_SEG + 2 * t, i1 = i0 + 1;
    int c0 = (i0 < NN) ? g_count[i0] : 0;
    int c1 = (i1 < NN) ? g_count[i1] : 0;
    int s = c0 + c1;
    sh[t] = s;
    __syncthreads();
    for (int d = 1; d < SCAN_THR; d <<= 1) {
        int v = sh[t];
        int u = (t >= d) ? sh[t - d] : 0;
        __syncthreads();
        sh[t] = v + u;
        __syncthreads();
    }
    int tb = g_bbase[b] + sh[t] - s;
    if (i0 < NN) { g_offs[i0] = tb;      g_cursor[i0] = tb;      g_invdeg[i0] = 1.0f / fmaxf((float)c0, 1.0f); }
    if (i1 < NN) { g_offs[i1] = tb + c0; g_cursor[i1] = tb + c0; g_invdeg[i1] = 1.0f / fmaxf((float)c1, 1.0f); }
}
__global__ void fill_kernel(const void* ei) {
    int i = blockIdx.x * blockDim.x + threadIdx.x;
    if (i < NE) {
        int s = edge_at(ei, i);
        int d = edge_at(ei, NE + i);
        s = min(max(s, 0), NN - 1);
        d = min(max(d, 0), NN - 1);
        int p = atomicAdd(&g_cursor[d], 1);
        g_srcs[p] = s;
    }
}

// ---------------- split-bf16 HMMA GEMM, A streamed as global fragments ----------------
// C[M, BNT] cols col0..col0+63 = A[M,128] @ W[128,BNT][:, col0:col0+64] (+bias)
// 512 threads, warp tile 32x16. smem = B tile only (34816 B).
template <int BNT, int CSEL>
__global__ __launch_bounds__(512, 2) void sgemm_mma_kernel(
    const float* __restrict__ W, const float* __restrict__ bias,
    float* __restrict__ Cext, int M)
{
    float* C = sel_out(CSEL, Cext);

    const int ROWB = 272;
    extern __shared__ char smem[];       // B: 64 rows hi + 64 rows lo
    const int OFF_BHI = 0;
    const int OFF_BLO = 64 * ROWB;       // 17408; total 34816

    uint32_t sb = smem_u32(smem);
    int tid = threadIdx.x, wid = tid >> 5, lane = tid & 31;
    int row0 = blockIdx.x * 128;
    int col0 = blockIdx.y * 64;

    // ---- convert/transpose W slice [128, 64] -> B[n][k] hi/lo ----
    {
        int n  = tid & 63;
        int kb = (tid >> 6) * 16;
        char* ph = smem + OFF_BHI + n * ROWB;
        char* pl = smem + OFF_BLO + n * ROWB;
#pragma unroll
        for (int k = kb; k < kb + 16; k += 2) {
            float v0 = W[(size_t)k * BNT + col0 + n];
            float v1 = W[(size_t)(k + 1) * BNT + col0 + n];
            uint32_t hw, lw;
            pack2(v0, v1, hw, lw);
            *(uint32_t*)(ph + k * 2) = hw;
            *(uint32_t*)(pl + k * 2) = lw;
        }
    }
    __syncthreads();

    // warps: wm 0..3 (32 rows), wn 0..3 (16 cols)
    int wm = wid & 3, wn = wid >> 2;
    int mrow = wm * 32;
    int ncol = wn * 16;
    int rbB = blockIdx.x * 8 + wm * 2;   // fragment row-block for mt=0

    float acc[2][2][4];
#pragma unroll
    for (int mt = 0; mt < 2; mt++)
#pragma unroll
        for (int nt = 0; nt < 2; nt++)
#pragma unroll
            for (int q = 0; q < 4; q++) acc[mt][nt][q] = 0.f;

    // B paired-x4 base: lanes 0-15 -> nt0 (n ncol..+7, k halves), lanes 16-31 -> nt1 (n+8)
    uint32_t nadd = ((lane >> 4) & 1) * 8;
    uint32_t cadd = ((lane >> 3) & 1) * 16;
    uint32_t bHiA = sb + OFF_BHI + (ncol + nadd + (lane & 7)) * ROWB + cadd;
    uint32_t bLoA = sb + OFF_BLO + (ncol + nadd + (lane & 7)) * ROWB + cadd;

#pragma unroll
    for (int ks = 0; ks < 8; ks++) {
        uint4 ah0 = g_afh[(size_t)((rbB + 0) * 8 + ks) * 32 + lane];
        uint4 ah1 = g_afh[(size_t)((rbB + 1) * 8 + ks) * 32 + lane];
        uint4 al0 = g_afl[(size_t)((rbB + 0) * 8 + ks) * 32 + lane];
        uint4 al1 = g_afl[(size_t)((rbB + 1) * 8 + ks) * 32 + lane];
        uint32_t bh[4], bl[4];
        ldsm_x4(bh, bHiA + ks * 32);
        ldsm_x4(bl, bLoA + ks * 32);
        const uint32_t* ah[2] = { (const uint32_t*)&ah0, (const uint32_t*)&ah1 };
        const uint32_t* al[2] = { (const uint32_t*)&al0, (const uint32_t*)&al1 };
#pragma unroll
        for (int mt = 0; mt < 2; mt++)
#pragma unroll
            for (int nt = 0; nt < 2; nt++) {
                float* a = acc[mt][nt];
                mma_bf16(a, ah[mt], &bh[nt * 2]);
                mma_bf16(a, ah[mt], &bl[nt * 2]);
                mma_bf16(a, al[mt], &bh[nt * 2]);
            }
    }

    // ---- epilogue ----
#pragma unroll
    for (int mt = 0; mt < 2; mt++) {
        int r0g = row0 + mrow + mt * 16 + (lane >> 2);
        int r1g = r0g + 8;
#pragma unroll
        for (int nt = 0; nt < 2; nt++) {
            int cc = col0 + ncol + nt * 8 + (lane & 3) * 2;
            float bx = bias ? bias[cc] : 0.f;
            float by = bias ? bias[cc + 1] : 0.f;
            if (r0g < M) {
                float2 v; v.x = acc[mt][nt][0] + bx; v.y = acc[mt][nt][1] + by;
                *(float2*)(C + (size_t)r0g * BNT + cc) = v;
            }
            if (r1g < M) {
                float2 v; v.x = acc[mt][nt][2] + bx; v.y = acc[mt][nt][3] + by;
                *(float2*)(C + (size_t)r1g * BNT + cc) = v;
            }
        }
    }
}

// ---------------- fused aggregate ----------------
template <int D, bool RELU, int OSEL>
__global__ void aggregate_kernel(float* __restrict__ Oext)
{
    float* out = sel_out(OSEL, Oext);
    const float4* yv = (const float4*)g_y;

    const int CH  = D / 4;
    const int NPW = 32 / CH;
    int gt   = blockIdx.x * blockDim.x + threadIdx.x;
    int warp = gt >> 5;
    int lane = gt & 31;
    int node = warp * NPW + lane / CH;
    int c    = lane % CH;
    if (node >= NN) return;

    int s = g_offs[node], e = g_offs[node + 1];
    float4 acc = make_float4(0.f, 0.f, 0.f, 0.f);
    int i = s;
    for (; i + 1 < e; i += 2) {
        int s0 = g_srcs[i], s1 = g_srcs[i + 1];
        float4 v0 = yv[(size_t)s0 * CH + c];
        float4 v1 = yv[(size_t)s1 * CH + c];
        acc.x += v0.x + v1.x; acc.y += v0.y + v1.y;
        acc.z += v0.z + v1.z; acc.w += v0.w + v1.w;
    }
    if (i < e) {
        int s0 = g_srcs[i];
        float4 v0 = yv[(size_t)s0 * CH + c];
        acc.x += v0.x; acc.y += v0.y; acc.z += v0.z; acc.w += v0.w;
    }
    float w = g_invdeg[node];
    float4* op = (float4*)out + (size_t)node * CH + c;
    float4 o = *op;
    o.x += w * acc.x; o.y += w * acc.y; o.z += w * acc.z; o.w += w * acc.w;
    if (RELU) {
        o.x = fmaxf(o.x, 0.f); o.y = fmaxf(o.y, 0.f);
        o.z = fmaxf(o.z, 0.f); o.w = fmaxf(o.w, 0.f);
    }
    *op = o;
}

// ---------------- launch ----------------
extern "C" void kernel_launch(void* const* d_in, const int* in_sizes, int n_in,
                              void* d_out, int out_size)
{
    const float* x   = (const float*)d_in[0];
    const void*  ei  = d_in[1];
    const float* Ws0 = (const float*)d_in[2];
    const float* Wn0 = (const float*)d_in[3];
    const float* b0  = (const float*)d_in[4];
    const float* Ws1 = (const float*)d_in[5];
    const float* Wn1 = (const float*)d_in[6];
    const float* b1  = (const float*)d_in[7];
    const float* Ws2 = (const float*)d_in[8];
    const float* Wn2 = (const float*)d_in[9];
    const float* b2  = (const float*)d_in[10];
    float* out = (float*)d_out;

    const int SMEM = 34816;
    cudaFuncSetAttribute(sgemm_mma_kernel<128, 1>, cudaFuncAttributeMaxDynamicSharedMemorySize, SMEM);
    cudaFuncSetAttribute(sgemm_mma_kernel<128, 2>, cudaFuncAttributeMaxDynamicSharedMemorySize, SMEM);
    cudaFuncSetAttribute(sgemm_mma_kernel<128, 3>, cudaFuncAttributeMaxDynamicSharedMemorySize, SMEM);
    cudaFuncSetAttribute(sgemm_mma_kernel<64, 0>,  cudaFuncAttributeMaxDynamicSharedMemorySize, SMEM);
    cudaFuncSetAttribute(sgemm_mma_kernel<64, 3>,  cudaFuncAttributeMaxDynamicSharedMemorySize, SMEM);

    const int tb = 256;
    const dim3 g2(391, 2), g1(391, 1);

    init_flag_kernel<<<1, 1>>>();
    detect_kernel<<<(2 * NE + tb - 1) / tb, tb>>>(ei);
    conv_frag_kernel<0><<<NRB, 256>>>(x);

    // 4th launch = big HMMA GEMM (ncu captures this one)
    sgemm_mma_kernel<128, 1><<<g2, 512, SMEM>>>(Ws0, b0, nullptr, NN);

    zero_count_kernel<<<(NN + tb - 1) / tb, tb>>>();
    hist_kernel<<<(NE + tb - 1) / tb, tb>>>(ei);
    scan1_kernel<<<SCAN_NB, SCAN_THR>>>();
    scan2_kernel<<<1, 128>>>();
    scan3_kernel<<<SCAN_NB, SCAN_THR>>>();
    fill_kernel<<<(NE + tb - 1) / tb, tb>>>(ei);

    sgemm_mma_kernel<128, 3><<<g2, 512, SMEM>>>(Wn0, nullptr, nullptr, NN);
    aggregate_kernel<128, true, 1><<<(NN * 32 + 255) / 256, 256>>>(nullptr);
    conv_frag_kernel<1><<<NRB, 256>>>(nullptr);

    sgemm_mma_kernel<128, 2><<<g2, 512, SMEM>>>(Ws1, b1, nullptr, NN);
    sgemm_mma_kernel<128, 3><<<g2, 512, SMEM>>>(Wn1, nullptr, nullptr, NN);
    aggregate_kernel<128, true, 2><<<(NN * 32 + 255) / 256, 256>>>(nullptr);
    conv_frag_kernel<2><<<NRB, 256>>>(nullptr);

    sgemm_mma_kernel<64, 0><<<g1, 512, SMEM>>>(Ws2, b2, out, NN);
    sgemm_mma_kernel<64, 3><<<g1, 512, SMEM>>>(Wn2, nullptr, nullptr, NN);
    aggregate_kernel<64, false, 0><<<(NN * 16 + 255) / 256, 256>>>(out);
}

// round 12
// speedup vs baseline: 4.7834x; 1.0540x over previous
#include <cuda_runtime.h>
#include <cuda_bf16.h>
#include <cstdint>

static const int NN = 50000;
static const int NE = 600000;
static const int NRB = 3128;                 // ceil(50048/16) 16-row blocks
static const int NFRAG = NRB * 256;          // uint4 fragment groups per buffer

// ---------------- scratch ----------------
__device__ float g_h0[NN * 128];
__device__ float g_h1[NN * 128];
__device__ float g_y[NN * 128];
__device__ uint4 g_afh[NFRAG];               // A fragments, hi bf16
__device__ uint4 g_afl[NFRAG];               // A fragments, lo bf16
__device__ __nv_bfloat16 g_wh[81920];        // all weights, transposed [n][k], hi
__device__ __nv_bfloat16 g_wl[81920];        // lo
__device__ float g_invdeg[NN];
__device__ int   g_count[NN];
__device__ int   g_offs[NN + 1];
__device__ int   g_cursor[NN];
__device__ int   g_srcs[NE];
__device__ int   g_is64;
__device__ int   g_bsum[128];
__device__ int   g_bbase[128];

// weight offsets in g_wh/g_wl (bf16 elements)
static const int WOFF_S0 = 0;
static const int WOFF_N0 = 16384;
static const int WOFF_S1 = 32768;
static const int WOFF_N1 = 49152;
static const int WOFF_S2 = 65536;
static const int WOFF_N2 = 73728;

__device__ __forceinline__ const float* sel_in(int SEL, const float* ext) {
    if (SEL == 1) return g_h0;
    if (SEL == 2) return g_h1;
    return ext;
}
__device__ __forceinline__ float* sel_out(int SEL, float* ext) {
    if (SEL == 1) return g_h0;
    if (SEL == 2) return g_h1;
    return ext;
}
__device__ __forceinline__ int edge_at(const void* ei, int i) {
    if (g_is64) return (int)((const long long*)ei)[i];
    return ((const int*)ei)[i];
}

__device__ __forceinline__ uint32_t smem_u32(const void* p) {
    uint32_t a;
    asm("{ .reg .u64 t; cvta.to.shared.u64 t, %1; cvt.u32.u64 %0, t; }" : "=r"(a) : "l"(p));
    return a;
}
__device__ __forceinline__ void ldsm_x4(uint32_t* r, uint32_t addr) {
    asm volatile("ldmatrix.sync.aligned.m8n8.x4.shared.b16 {%0,%1,%2,%3}, [%4];"
                 : "=r"(r[0]), "=r"(r[1]), "=r"(r[2]), "=r"(r[3]) : "r"(addr));
}
__device__ __forceinline__ void mma_bf16(float* c, const uint32_t* a, const uint32_t* b) {
    asm volatile(
        "mma.sync.aligned.m16n8k16.row.col.f32.bf16.bf16.f32 "
        "{%0,%1,%2,%3}, {%4,%5,%6,%7}, {%8,%9}, {%0,%1,%2,%3};"
        : "+f"(c[0]), "+f"(c[1]), "+f"(c[2]), "+f"(c[3])
        : "r"(a[0]), "r"(a[1]), "r"(a[2]), "r"(a[3]), "r"(b[0]), "r"(b[1]));
}
__device__ __forceinline__ void split_bf16(float v, __nv_bfloat16& h, __nv_bfloat16& l) {
    h = __float2bfloat16(v);
    l = __float2bfloat16(v - __bfloat162float(h));
}
__device__ __forceinline__ void pack2(float a, float b, uint32_t& hw, uint32_t& lw) {
    __nv_bfloat16 ha, la, hb, lb;
    split_bf16(a, ha, la);
    split_bf16(b, hb, lb);
    __nv_bfloat162 ph; ph.x = ha; ph.y = hb;
    __nv_bfloat162 pl; pl.x = la; pl.y = lb;
    hw = *(uint32_t*)&ph;
    lw = *(uint32_t*)&pl;
}

// ---------------- dtype probe ----------------
__global__ void init_flag_kernel() { g_is64 = 1; }
__global__ void detect_kernel(const void* ei) {
    int i = blockIdx.x * blockDim.x + threadIdx.x;
    int bad = 0;
    if (i < 2 * NE) {
        long long v = ((const long long*)ei)[i];
        bad = (v < 0 || v >= NN) ? 1 : 0;
    }
    if (__syncthreads_or(bad)) {
        if (threadIdx.x == 0) g_is64 = 0;
    }
}

// ---------------- weight conv: all 6 matrices -> transposed bf16 hi/lo, one launch ----------------
__global__ void conv_w_kernel(const float* __restrict__ W0s, const float* __restrict__ W0n,
                              const float* __restrict__ W1s, const float* __restrict__ W1n,
                              const float* __restrict__ W2s, const float* __restrict__ W2n)
{
    int i = blockIdx.x * 256 + threadIdx.x;   // 0..81919
    const float* src;
    int off, N;
    if      (i < 16384) { src = W0s; off = WOFF_S0; N = 128; }
    else if (i < 32768) { src = W0n; off = WOFF_N0; N = 128; }
    else if (i < 49152) { src = W1s; off = WOFF_S1; N = 128; }
    else if (i < 65536) { src = W1n; off = WOFF_N1; N = 128; }
    else if (i < 73728) { src = W2s; off = WOFF_S2; N = 64;  }
    else                { src = W2n; off = WOFF_N2; N = 64;  }
    int j = i - off;
    int n = j >> 7, k = j & 127;
    float v = src[(size_t)k * N + n];
    __nv_bfloat16 h, l;
    split_bf16(v, h, l);
    g_wh[i] = h;
    g_wl[i] = l;
}

// ---------------- conv: f32 matrix [NN,128] -> mma A-fragment layout (hi/lo) ----------------
template <int SSEL>
__global__ void conv_frag_kernel(const float* __restrict__ ext) {
    const float2* src = (const float2*)sel_in(SSEL, ext);
    int i = blockIdx.x * 256 + threadIdx.x;
    int rb = i >> 8, ks = (i >> 5) & 7, lane = i & 31;
    int r0 = rb * 16 + (lane >> 2), r1 = r0 + 8;
    int cp0 = ks * 8 + (lane & 3), cp1 = cp0 + 4;
    const float2 z = make_float2(0.f, 0.f);
    float2 v00 = (r0 < NN) ? src[(size_t)r0 * 64 + cp0] : z;
    float2 v10 = (r1 < NN) ? src[(size_t)r1 * 64 + cp0] : z;
    float2 v01 = (r0 < NN) ? src[(size_t)r0 * 64 + cp1] : z;
    float2 v11 = (r1 < NN) ? src[(size_t)r1 * 64 + cp1] : z;
    uint4 h, l;
    pack2(v00.x, v00.y, h.x, l.x);
    pack2(v10.x, v10.y, h.y, l.y);
    pack2(v01.x, v01.y, h.z, l.z);
    pack2(v11.x, v11.y, h.w, l.w);
    g_afh[i] = h;
    g_afl[i] = l;
}

// ---------------- CSR build ----------------
__global__ void zero_count_kernel() {
    int i = blockIdx.x * blockDim.x + threadIdx.x;
    if (i < NN) g_count[i] = 0;
}
__global__ void hist_kernel(const void* ei) {
    int i = blockIdx.x * blockDim.x + threadIdx.x;
    if (i < NE) {
        int d = edge_at(ei, NE + i);
        d = min(max(d, 0), NN - 1);
        atomicAdd(&g_count[d], 1);
    }
}

static const int SCAN_SEG = 512;
static const int SCAN_THR = 256;
static const int SCAN_NB  = (NN + SCAN_SEG - 1) / SCAN_SEG;  // 98

__global__ void scan1_kernel() {
    __shared__ int red[SCAN_THR];
    int b = blockIdx.x, t = threadIdx.x;
    int i0 = b * SCAN_SEG + 2 * t, i1 = i0 + 1;
    int s = 0;
    if (i0 < NN) s += g_count[i0];
    if (i1 < NN) s += g_count[i1];
    red[t] = s;
    __syncthreads();
    for (int d = SCAN_THR / 2; d > 0; d >>= 1) {
        if (t < d) red[t] += red[t + d];
        __syncthreads();
    }
    if (t == 0) g_bsum[b] = red[0];
}
__global__ void scan2_kernel() {
    __shared__ int sh[128];
    int t = threadIdx.x;
    sh[t] = (t < SCAN_NB) ? g_bsum[t] : 0;
    __syncthreads();
    for (int d = 1; d < 128; d <<= 1) {
        int v = sh[t];
        int u = (t >= d) ? sh[t - d] : 0;
        __syncthreads();
        sh[t] = v + u;
        __syncthreads();
    }
    if (t < SCAN_NB) g_bbase[t] = sh[t] - g_bsum[t];
    if (t == 127) g_offs[NN] = sh[127];
}
__global__ void scan3_kernel() {
    __shared__ int sh[SCAN_THR];
    int b = blockIdx.x, t = threadIdx.x;
    int i0 = b * SCAN_SEG + 2 * t, i1 = i0 + 1;
    int c0 = (i0 < NN) ? g_count[i0] : 0;
    int c1 = (i1 < NN) ? g_count[i1] : 0;
    int s = c0 + c1;
    sh[t] = s;
    __syncthreads();
    for (int d = 1; d < SCAN_THR; d <<= 1) {
        int v = sh[t];
        int u = (t >= d) ? sh[t - d] : 0;
        __syncthreads();
        sh[t] = v + u;
        __syncthreads();
    }
    int tb = g_bbase[b] + sh[t] - s;
    if (i0 < NN) { g_offs[i0] = tb;      g_cursor[i0] = tb;      g_invdeg[i0] = 1.0f / fmaxf((float)c0, 1.0f); }
    if (i1 < NN) { g_offs[i1] = tb + c0; g_cursor[i1] = tb + c0; g_invdeg[i1] = 1.0f / fmaxf((float)c1, 1.0f); }
}
__global__ void fill_kernel(const void* ei) {
    int i = blockIdx.x * blockDim.x + threadIdx.x;
    if (i < NE) {
        int s = edge_at(ei, i);
        int d = edge_at(ei, NE + i);
        s = min(max(s, 0), NN - 1);
        d = min(max(d, 0), NN - 1);
        int p = atomicAdd(&g_cursor[d], 1);
        g_srcs[p] = s;
    }
}

// ---------------- merged dual-output HMMA GEMM ----------------
// grid (391, 2*NOUT/64): low y-half -> C_self (+bias), high y-half -> g_y (neighbor).
template <int NOUT, int LOFF_S, int LOFF_N, int CSEL_S>
__global__ __launch_bounds__(512, 2) void sgemm_mma_kernel(
    const float* __restrict__ bias, float* __restrict__ Cext, int M)
{
    const int SLICES = NOUT / 64;
    int half  = blockIdx.y / SLICES;
    int slice = blockIdx.y % SLICES;

    const __nv_bfloat16* wh = g_wh + (half ? LOFF_N : LOFF_S) + slice * 64 * 128;
    const __nv_bfloat16* wl = g_wl + (half ? LOFF_N : LOFF_S) + slice * 64 * 128;
    float* C = half ? g_y : sel_out(CSEL_S, Cext);
    const float* bb = half ? nullptr : bias;
    int col0 = slice * 64;

    const int ROWB = 272;
    extern __shared__ char smem[];
    const int OFF_BHI = 0;
    const int OFF_BLO = 64 * ROWB;       // total 34816

    uint32_t sb = smem_u32(smem);
    int tid = threadIdx.x, wid = tid >> 5, lane = tid & 31;
    int row0 = blockIdx.x * 128;

    // ---- copy pre-converted B tile: 64 rows x 16 uint4 chunks (256 B/row) ----
#pragma unroll
    for (int i = tid; i < 64 * 16; i += 512) {
        int n = i >> 4, ch = i & 15;
        *(uint4*)(smem + OFF_BHI + n * ROWB + ch * 16) = *(const uint4*)(wh + n * 128 + ch * 8);
        *(uint4*)(smem + OFF_BLO + n * ROWB + ch * 16) = *(const uint4*)(wl + n * 128 + ch * 8);
    }
    __syncthreads();

    // warps: wm 0..3 (32 rows), wn 0..3 (16 cols)
    int wm = wid & 3, wn = wid >> 2;
    int mrow = wm * 32;
    int ncol = wn * 16;
    int rbB = blockIdx.x * 8 + wm * 2;

    float acc[2][2][4];
#pragma unroll
    for (int mt = 0; mt < 2; mt++)
#pragma unroll
        for (int nt = 0; nt < 2; nt++)
#pragma unroll
            for (int q = 0; q < 4; q++) acc[mt][nt][q] = 0.f;

    uint32_t nadd = ((lane >> 4) & 1) * 8;
    uint32_t cadd = ((lane >> 3) & 1) * 16;
    uint32_t bHiA = sb + OFF_BHI + (ncol + nadd + (lane & 7)) * ROWB + cadd;
    uint32_t bLoA = sb + OFF_BLO + (ncol + nadd + (lane & 7)) * ROWB + cadd;

#pragma unroll
    for (int ks = 0; ks < 8; ks++) {
        uint4 ah0 = g_afh[(size_t)((rbB + 0) * 8 + ks) * 32 + lane];
        uint4 ah1 = g_afh[(size_t)((rbB + 1) * 8 + ks) * 32 + lane];
        uint4 al0 = g_afl[(size_t)((rbB + 0) * 8 + ks) * 32 + lane];
        uint4 al1 = g_afl[(size_t)((rbB + 1) * 8 + ks) * 32 + lane];
        uint32_t bh[4], bl[4];
        ldsm_x4(bh, bHiA + ks * 32);
        ldsm_x4(bl, bLoA + ks * 32);
        const uint32_t* ah[2] = { (const uint32_t*)&ah0, (const uint32_t*)&ah1 };
        const uint32_t* al[2] = { (const uint32_t*)&al0, (const uint32_t*)&al1 };
#pragma unroll
        for (int mt = 0; mt < 2; mt++)
#pragma unroll
            for (int nt = 0; nt < 2; nt++) {
                float* a = acc[mt][nt];
                mma_bf16(a, ah[mt], &bh[nt * 2]);
                mma_bf16(a, ah[mt], &bl[nt * 2]);
                mma_bf16(a, al[mt], &bh[nt * 2]);
            }
    }

    // ---- epilogue ----
#pragma unroll
    for (int mt = 0; mt < 2; mt++) {
        int r0g = row0 + mrow + mt * 16 + (lane >> 2);
        int r1g = r0g + 8;
#pragma unroll
        for (int nt = 0; nt < 2; nt++) {
            int cc = col0 + ncol + nt * 8 + (lane & 3) * 2;
            float bx = bb ? bb[cc] : 0.f;
            float by = bb ? bb[cc + 1] : 0.f;
            if (r0g < M) {
                float2 v; v.x = acc[mt][nt][0] + bx; v.y = acc[mt][nt][1] + by;
                *(float2*)(C + (size_t)r0g * NOUT + cc) = v;
            }
            if (r1g < M) {
                float2 v; v.x = acc[mt][nt][2] + bx; v.y = acc[mt][nt][3] + by;
                *(float2*)(C + (size_t)r1g * NOUT + cc) = v;
            }
        }
    }
}

// ---------------- fused aggregate ----------------
template <int D, bool RELU, int OSEL>
__global__ void aggregate_kernel(float* __restrict__ Oext)
{
    float* out = sel_out(OSEL, Oext);
    const float4* yv = (const float4*)g_y;

    const int CH  = D / 4;
    const int NPW = 32 / CH;
    int gt   = blockIdx.x * blockDim.x + threadIdx.x;
    int warp = gt >> 5;
    int lane = gt & 31;
    int node = warp * NPW + lane / CH;
    int c    = lane % CH;
    if (node >= NN) return;

    int s = g_offs[node], e = g_offs[node + 1];
    float4 acc = make_float4(0.f, 0.f, 0.f, 0.f);
    int i = s;
    for (; i + 1 < e; i += 2) {
        int s0 = g_srcs[i], s1 = g_srcs[i + 1];
        float4 v0 = yv[(size_t)s0 * CH + c];
        float4 v1 = yv[(size_t)s1 * CH + c];
        acc.x += v0.x + v1.x; acc.y += v0.y + v1.y;
        acc.z += v0.z + v1.z; acc.w += v0.w + v1.w;
    }
    if (i < e) {
        int s0 = g_srcs[i];
        float4 v0 = yv[(size_t)s0 * CH + c];
        acc.x += v0.x; acc.y += v0.y; acc.z += v0.z; acc.w += v0.w;
    }
    float w = g_invdeg[node];
    float4* op = (float4*)out + (size_t)node * CH + c;
    float4 o = *op;
    o.x += w * acc.x; o.y += w * acc.y; o.z += w * acc.z; o.w += w * acc.w;
    if (RELU) {
        o.x = fmaxf(o.x, 0.f); o.y = fmaxf(o.y, 0.f);
        o.z = fmaxf(o.z, 0.f); o.w = fmaxf(o.w, 0.f);
    }
    *op = o;
}

// ---------------- launch ----------------
extern "C" void kernel_launch(void* const* d_in, const int* in_sizes, int n_in,
                              void* d_out, int out_size)
{
    const float* x   = (const float*)d_in[0];
    const void*  ei  = d_in[1];
    const float* Ws0 = (const float*)d_in[2];
    const float* Wn0 = (const float*)d_in[3];
    const float* b0  = (const float*)d_in[4];
    const float* Ws1 = (const float*)d_in[5];
    const float* Wn1 = (const float*)d_in[6];
    const float* b1  = (const float*)d_in[7];
    const float* Ws2 = (const float*)d_in[8];
    const float* Wn2 = (const float*)d_in[9];
    const float* b2  = (const float*)d_in[10];
    float* out = (float*)d_out;

    const int SMEM = 34816;
    cudaFuncSetAttribute(sgemm_mma_kernel<128, WOFF_S0, WOFF_N0, 1>, cudaFuncAttributeMaxDynamicSharedMemorySize, SMEM);
    cudaFuncSetAttribute(sgemm_mma_kernel<128, WOFF_S1, WOFF_N1, 2>, cudaFuncAttributeMaxDynamicSharedMemorySize, SMEM);
    cudaFuncSetAttribute(sgemm_mma_kernel<64,  WOFF_S2, WOFF_N2, 0>, cudaFuncAttributeMaxDynamicSharedMemorySize, SMEM);

    const int tb = 256;
    const dim3 gL01(391, 4), gL2(391, 2);

    init_flag_kernel<<<1, 1>>>();
    detect_kernel<<<(2 * NE + tb - 1) / tb, tb>>>(ei);
    conv_frag_kernel<0><<<NRB, 256>>>(x);
    conv_w_kernel<<<320, 256>>>(Ws0, Wn0, Ws1, Wn1, Ws2, Wn2);

    // layer 0: both GEMMs in one launch
    sgemm_mma_kernel<128, WOFF_S0, WOFF_N0, 1><<<gL01, 512, SMEM>>>(b0, nullptr, NN);

    zero_count_kernel<<<(NN + tb - 1) / tb, tb>>>();
    hist_kernel<<<(NE + tb - 1) / tb, tb>>>(ei);
    scan1_kernel<<<SCAN_NB, SCAN_THR>>>();
    scan2_kernel<<<1, 128>>>();
    scan3_kernel<<<SCAN_NB, SCAN_THR>>>();
    fill_kernel<<<(NE + tb - 1) / tb, tb>>>(ei);

    aggregate_kernel<128, true, 1><<<(NN * 32 + 255) / 256, 256>>>(nullptr);
    conv_frag_kernel<1><<<NRB, 256>>>(nullptr);

    sgemm_mma_kernel<128, WOFF_S1, WOFF_N1, 2><<<gL01, 512, SMEM>>>(b1, nullptr, NN);
    aggregate_kernel<128, true, 2><<<(NN * 32 + 255) / 256, 256>>>(nullptr);
    conv_frag_kernel<2><<<NRB, 256>>>(nullptr);

    sgemm_mma_kernel<64, WOFF_S2, WOFF_N2, 0><<<gL2, 512, SMEM>>>(b2, out, NN);
    aggregate_kernel<64, false, 0><<<(NN * 16 + 255) / 256, 256>>>(out);
}

// round 13
// speedup vs baseline: 5.1472x; 1.0761x over previous
#include <cuda_runtime.h>
#include <cuda_bf16.h>
#include <cstdint>

static const int NN = 50000;
static const int NE = 600000;
static const int NRB = 3128;                 // ceil(50048/16) 16-row blocks
static const int NFRAG = NRB * 256;          // uint4 fragment groups per buffer

// ---------------- scratch ----------------
__device__ float g_h0[NN * 128];
__device__ float g_h1[NN * 128];
__device__ float g_y[NN * 128];
__device__ uint4 g_afh[NFRAG];               // A fragments, hi bf16
__device__ uint4 g_afl[NFRAG];               // A fragments, lo bf16
__device__ __nv_bfloat16 g_wh[81920];        // all weights, transposed [n][k], hi
__device__ __nv_bfloat16 g_wl[81920];        // lo
__device__ float g_invdeg[NN];
__device__ int   g_count[NN];
__device__ int   g_offs[NN + 1];
__device__ int   g_cursor[NN];
__device__ int   g_srcs[NE];
__device__ int   g_is64;
__device__ int   g_bsum[128];
__device__ int   g_bbase[128];

// weight offsets in g_wh/g_wl (bf16 elements)
static const int WOFF_S0 = 0;
static const int WOFF_N0 = 16384;
static const int WOFF_S1 = 32768;
static const int WOFF_N1 = 49152;
static const int WOFF_S2 = 65536;
static const int WOFF_N2 = 73728;

__device__ __forceinline__ float* sel_out(int SEL, float* ext) {
    if (SEL == 1) return g_h0;
    if (SEL == 2) return g_h1;
    return ext;
}
__device__ __forceinline__ int edge_at(const void* ei, int i) {
    if (g_is64) return (int)((const long long*)ei)[i];
    return ((const int*)ei)[i];
}

__device__ __forceinline__ uint32_t smem_u32(const void* p) {
    uint32_t a;
    asm("{ .reg .u64 t; cvta.to.shared.u64 t, %1; cvt.u32.u64 %0, t; }" : "=r"(a) : "l"(p));
    return a;
}
__device__ __forceinline__ void ldsm_x4(uint32_t* r, uint32_t addr) {
    asm volatile("ldmatrix.sync.aligned.m8n8.x4.shared.b16 {%0,%1,%2,%3}, [%4];"
                 : "=r"(r[0]), "=r"(r[1]), "=r"(r[2]), "=r"(r[3]) : "r"(addr));
}
__device__ __forceinline__ void mma_bf16(float* c, const uint32_t* a, const uint32_t* b) {
    asm volatile(
        "mma.sync.aligned.m16n8k16.row.col.f32.bf16.bf16.f32 "
        "{%0,%1,%2,%3}, {%4,%5,%6,%7}, {%8,%9}, {%0,%1,%2,%3};"
        : "+f"(c[0]), "+f"(c[1]), "+f"(c[2]), "+f"(c[3])
        : "r"(a[0]), "r"(a[1]), "r"(a[2]), "r"(a[3]), "r"(b[0]), "r"(b[1]));
}
__device__ __forceinline__ void split_bf16(float v, __nv_bfloat16& h, __nv_bfloat16& l) {
    h = __float2bfloat16(v);
    l = __float2bfloat16(v - __bfloat162float(h));
}
__device__ __forceinline__ void pack2(float a, float b, uint32_t& hw, uint32_t& lw) {
    __nv_bfloat16 ha, la, hb, lb;
    split_bf16(a, ha, la);
    split_bf16(b, hb, lb);
    __nv_bfloat162 ph; ph.x = ha; ph.y = hb;
    __nv_bfloat162 pl; pl.x = la; pl.y = lb;
    hw = *(uint32_t*)&ph;
    lw = *(uint32_t*)&pl;
}

// ---------------- dtype probe ----------------
__global__ void init_flag_kernel() { g_is64 = 1; }
__global__ void detect_kernel(const void* ei) {
    int i = blockIdx.x * blockDim.x + threadIdx.x;
    int bad = 0;
    if (i < 2 * NE) {
        long long v = ((const long long*)ei)[i];
        bad = (v < 0 || v >= NN) ? 1 : 0;
    }
    if (__syncthreads_or(bad)) {
        if (threadIdx.x == 0) g_is64 = 0;
    }
}

// ---------------- weight conv: all 6 matrices -> transposed bf16 hi/lo ----------------
__global__ void conv_w_kernel(const float* __restrict__ W0s, const float* __restrict__ W0n,
                              const float* __restrict__ W1s, const float* __restrict__ W1n,
                              const float* __restrict__ W2s, const float* __restrict__ W2n)
{
    int i = blockIdx.x * 256 + threadIdx.x;   // 0..81919
    const float* src;
    int off, N;
    if      (i < 16384) { src = W0s; off = WOFF_S0; N = 128; }
    else if (i < 32768) { src = W0n; off = WOFF_N0; N = 128; }
    else if (i < 49152) { src = W1s; off = WOFF_S1; N = 128; }
    else if (i < 65536) { src = W1n; off = WOFF_N1; N = 128; }
    else if (i < 73728) { src = W2s; off = WOFF_S2; N = 64;  }
    else                { src = W2n; off = WOFF_N2; N = 64;  }
    int j = i - off;
    int n = j >> 7, k = j & 127;
    float v = src[(size_t)k * N + n];
    __nv_bfloat16 h, l;
    split_bf16(v, h, l);
    g_wh[i] = h;
    g_wl[i] = l;
}

// ---------------- conv: f32 x [NN,128] -> A fragments (hi/lo) ----------------
__global__ void conv_x_frag_kernel(const float* __restrict__ x) {
    const float2* src = (const float2*)x;
    int i = blockIdx.x * 256 + threadIdx.x;
    int rb = i >> 8, ks = (i >> 5) & 7, lane = i & 31;
    int r0 = rb * 16 + (lane >> 2), r1 = r0 + 8;
    int cp0 = ks * 8 + (lane & 3), cp1 = cp0 + 4;
    const float2 z = make_float2(0.f, 0.f);
    float2 v00 = (r0 < NN) ? src[(size_t)r0 * 64 + cp0] : z;
    float2 v10 = (r1 < NN) ? src[(size_t)r1 * 64 + cp0] : z;
    float2 v01 = (r0 < NN) ? src[(size_t)r0 * 64 + cp1] : z;
    float2 v11 = (r1 < NN) ? src[(size_t)r1 * 64 + cp1] : z;
    uint4 h, l;
    pack2(v00.x, v00.y, h.x, l.x);
    pack2(v10.x, v10.y, h.y, l.y);
    pack2(v01.x, v01.y, h.z, l.z);
    pack2(v11.x, v11.y, h.w, l.w);
    g_afh[i] = h;
    g_afl[i] = l;
}

// ---------------- CSR build ----------------
__global__ void zero_count_kernel() {
    int i = blockIdx.x * blockDim.x + threadIdx.x;
    if (i < NN) g_count[i] = 0;
}
__global__ void hist_kernel(const void* ei) {
    int i = blockIdx.x * blockDim.x + threadIdx.x;
    if (i < NE) {
        int d = edge_at(ei, NE + i);
        d = min(max(d, 0), NN - 1);
        atomicAdd(&g_count[d], 1);
    }
}

static const int SCAN_SEG = 512;
static const int SCAN_THR = 256;
static const int SCAN_NB  = (NN + SCAN_SEG - 1) / SCAN_SEG;  // 98

__global__ void scan1_kernel() {
    __shared__ int red[SCAN_THR];
    int b = blockIdx.x, t = threadIdx.x;
    int i0 = b * SCAN_SEG + 2 * t, i1 = i0 + 1;
    int s = 0;
    if (i0 < NN) s += g_count[i0];
    if (i1 < NN) s += g_count[i1];
    red[t] = s;
    __syncthreads();
    for (int d = SCAN_THR / 2; d > 0; d >>= 1) {
        if (t < d) red[t] += red[t + d];
        __syncthreads();
    }
    if (t == 0) g_bsum[b] = red[0];
}
__global__ void scan2_kernel() {
    __shared__ int sh[128];
    int t = threadIdx.x;
    sh[t] = (t < SCAN_NB) ? g_bsum[t] : 0;
    __syncthreads();
    for (int d = 1; d < 128; d <<= 1) {
        int v = sh[t];
        int u = (t >= d) ? sh[t - d] : 0;
        __syncthreads();
        sh[t] = v + u;
        __syncthreads();
    }
    if (t < SCAN_NB) g_bbase[t] = sh[t] - g_bsum[t];
    if (t == 127) g_offs[NN] = sh[127];
}
__global__ void scan3_kernel() {
    __shared__ int sh[SCAN_THR];
    int b = blockIdx.x, t = threadIdx.x;
    int i0 = b * SCAN_SEG + 2 * t, i1 = i0 + 1;
    int c0 = (i0 < NN) ? g_count[i0] : 0;
    int c1 = (i1 < NN) ? g_count[i1] : 0;
    int s = c0 + c1;
    sh[t] = s;
    __syncthreads();
    for (int d = 1; d < SCAN_THR; d <<= 1) {
        int v = sh[t];
        int u = (t >= d) ? sh[t - d] : 0;
        __syncthreads();
        sh[t] = v + u;
        __syncthreads();
    }
    int tb = g_bbase[b] + sh[t] - s;
    if (i0 < NN) { g_offs[i0] = tb;      g_cursor[i0] = tb;      g_invdeg[i0] = 1.0f / fmaxf((float)c0, 1.0f); }
    if (i1 < NN) { g_offs[i1] = tb + c0; g_cursor[i1] = tb + c0; g_invdeg[i1] = 1.0f / fmaxf((float)c1, 1.0f); }
}
__global__ void fill_kernel(const void* ei) {
    int i = blockIdx.x * blockDim.x + threadIdx.x;
    if (i < NE) {
        int s = edge_at(ei, i);
        int d = edge_at(ei, NE + i);
        s = min(max(s, 0), NN - 1);
        d = min(max(d, 0), NN - 1);
        int p = atomicAdd(&g_cursor[d], 1);
        g_srcs[p] = s;
    }
}

// ---------------- merged dual-output HMMA GEMM ----------------
// grid (391, 2*NOUT/64): low y-half -> C_self (+bias), high y-half -> g_y (neighbor).
template <int NOUT, int LOFF_S, int LOFF_N, int CSEL_S>
__global__ __launch_bounds__(512, 2) void sgemm_mma_kernel(
    const float* __restrict__ bias, float* __restrict__ Cext, int M)
{
    const int SLICES = NOUT / 64;
    int half  = blockIdx.y / SLICES;
    int slice = blockIdx.y % SLICES;

    const __nv_bfloat16* wh = g_wh + (half ? LOFF_N : LOFF_S) + slice * 64 * 128;
    const __nv_bfloat16* wl = g_wl + (half ? LOFF_N : LOFF_S) + slice * 64 * 128;
    float* C = half ? g_y : sel_out(CSEL_S, Cext);
    const float* bb = half ? nullptr : bias;
    int col0 = slice * 64;

    const int ROWB = 272;
    extern __shared__ char smem[];
    const int OFF_BHI = 0;
    const int OFF_BLO = 64 * ROWB;       // total 34816

    uint32_t sb = smem_u32(smem);
    int tid = threadIdx.x, wid = tid >> 5, lane = tid & 31;
    int row0 = blockIdx.x * 128;

    // ---- copy pre-converted B tile: 64 rows x 16 uint4 chunks (256 B/row) ----
#pragma unroll
    for (int i = tid; i < 64 * 16; i += 512) {
        int n = i >> 4, ch = i & 15;
        *(uint4*)(smem + OFF_BHI + n * ROWB + ch * 16) = *(const uint4*)(wh + n * 128 + ch * 8);
        *(uint4*)(smem + OFF_BLO + n * ROWB + ch * 16) = *(const uint4*)(wl + n * 128 + ch * 8);
    }
    __syncthreads();

    int wm = wid & 3, wn = wid >> 2;
    int mrow = wm * 32;
    int ncol = wn * 16;
    int rbB = blockIdx.x * 8 + wm * 2;

    float acc[2][2][4];
#pragma unroll
    for (int mt = 0; mt < 2; mt++)
#pragma unroll
        for (int nt = 0; nt < 2; nt++)
#pragma unroll
            for (int q = 0; q < 4; q++) acc[mt][nt][q] = 0.f;

    uint32_t nadd = ((lane >> 4) & 1) * 8;
    uint32_t cadd = ((lane >> 3) & 1) * 16;
    uint32_t bHiA = sb + OFF_BHI + (ncol + nadd + (lane & 7)) * ROWB + cadd;
    uint32_t bLoA = sb + OFF_BLO + (ncol + nadd + (lane & 7)) * ROWB + cadd;

#pragma unroll
    for (int ks = 0; ks < 8; ks++) {
        uint4 ah0 = g_afh[(size_t)((rbB + 0) * 8 + ks) * 32 + lane];
        uint4 ah1 = g_afh[(size_t)((rbB + 1) * 8 + ks) * 32 + lane];
        uint4 al0 = g_afl[(size_t)((rbB + 0) * 8 + ks) * 32 + lane];
        uint4 al1 = g_afl[(size_t)((rbB + 1) * 8 + ks) * 32 + lane];
        uint32_t bh[4], bl[4];
        ldsm_x4(bh, bHiA + ks * 32);
        ldsm_x4(bl, bLoA + ks * 32);
        const uint32_t* ah[2] = { (const uint32_t*)&ah0, (const uint32_t*)&ah1 };
        const uint32_t* al[2] = { (const uint32_t*)&al0, (const uint32_t*)&al1 };
#pragma unroll
        for (int mt = 0; mt < 2; mt++)
#pragma unroll
            for (int nt = 0; nt < 2; nt++) {
                float* a = acc[mt][nt];
                mma_bf16(a, ah[mt], &bh[nt * 2]);
                mma_bf16(a, ah[mt], &bl[nt * 2]);
                mma_bf16(a, al[mt], &bh[nt * 2]);
            }
    }

#pragma unroll
    for (int mt = 0; mt < 2; mt++) {
        int r0g = row0 + mrow + mt * 16 + (lane >> 2);
        int r1g = r0g + 8;
#pragma unroll
        for (int nt = 0; nt < 2; nt++) {
            int cc = col0 + ncol + nt * 8 + (lane & 3) * 2;
            float bx = bb ? bb[cc] : 0.f;
            float by = bb ? bb[cc + 1] : 0.f;
            if (r0g < M) {
                float2 v; v.x = acc[mt][nt][0] + bx; v.y = acc[mt][nt][1] + by;
                *(float2*)(C + (size_t)r0g * NOUT + cc) = v;
            }
            if (r1g < M) {
                float2 v; v.x = acc[mt][nt][2] + bx; v.y = acc[mt][nt][3] + by;
                *(float2*)(C + (size_t)r1g * NOUT + cc) = v;
            }
        }
    }
}

// ---------------- fused aggregate + relu + fragment emission (layers 0/1) ----------------
// 512 threads = 16 nodes (one full fragment row-block). Gathers, stages 16x128 f32 in smem,
// then 256 threads emit the rb's A fragments (hi/lo) coalesced. No f32 h write-back.
template <int OSEL>
__global__ __launch_bounds__(512) void agg_frag_kernel()
{
    __shared__ float sh[16][132];            // row stride 132 floats (16B-aligned, 4-bank shift)
    const float4* yv = (const float4*)g_y;
    const float* self = (OSEL == 1) ? g_h0 : g_h1;

    int rb = blockIdx.x;
    int tid = threadIdx.x, w = tid >> 5, lane = tid & 31;
    int node = rb * 16 + w;

    float4 o = make_float4(0.f, 0.f, 0.f, 0.f);
    if (node < NN) {
        int s = g_offs[node], e = g_offs[node + 1];
        float4 acc = make_float4(0.f, 0.f, 0.f, 0.f);
        int i = s;
        for (; i + 1 < e; i += 2) {
            int s0 = g_srcs[i], s1 = g_srcs[i + 1];
            float4 v0 = yv[(size_t)s0 * 32 + lane];
            float4 v1 = yv[(size_t)s1 * 32 + lane];
            acc.x += v0.x + v1.x; acc.y += v0.y + v1.y;
            acc.z += v0.z + v1.z; acc.w += v0.w + v1.w;
        }
        if (i < e) {
            int s0 = g_srcs[i];
            float4 v0 = yv[(size_t)s0 * 32 + lane];
            acc.x += v0.x; acc.y += v0.y; acc.z += v0.z; acc.w += v0.w;
        }
        float wg = g_invdeg[node];
        float4 sf = ((const float4*)self)[(size_t)node * 32 + lane];
        o.x = fmaxf(sf.x + wg * acc.x, 0.f);
        o.y = fmaxf(sf.y + wg * acc.y, 0.f);
        o.z = fmaxf(sf.z + wg * acc.z, 0.f);
        o.w = fmaxf(sf.w + wg * acc.w, 0.f);
    }
    *(float4*)&sh[w][lane * 4] = o;
    __syncthreads();

    if (tid < 256) {
        int ks = tid >> 5, lf = tid & 31;
        int r0 = lf >> 2, r1 = r0 + 8;
        int cp0 = ks * 8 + (lf & 3), cp1 = cp0 + 4;
        uint4 h, l;
        pack2(sh[r0][cp0 * 2], sh[r0][cp0 * 2 + 1], h.x, l.x);
        pack2(sh[r1][cp0 * 2], sh[r1][cp0 * 2 + 1], h.y, l.y);
        pack2(sh[r0][cp1 * 2], sh[r0][cp1 * 2 + 1], h.z, l.z);
        pack2(sh[r1][cp1 * 2], sh[r1][cp1 * 2 + 1], h.w, l.w);
        size_t idx = (size_t)(rb * 8 + ks) * 32 + lf;
        g_afh[idx] = h;
        g_afl[idx] = l;
    }
}

// ---------------- final aggregate (D=64, writes d_out, no relu) ----------------
__global__ void agg_final_kernel(float* __restrict__ out)
{
    const float4* yv = (const float4*)g_y;
    const int CH = 16;                 // 64/4
    int gt   = blockIdx.x * blockDim.x + threadIdx.x;
    int warp = gt >> 5;
    int lane = gt & 31;
    int node = warp * 2 + lane / CH;
    int c    = lane % CH;
    if (node >= NN) return;

    int s = g_offs[node], e = g_offs[node + 1];
    float4 acc = make_float4(0.f, 0.f, 0.f, 0.f);
    int i = s;
    for (; i + 1 < e; i += 2) {
        int s0 = g_srcs[i], s1 = g_srcs[i + 1];
        float4 v0 = yv[(size_t)s0 * CH + c];
        float4 v1 = yv[(size_t)s1 * CH + c];
        acc.x += v0.x + v1.x; acc.y += v0.y + v1.y;
        acc.z += v0.z + v1.z; acc.w += v0.w + v1.w;
    }
    if (i < e) {
        int s0 = g_srcs[i];
        float4 v0 = yv[(size_t)s0 * CH + c];
        acc.x += v0.x; acc.y += v0.y; acc.z += v0.z; acc.w += v0.w;
    }
    float w = g_invdeg[node];
    float4* op = (float4*)out + (size_t)node * CH + c;
    float4 o = *op;
    o.x += w * acc.x; o.y += w * acc.y; o.z += w * acc.z; o.w += w * acc.w;
    *op = o;
}

// ---------------- launch ----------------
extern "C" void kernel_launch(void* const* d_in, const int* in_sizes, int n_in,
                              void* d_out, int out_size)
{
    const float* x   = (const float*)d_in[0];
    const void*  ei  = d_in[1];
    const float* Ws0 = (const float*)d_in[2];
    const float* Wn0 = (const float*)d_in[3];
    const float* b0  = (const float*)d_in[4];
    const float* Ws1 = (const float*)d_in[5];
    const float* Wn1 = (const float*)d_in[6];
    const float* b1  = (const float*)d_in[7];
    const float* Ws2 = (const float*)d_in[8];
    const float* Wn2 = (const float*)d_in[9];
    const float* b2  = (const float*)d_in[10];
    float* out = (float*)d_out;

    const int SMEM = 34816;
    cudaFuncSetAttribute(sgemm_mma_kernel<128, WOFF_S0, WOFF_N0, 1>, cudaFuncAttributeMaxDynamicSharedMemorySize, SMEM);
    cudaFuncSetAttribute(sgemm_mma_kernel<128, WOFF_S1, WOFF_N1, 2>, cudaFuncAttributeMaxDynamicSharedMemorySize, SMEM);
    cudaFuncSetAttribute(sgemm_mma_kernel<64,  WOFF_S2, WOFF_N2, 0>, cudaFuncAttributeMaxDynamicSharedMemorySize, SMEM);

    const int tb = 256;
    const dim3 gL01(391, 4), gL2(391, 2);

    // fork-join: CSR build overlaps conv+GEMM0 on a side stream
    cudaStream_t s2;
    cudaStreamCreateWithFlags(&s2, cudaStreamNonBlocking);
    cudaEvent_t evF, evJ;
    cudaEventCreateWithFlags(&evF, cudaEventDisableTiming);
    cudaEventCreateWithFlags(&evJ, cudaEventDisableTiming);

    init_flag_kernel<<<1, 1>>>();
    detect_kernel<<<(2 * NE + tb - 1) / tb, tb>>>(ei);
    cudaEventRecord(evF, 0);
    cudaStreamWaitEvent(s2, evF, 0);

    // side stream: CSR build
    zero_count_kernel<<<(NN + tb - 1) / tb, tb, 0, s2>>>();
    hist_kernel<<<(NE + tb - 1) / tb, tb, 0, s2>>>(ei);
    scan1_kernel<<<SCAN_NB, SCAN_THR, 0, s2>>>();
    scan2_kernel<<<1, 128, 0, s2>>>();
    scan3_kernel<<<SCAN_NB, SCAN_THR, 0, s2>>>();
    fill_kernel<<<(NE + tb - 1) / tb, tb, 0, s2>>>(ei);
    cudaEventRecord(evJ, s2);

    // main stream: conversions + layer-0 GEMM (overlapped with CSR)
    conv_x_frag_kernel<<<NRB, 256>>>(x);
    conv_w_kernel<<<320, 256>>>(Ws0, Wn0, Ws1, Wn1, Ws2, Wn2);
    sgemm_mma_kernel<128, WOFF_S0, WOFF_N0, 1><<<gL01, 512, SMEM>>>(b0, nullptr, NN);
    cudaStreamWaitEvent(0, evJ, 0);

    agg_frag_kernel<1><<<NRB, 512>>>();
    sgemm_mma_kernel<128, WOFF_S1, WOFF_N1, 2><<<gL01, 512, SMEM>>>(b1, nullptr, NN);
    agg_frag_kernel<2><<<NRB, 512>>>();
    sgemm_mma_kernel<64, WOFF_S2, WOFF_N2, 0><<<gL2, 512, SMEM>>>(b2, out, NN);
    agg_final_kernel<<<(NN * 16 + 255) / 256, 256>>>(out);
}

// round 14
// speedup vs baseline: 5.3328x; 1.0361x over previous
#include <cuda_runtime.h>
#include <cuda_bf16.h>
#include <cstdint>

static const int NN = 50000;
static const int NE = 600000;
static const int NRB = 3128;                 // ceil(50048/16) 16-row blocks
static const int NFRAG = NRB * 256;          // uint4 A-fragment groups per buffer

// ---------------- scratch ----------------
__device__ float g_h0[NN * 128];
__device__ float g_h1[NN * 128];
__device__ float g_y[NN * 128];
__device__ uint4 g_afh[NFRAG];               // A fragments hi
__device__ uint4 g_afl[NFRAG];               // A fragments lo
__device__ uint4 g_wfh[10240];               // B fragments hi (all 6 matrices)
__device__ uint4 g_wfl[10240];               // B fragments lo
__device__ float g_invdeg[NN];
__device__ int   g_count[NN];
__device__ int   g_offs[NN + 1];
__device__ int   g_cursor[NN];
__device__ int   g_srcs[NE];
__device__ int   g_is64;
__device__ int   g_bsum[128];
__device__ int   g_bbase[128];

// B-fragment offsets (uint4 units): per matrix N*16 uint4
static const int WF_S0 = 0;
static const int WF_N0 = 2048;
static const int WF_S1 = 4096;
static const int WF_N1 = 6144;
static const int WF_S2 = 8192;
static const int WF_N2 = 9216;

__device__ __forceinline__ float* sel_out(int SEL, float* ext) {
    if (SEL == 1) return g_h0;
    if (SEL == 2) return g_h1;
    return ext;
}
__device__ __forceinline__ int edge_at(const void* ei, int i) {
    if (g_is64) return (int)((const long long*)ei)[i];
    return ((const int*)ei)[i];
}
__device__ __forceinline__ void mma_bf16(float* c, const uint32_t* a, const uint32_t* b) {
    asm volatile(
        "mma.sync.aligned.m16n8k16.row.col.f32.bf16.bf16.f32 "
        "{%0,%1,%2,%3}, {%4,%5,%6,%7}, {%8,%9}, {%0,%1,%2,%3};"
        : "+f"(c[0]), "+f"(c[1]), "+f"(c[2]), "+f"(c[3])
        : "r"(a[0]), "r"(a[1]), "r"(a[2]), "r"(a[3]), "r"(b[0]), "r"(b[1]));
}
__device__ __forceinline__ void split_bf16(float v, __nv_bfloat16& h, __nv_bfloat16& l) {
    h = __float2bfloat16(v);
    l = __float2bfloat16(v - __bfloat162float(h));
}
__device__ __forceinline__ void pack2(float a, float b, uint32_t& hw, uint32_t& lw) {
    __nv_bfloat16 ha, la, hb, lb;
    split_bf16(a, ha, la);
    split_bf16(b, hb, lb);
    __nv_bfloat162 ph; ph.x = ha; ph.y = hb;
    __nv_bfloat162 pl; pl.x = la; pl.y = lb;
    hw = *(uint32_t*)&ph;
    lw = *(uint32_t*)&pl;
}

// ---------------- dtype probe ----------------
__global__ void init_flag_kernel() { g_is64 = 1; }
__global__ void detect_kernel(const void* ei) {
    int i = blockIdx.x * blockDim.x + threadIdx.x;
    int bad = 0;
    if (i < 2 * NE) {
        long long v = ((const long long*)ei)[i];
        bad = (v < 0 || v >= NN) ? 1 : 0;
    }
    if (__syncthreads_or(bad)) {
        if (threadIdx.x == 0) g_is64 = 0;
    }
}

// ---------------- weight conv: 6 matrices -> B-fragment layout (hi/lo) ----------------
// per matrix layout: idx = (n16*8 + ks)*32 + lane
// lane l: nE = n16*16 + (l>>2), nO = nE+8, k0 = ks*16 + (l&3)*2
// uint4 = { (nE,k0|k0+1), (nE,k0+8|k0+9), (nO,k0|k0+1), (nO,k0+8|k0+9) }
__global__ void conv_w_frag_kernel(const float* __restrict__ W0s, const float* __restrict__ W0n,
                                   const float* __restrict__ W1s, const float* __restrict__ W1n,
                                   const float* __restrict__ W2s, const float* __restrict__ W2n)
{
    int i = blockIdx.x * 256 + threadIdx.x;   // 0..10239
    if (i >= 10240) return;
    const float* src;
    int off, N;
    if      (i < 2048) { src = W0s; off = WF_S0; N = 128; }
    else if (i < 4096) { src = W0n; off = WF_N0; N = 128; }
    else if (i < 6144) { src = W1s; off = WF_S1; N = 128; }
    else if (i < 8192) { src = W1n; off = WF_N1; N = 128; }
    else if (i < 9216) { src = W2s; off = WF_S2; N = 64;  }
    else               { src = W2n; off = WF_N2; N = 64;  }
    int j = i - off;
    int lane = j & 31, ks = (j >> 5) & 7, n16 = j >> 8;
    int nE = n16 * 16 + (lane >> 2), nO = nE + 8;
    int k0 = ks * 16 + (lane & 3) * 2;
    uint4 h, l;
    pack2(src[(size_t)k0 * N + nE],       src[(size_t)(k0 + 1) * N + nE], h.x, l.x);
    pack2(src[(size_t)(k0 + 8) * N + nE], src[(size_t)(k0 + 9) * N + nE], h.y, l.y);
    pack2(src[(size_t)k0 * N + nO],       src[(size_t)(k0 + 1) * N + nO], h.z, l.z);
    pack2(src[(size_t)(k0 + 8) * N + nO], src[(size_t)(k0 + 9) * N + nO], h.w, l.w);
    g_wfh[i] = h;
    g_wfl[i] = l;
}

// ---------------- conv: f32 x [NN,128] -> A fragments (hi/lo) ----------------
__global__ void conv_x_frag_kernel(const float* __restrict__ x) {
    const float2* src = (const float2*)x;
    int i = blockIdx.x * 256 + threadIdx.x;
    int rb = i >> 8, ks = (i >> 5) & 7, lane = i & 31;
    int r0 = rb * 16 + (lane >> 2), r1 = r0 + 8;
    int cp0 = ks * 8 + (lane & 3), cp1 = cp0 + 4;
    const float2 z = make_float2(0.f, 0.f);
    float2 v00 = (r0 < NN) ? src[(size_t)r0 * 64 + cp0] : z;
    float2 v10 = (r1 < NN) ? src[(size_t)r1 * 64 + cp0] : z;
    float2 v01 = (r0 < NN) ? src[(size_t)r0 * 64 + cp1] : z;
    float2 v11 = (r1 < NN) ? src[(size_t)r1 * 64 + cp1] : z;
    uint4 h, l;
    pack2(v00.x, v00.y, h.x, l.x);
    pack2(v10.x, v10.y, h.y, l.y);
    pack2(v01.x, v01.y, h.z, l.z);
    pack2(v11.x, v11.y, h.w, l.w);
    g_afh[i] = h;
    g_afl[i] = l;
}

// ---------------- CSR build ----------------
__global__ void zero_count_kernel() {
    int i = blockIdx.x * blockDim.x + threadIdx.x;
    if (i < NN) g_count[i] = 0;
}
__global__ void hist_kernel(const void* ei) {
    int i = blockIdx.x * blockDim.x + threadIdx.x;
    if (i < NE) {
        int d = edge_at(ei, NE + i);
        d = min(max(d, 0), NN - 1);
        atomicAdd(&g_count[d], 1);
    }
}

static const int SCAN_SEG = 512;
static const int SCAN_THR = 256;
static const int SCAN_NB  = (NN + SCAN_SEG - 1) / SCAN_SEG;  // 98

__global__ void scan1_kernel() {
    __shared__ int red[SCAN_THR];
    int b = blockIdx.x, t = threadIdx.x;
    int i0 = b * SCAN_SEG + 2 * t, i1 = i0 + 1;
    int s = 0;
    if (i0 < NN) s += g_count[i0];
    if (i1 < NN) s += g_count[i1];
    red[t] = s;
    __syncthreads();
    for (int d = SCAN_THR / 2; d > 0; d >>= 1) {
        if (t < d) red[t] += red[t + d];
        __syncthreads();
    }
    if (t == 0) g_bsum[b] = red[0];
}
__global__ void scan2_kernel() {
    __shared__ int sh[128];
    int t = threadIdx.x;
    sh[t] = (t < SCAN_NB) ? g_bsum[t] : 0;
    __syncthreads();
    for (int d = 1; d < 128; d <<= 1) {
        int v = sh[t];
        int u = (t >= d) ? sh[t - d] : 0;
        __syncthreads();
        sh[t] = v + u;
        __syncthreads();
    }
    if (t < SCAN_NB) g_bbase[t] = sh[t] - g_bsum[t];
    if (t == 127) g_offs[NN] = sh[127];
}
__global__ void scan3_kernel() {
    __shared__ int sh[SCAN_THR];
    int b = blockIdx.x, t = threadIdx.x;
    int i0 = b * SCAN_SEG + 2 * t, i1 = i0 + 1;
    int c0 = (i0 < NN) ? g_count[i0] : 0;
    int c1 = (i1 < NN) ? g_count[i1] : 0;
    int s = c0 + c1;
    sh[t] = s;
    __syncthreads();
    for (int d = 1; d < SCAN_THR; d <<= 1) {
        int v = sh[t];
        int u = (t >= d) ? sh[t - d] : 0;
        __syncthreads();
        sh[t] = v + u;
        __syncthreads();
    }
    int tb = g_bbase[b] + sh[t] - s;
    if (i0 < NN) { g_offs[i0] = tb;      g_cursor[i0] = tb;      g_invdeg[i0] = 1.0f / fmaxf((float)c0, 1.0f); }
    if (i1 < NN) { g_offs[i1] = tb + c0; g_cursor[i1] = tb + c0; g_invdeg[i1] = 1.0f / fmaxf((float)c1, 1.0f); }
}
__global__ void fill_kernel(const void* ei) {
    int i = blockIdx.x * blockDim.x + threadIdx.x;
    if (i < NE) {
        int s = edge_at(ei, i);
        int d = edge_at(ei, NE + i);
        s = min(max(s, 0), NN - 1);
        d = min(max(d, 0), NN - 1);
        int p = atomicAdd(&g_cursor[d], 1);
        g_srcs[p] = s;
    }
}

// ---------------- smem-free dual-output HMMA GEMM ----------------
// grid (391, 2): y=0 -> C_self (+bias), y=1 -> g_y. CTA covers 128 rows x NOUT cols.
// A + B operands both streamed as pre-built global fragments. No smem, no syncthreads.
template <int NOUT, int LOFF_S, int LOFF_N, int CSEL_S>
__global__ __launch_bounds__(512, 2) void sgemm_mma_kernel(
    const float* __restrict__ bias, float* __restrict__ Cext, int M)
{
    const int NT = NOUT / 32;            // n-tiles per warp: 4 (NOUT=128) or 2 (NOUT=64)
    int half = blockIdx.y;
    const uint4* wfh = g_wfh + (half ? LOFF_N : LOFF_S);
    const uint4* wfl = g_wfl + (half ? LOFF_N : LOFF_S);
    float* C = half ? g_y : sel_out(CSEL_S, Cext);
    const float* bb = half ? nullptr : bias;

    int tid = threadIdx.x, wid = tid >> 5, lane = tid & 31;
    int row0 = blockIdx.x * 128;
    int wm = wid & 3, wn = wid >> 2;
    int mrow = wm * 32;
    int ncol = wn * (NT * 8);
    int rbB = blockIdx.x * 8 + wm * 2;
    int n16_0 = ncol >> 4;               // first 16-col fragment block for this warp

    float acc[2][NT][4];
#pragma unroll
    for (int mt = 0; mt < 2; mt++)
#pragma unroll
        for (int nt = 0; nt < NT; nt++)
#pragma unroll
            for (int q = 0; q < 4; q++) acc[mt][nt][q] = 0.f;

#pragma unroll
    for (int ks = 0; ks < 8; ks++) {
        uint4 ah0 = g_afh[(size_t)((rbB + 0) * 8 + ks) * 32 + lane];
        uint4 ah1 = g_afh[(size_t)((rbB + 1) * 8 + ks) * 32 + lane];
        uint4 al0 = g_afl[(size_t)((rbB + 0) * 8 + ks) * 32 + lane];
        uint4 al1 = g_afl[(size_t)((rbB + 1) * 8 + ks) * 32 + lane];
        const uint32_t* ah[2] = { (const uint32_t*)&ah0, (const uint32_t*)&ah1 };
        const uint32_t* al[2] = { (const uint32_t*)&al0, (const uint32_t*)&al1 };
#pragma unroll
        for (int p = 0; p < NT / 2; p++) {
            uint4 BH = wfh[(size_t)((n16_0 + p) * 8 + ks) * 32 + lane];
            uint4 BL = wfl[(size_t)((n16_0 + p) * 8 + ks) * 32 + lane];
            const uint32_t* bh = (const uint32_t*)&BH;
            const uint32_t* bl = (const uint32_t*)&BL;
#pragma unroll
            for (int mt = 0; mt < 2; mt++)
#pragma unroll
                for (int h = 0; h < 2; h++) {
                    float* a = acc[mt][2 * p + h];
                    mma_bf16(a, ah[mt], &bh[h * 2]);
                    mma_bf16(a, ah[mt], &bl[h * 2]);
                    mma_bf16(a, al[mt], &bh[h * 2]);
                }
        }
    }

    // ---- epilogue ----
#pragma unroll
    for (int mt = 0; mt < 2; mt++) {
        int r0g = row0 + mrow + mt * 16 + (lane >> 2);
        int r1g = r0g + 8;
#pragma unroll
        for (int nt = 0; nt < NT; nt++) {
            int cc = ncol + nt * 8 + (lane & 3) * 2;
            float bx = bb ? bb[cc] : 0.f;
            float by = bb ? bb[cc + 1] : 0.f;
            if (r0g < M) {
                float2 v; v.x = acc[mt][nt][0] + bx; v.y = acc[mt][nt][1] + by;
                *(float2*)(C + (size_t)r0g * NOUT + cc) = v;
            }
            if (r1g < M) {
                float2 v; v.x = acc[mt][nt][2] + bx; v.y = acc[mt][nt][3] + by;
                *(float2*)(C + (size_t)r1g * NOUT + cc) = v;
            }
        }
    }
}

// ---------------- fused aggregate + relu + A-fragment emission (layers 0/1) ----------------
template <int OSEL>
__global__ __launch_bounds__(512) void agg_frag_kernel()
{
    __shared__ float sh[16][132];
    const float4* yv = (const float4*)g_y;
    const float* self = (OSEL == 1) ? g_h0 : g_h1;

    int rb = blockIdx.x;
    int tid = threadIdx.x, w = tid >> 5, lane = tid & 31;
    int node = rb * 16 + w;

    float4 o = make_float4(0.f, 0.f, 0.f, 0.f);
    if (node < NN) {
        int s = g_offs[node], e = g_offs[node + 1];
        float4 acc = make_float4(0.f, 0.f, 0.f, 0.f);
        int i = s;
        for (; i + 1 < e; i += 2) {
            int s0 = g_srcs[i], s1 = g_srcs[i + 1];
            float4 v0 = yv[(size_t)s0 * 32 + lane];
            float4 v1 = yv[(size_t)s1 * 32 + lane];
            acc.x += v0.x + v1.x; acc.y += v0.y + v1.y;
            acc.z += v0.z + v1.z; acc.w += v0.w + v1.w;
        }
        if (i < e) {
            int s0 = g_srcs[i];
            float4 v0 = yv[(size_t)s0 * 32 + lane];
            acc.x += v0.x; acc.y += v0.y; acc.z += v0.z; acc.w += v0.w;
        }
        float wg = g_invdeg[node];
        float4 sf = ((const float4*)self)[(size_t)node * 32 + lane];
        o.x = fmaxf(sf.x + wg * acc.x, 0.f);
        o.y = fmaxf(sf.y + wg * acc.y, 0.f);
        o.z = fmaxf(sf.z + wg * acc.z, 0.f);
        o.w = fmaxf(sf.w + wg * acc.w, 0.f);
    }
    *(float4*)&sh[w][lane * 4] = o;
    __syncthreads();

    if (tid < 256) {
        int ks = tid >> 5, lf = tid & 31;
        int r0 = lf >> 2, r1 = r0 + 8;
        int cp0 = ks * 8 + (lf & 3), cp1 = cp0 + 4;
        uint4 h, l;
        pack2(sh[r0][cp0 * 2], sh[r0][cp0 * 2 + 1], h.x, l.x);
        pack2(sh[r1][cp0 * 2], sh[r1][cp0 * 2 + 1], h.y, l.y);
        pack2(sh[r0][cp1 * 2], sh[r0][cp1 * 2 + 1], h.z, l.z);
        pack2(sh[r1][cp1 * 2], sh[r1][cp1 * 2 + 1], h.w, l.w);
        size_t idx = (size_t)(rb * 8 + ks) * 32 + lf;
        g_afh[idx] = h;
        g_afl[idx] = l;
    }
}

// ---------------- final aggregate (D=64, writes d_out, no relu) ----------------
__global__ void agg_final_kernel(float* __restrict__ out)
{
    const float4* yv = (const float4*)g_y;
    const int CH = 16;
    int gt   = blockIdx.x * blockDim.x + threadIdx.x;
    int warp = gt >> 5;
    int lane = gt & 31;
    int node = warp * 2 + lane / CH;
    int c    = lane % CH;
    if (node >= NN) return;

    int s = g_offs[node], e = g_offs[node + 1];
    float4 acc = make_float4(0.f, 0.f, 0.f, 0.f);
    int i = s;
    for (; i + 1 < e; i += 2) {
        int s0 = g_srcs[i], s1 = g_srcs[i + 1];
        float4 v0 = yv[(size_t)s0 * CH + c];
        float4 v1 = yv[(size_t)s1 * CH + c];
        acc.x += v0.x + v1.x; acc.y += v0.y + v1.y;
        acc.z += v0.z + v1.z; acc.w += v0.w + v1.w;
    }
    if (i < e) {
        int s0 = g_srcs[i];
        float4 v0 = yv[(size_t)s0 * CH + c];
        acc.x += v0.x; acc.y += v0.y; acc.z += v0.z; acc.w += v0.w;
    }
    float w = g_invdeg[node];
    float4* op = (float4*)out + (size_t)node * CH + c;
    float4 o = *op;
    o.x += w * acc.x; o.y += w * acc.y; o.z += w * acc.z; o.w += w * acc.w;
    *op = o;
}

// ---------------- launch ----------------
extern "C" void kernel_launch(void* const* d_in, const int* in_sizes, int n_in,
                              void* d_out, int out_size)
{
    const float* x   = (const float*)d_in[0];
    const void*  ei  = d_in[1];
    const float* Ws0 = (const float*)d_in[2];
    const float* Wn0 = (const float*)d_in[3];
    const float* b0  = (const float*)d_in[4];
    const float* Ws1 = (const float*)d_in[5];
    const float* Wn1 = (const float*)d_in[6];
    const float* b1  = (const float*)d_in[7];
    const float* Ws2 = (const float*)d_in[8];
    const float* Wn2 = (const float*)d_in[9];
    const float* b2  = (const float*)d_in[10];
    float* out = (float*)d_out;

    const int tb = 256;
    const dim3 g2(391, 2);

    // fork-join: CSR build overlaps conv+GEMM0 on a side stream
    cudaStream_t s2;
    cudaStreamCreateWithFlags(&s2, cudaStreamNonBlocking);
    cudaEvent_t evF, evJ;
    cudaEventCreateWithFlags(&evF, cudaEventDisableTiming);
    cudaEventCreateWithFlags(&evJ, cudaEventDisableTiming);

    init_flag_kernel<<<1, 1>>>();
    detect_kernel<<<(2 * NE + tb - 1) / tb, tb>>>(ei);
    cudaEventRecord(evF, 0);
    cudaStreamWaitEvent(s2, evF, 0);

    // side stream: CSR build
    zero_count_kernel<<<(NN + tb - 1) / tb, tb, 0, s2>>>();
    hist_kernel<<<(NE + tb - 1) / tb, tb, 0, s2>>>(ei);
    scan1_kernel<<<SCAN_NB, SCAN_THR, 0, s2>>>();
    scan2_kernel<<<1, 128, 0, s2>>>();
    scan3_kernel<<<SCAN_NB, SCAN_THR, 0, s2>>>();
    fill_kernel<<<(NE + tb - 1) / tb, tb, 0, s2>>>(ei);
    cudaEventRecord(evJ, s2);

    // main stream: conversions + layer-0 GEMM (overlapped with CSR)
    conv_x_frag_kernel<<<NRB, 256>>>(x);
    conv_w_frag_kernel<<<40, 256>>>(Ws0, Wn0, Ws1, Wn1, Ws2, Wn2);
    sgemm_mma_kernel<128, WF_S0, WF_N0, 1><<<g2, 512>>>(b0, nullptr, NN);
    cudaStreamWaitEvent(0, evJ, 0);

    agg_frag_kernel<1><<<NRB, 512>>>();
    sgemm_mma_kernel<128, WF_S1, WF_N1, 2><<<g2, 512>>>(b1, nullptr, NN);
    agg_frag_kernel<2><<<NRB, 512>>>();
    sgemm_mma_kernel<64, WF_S2, WF_N2, 0><<<g2, 512>>>(b2, out, NN);
    agg_final_kernel<<<(NN * 16 + 255) / 256, 256>>>(out);
}

// round 15
// speedup vs baseline: 5.6362x; 1.0569x over previous
#include <cuda_runtime.h>
#include <cuda_bf16.h>
#include <cstdint>

static const int NN = 50000;
static const int NE = 600000;
static const int NRB = 3128;                 // ceil(50048/16) 16-row blocks
static const int NFRAG = NRB * 256;          // uint4 A-fragment groups per buffer

// ---------------- scratch ----------------
__device__ float g_h0[NN * 128];
__device__ float g_h1[NN * 128];
__device__ float g_y[NN * 128];
__device__ uint4 g_afh[NFRAG];               // A fragments hi
__device__ uint4 g_afl[NFRAG];               // A fragments lo
__device__ uint4 g_wfh[10240];               // B fragments hi (all 6 matrices)
__device__ uint4 g_wfl[10240];               // B fragments lo
__device__ float g_invdeg[NN];
__device__ int   g_count[NN];
__device__ int   g_offs[NN + 1];
__device__ int   g_cursor[NN];
__device__ int   g_srcs[NE];
__device__ int   g_is64;
__device__ int   g_bsum[128];
__device__ int   g_bbase[128];

// B-fragment offsets (uint4 units)
static const int WF_S0 = 0;
static const int WF_N0 = 2048;
static const int WF_S1 = 4096;
static const int WF_N1 = 6144;
static const int WF_S2 = 8192;
static const int WF_N2 = 9216;

__device__ __forceinline__ float* sel_out(int SEL, float* ext) {
    if (SEL == 1) return g_h0;
    if (SEL == 2) return g_h1;
    return ext;
}
__device__ __forceinline__ int edge_at(const void* ei, int i) {
    if (g_is64) return (int)((const long long*)ei)[i];
    return ((const int*)ei)[i];
}
__device__ __forceinline__ void mma_bf16(float* c, const uint32_t* a, const uint32_t* b) {
    asm volatile(
        "mma.sync.aligned.m16n8k16.row.col.f32.bf16.bf16.f32 "
        "{%0,%1,%2,%3}, {%4,%5,%6,%7}, {%8,%9}, {%0,%1,%2,%3};"
        : "+f"(c[0]), "+f"(c[1]), "+f"(c[2]), "+f"(c[3])
        : "r"(a[0]), "r"(a[1]), "r"(a[2]), "r"(a[3]), "r"(b[0]), "r"(b[1]));
}
__device__ __forceinline__ void split_bf16(float v, __nv_bfloat16& h, __nv_bfloat16& l) {
    h = __float2bfloat16(v);
    l = __float2bfloat16(v - __bfloat162float(h));
}
__device__ __forceinline__ void pack2(float a, float b, uint32_t& hw, uint32_t& lw) {
    __nv_bfloat16 ha, la, hb, lb;
    split_bf16(a, ha, la);
    split_bf16(b, hb, lb);
    __nv_bfloat162 ph; ph.x = ha; ph.y = hb;
    __nv_bfloat162 pl; pl.x = la; pl.y = lb;
    hw = *(uint32_t*)&ph;
    lw = *(uint32_t*)&pl;
}

// ---------------- dtype probe ----------------
__global__ void init_flag_kernel() { g_is64 = 1; }
__global__ void detect_kernel(const void* ei) {
    int i = blockIdx.x * blockDim.x + threadIdx.x;
    int bad = 0;
    if (i < 2 * NE) {
        long long v = ((const long long*)ei)[i];
        bad = (v < 0 || v >= NN) ? 1 : 0;
    }
    if (__syncthreads_or(bad)) {
        if (threadIdx.x == 0) g_is64 = 0;
    }
}

// ---------------- weight conv -> B-fragment layout (hi/lo) ----------------
__global__ void conv_w_frag_kernel(const float* __restrict__ W0s, const float* __restrict__ W0n,
                                   const float* __restrict__ W1s, const float* __restrict__ W1n,
                                   const float* __restrict__ W2s, const float* __restrict__ W2n)
{
    int i = blockIdx.x * 256 + threadIdx.x;   // 0..10239
    if (i >= 10240) return;
    const float* src;
    int off, N;
    if      (i < 2048) { src = W0s; off = WF_S0; N = 128; }
    else if (i < 4096) { src = W0n; off = WF_N0; N = 128; }
    else if (i < 6144) { src = W1s; off = WF_S1; N = 128; }
    else if (i < 8192) { src = W1n; off = WF_N1; N = 128; }
    else if (i < 9216) { src = W2s; off = WF_S2; N = 64;  }
    else               { src = W2n; off = WF_N2; N = 64;  }
    int j = i - off;
    int lane = j & 31, ks = (j >> 5) & 7, n16 = j >> 8;
    int nE = n16 * 16 + (lane >> 2), nO = nE + 8;
    int k0 = ks * 16 + (lane & 3) * 2;
    uint4 h, l;
    pack2(src[(size_t)k0 * N + nE],       src[(size_t)(k0 + 1) * N + nE], h.x, l.x);
    pack2(src[(size_t)(k0 + 8) * N + nE], src[(size_t)(k0 + 9) * N + nE], h.y, l.y);
    pack2(src[(size_t)k0 * N + nO],       src[(size_t)(k0 + 1) * N + nO], h.z, l.z);
    pack2(src[(size_t)(k0 + 8) * N + nO], src[(size_t)(k0 + 9) * N + nO], h.w, l.w);
    g_wfh[i] = h;
    g_wfl[i] = l;
}

// ---------------- conv: f32 x [NN,128] -> A fragments (hi/lo) ----------------
__global__ void conv_x_frag_kernel(const float* __restrict__ x) {
    const float2* src = (const float2*)x;
    int i = blockIdx.x * 256 + threadIdx.x;
    int rb = i >> 8, ks = (i >> 5) & 7, lane = i & 31;
    int r0 = rb * 16 + (lane >> 2), r1 = r0 + 8;
    int cp0 = ks * 8 + (lane & 3), cp1 = cp0 + 4;
    const float2 z = make_float2(0.f, 0.f);
    float2 v00 = (r0 < NN) ? src[(size_t)r0 * 64 + cp0] : z;
    float2 v10 = (r1 < NN) ? src[(size_t)r1 * 64 + cp0] : z;
    float2 v01 = (r0 < NN) ? src[(size_t)r0 * 64 + cp1] : z;
    float2 v11 = (r1 < NN) ? src[(size_t)r1 * 64 + cp1] : z;
    uint4 h, l;
    pack2(v00.x, v00.y, h.x, l.x);
    pack2(v10.x, v10.y, h.y, l.y);
    pack2(v01.x, v01.y, h.z, l.z);
    pack2(v11.x, v11.y, h.w, l.w);
    g_afh[i] = h;
    g_afl[i] = l;
}

// ---------------- CSR build ----------------
__global__ void zero_count_kernel() {
    int i = blockIdx.x * blockDim.x + threadIdx.x;
    if (i < NN) g_count[i] = 0;
}
__global__ void hist_kernel(const void* ei) {
    int i = blockIdx.x * blockDim.x + threadIdx.x;
    if (i < NE) {
        int d = edge_at(ei, NE + i);
        d = min(max(d, 0), NN - 1);
        atomicAdd(&g_count[d], 1);
    }
}

static const int SCAN_SEG = 512;
static const int SCAN_THR = 256;
static const int SCAN_NB  = (NN + SCAN_SEG - 1) / SCAN_SEG;  // 98

__global__ void scan1_kernel() {
    __shared__ int red[SCAN_THR];
    int b = blockIdx.x, t = threadIdx.x;
    int i0 = b * SCAN_SEG + 2 * t, i1 = i0 + 1;
    int s = 0;
    if (i0 < NN) s += g_count[i0];
    if (i1 < NN) s += g_count[i1];
    red[t] = s;
    __syncthreads();
    for (int d = SCAN_THR / 2; d > 0; d >>= 1) {
        if (t < d) red[t] += red[t + d];
        __syncthreads();
    }
    if (t == 0) g_bsum[b] = red[0];
}
__global__ void scan2_kernel() {
    __shared__ int sh[128];
    int t = threadIdx.x;
    sh[t] = (t < SCAN_NB) ? g_bsum[t] : 0;
    __syncthreads();
    for (int d = 1; d < 128; d <<= 1) {
        int v = sh[t];
        int u = (t >= d) ? sh[t - d] : 0;
        __syncthreads();
        sh[t] = v + u;
        __syncthreads();
    }
    if (t < SCAN_NB) g_bbase[t] = sh[t] - g_bsum[t];
    if (t == 127) g_offs[NN] = sh[127];
}
__global__ void scan3_kernel() {
    __shared__ int sh[SCAN_THR];
    int b = blockIdx.x, t = threadIdx.x;
    int i0 = b * SCAN_SEG + 2 * t, i1 = i0 + 1;
    int c0 = (i0 < NN) ? g_count[i0] : 0;
    int c1 = (i1 < NN) ? g_count[i1] : 0;
    int s = c0 + c1;
    sh[t] = s;
    __syncthreads();
    for (int d = 1; d < SCAN_THR; d <<= 1) {
        int v = sh[t];
        int u = (t >= d) ? sh[t - d] : 0;
        __syncthreads();
        sh[t] = v + u;
        __syncthreads();
    }
    int tb = g_bbase[b] + sh[t] - s;
    if (i0 < NN) { g_offs[i0] = tb;      g_cursor[i0] = tb;      g_invdeg[i0] = 1.0f / fmaxf((float)c0, 1.0f); }
    if (i1 < NN) { g_offs[i1] = tb + c0; g_cursor[i1] = tb + c0; g_invdeg[i1] = 1.0f / fmaxf((float)c1, 1.0f); }
}
__global__ void fill_kernel(const void* ei) {
    int i = blockIdx.x * blockDim.x + threadIdx.x;
    if (i < NE) {
        int s = edge_at(ei, i);
        int d = edge_at(ei, NE + i);
        s = min(max(s, 0), NN - 1);
        d = min(max(d, 0), NN - 1);
        int p = atomicAdd(&g_cursor[d], 1);
        g_srcs[p] = s;
    }
}

// ---------------- dual-accumulator HMMA GEMM: one CTA -> BOTH outputs ----------------
// grid (391, 1). CTA covers 128 rows x NOUT cols for self AND neighbor matrices.
// A fragments loaded ONCE per ks, feed both accumulator sets (A L2 traffic halved).
template <int NOUT, int LOFF_S, int LOFF_N, int CSEL_S>
__global__ __launch_bounds__(512, 1) void sgemm_mma_kernel(
    const float* __restrict__ bias, float* __restrict__ Cext, int M)
{
    const int NT = NOUT / 32;            // n-tiles per warp per matrix: 4 or 2
    float* CS = sel_out(CSEL_S, Cext);

    int tid = threadIdx.x, wid = tid >> 5, lane = tid & 31;
    int row0 = blockIdx.x * 128;
    int wm = wid & 3, wn = wid >> 2;
    int mrow = wm * 32;
    int ncol = wn * (NT * 8);
    int rbB = blockIdx.x * 8 + wm * 2;
    int n16_0 = ncol >> 4;

    float acc[2][2][NT][4];              // [matrix][mt][nt][q]
#pragma unroll
    for (int mx = 0; mx < 2; mx++)
#pragma unroll
        for (int mt = 0; mt < 2; mt++)
#pragma unroll
            for (int nt = 0; nt < NT; nt++)
#pragma unroll
                for (int q = 0; q < 4; q++) acc[mx][mt][nt][q] = 0.f;

#pragma unroll
    for (int ks = 0; ks < 8; ks++) {
        uint4 ah0 = g_afh[(size_t)((rbB + 0) * 8 + ks) * 32 + lane];
        uint4 ah1 = g_afh[(size_t)((rbB + 1) * 8 + ks) * 32 + lane];
        uint4 al0 = g_afl[(size_t)((rbB + 0) * 8 + ks) * 32 + lane];
        uint4 al1 = g_afl[(size_t)((rbB + 1) * 8 + ks) * 32 + lane];
        const uint32_t* ah[2] = { (const uint32_t*)&ah0, (const uint32_t*)&ah1 };
        const uint32_t* al[2] = { (const uint32_t*)&al0, (const uint32_t*)&al1 };
#pragma unroll
        for (int p = 0; p < NT / 2; p++) {
            size_t bidx = (size_t)((n16_0 + p) * 8 + ks) * 32 + lane;
#pragma unroll
            for (int mx = 0; mx < 2; mx++) {
                int loff = mx ? LOFF_N : LOFF_S;
                uint4 BH = g_wfh[loff + bidx];
                uint4 BL = g_wfl[loff + bidx];
                const uint32_t* bh = (const uint32_t*)&BH;
                const uint32_t* bl = (const uint32_t*)&BL;
#pragma unroll
                for (int mt = 0; mt < 2; mt++)
#pragma unroll
                    for (int h = 0; h < 2; h++) {
                        float* a = acc[mx][mt][2 * p + h];
                        mma_bf16(a, ah[mt], &bh[h * 2]);
                        mma_bf16(a, ah[mt], &bl[h * 2]);
                        mma_bf16(a, al[mt], &bh[h * 2]);
                    }
            }
        }
    }

    // ---- epilogue: both outputs ----
#pragma unroll
    for (int mt = 0; mt < 2; mt++) {
        int r0g = row0 + mrow + mt * 16 + (lane >> 2);
        int r1g = r0g + 8;
#pragma unroll
        for (int nt = 0; nt < NT; nt++) {
            int cc = ncol + nt * 8 + (lane & 3) * 2;
            float bx = bias ? bias[cc] : 0.f;
            float by = bias ? bias[cc + 1] : 0.f;
            if (r0g < M) {
                float2 v;
                v.x = acc[0][mt][nt][0] + bx; v.y = acc[0][mt][nt][1] + by;
                *(float2*)(CS + (size_t)r0g * NOUT + cc) = v;
                v.x = acc[1][mt][nt][0]; v.y = acc[1][mt][nt][1];
                *(float2*)(g_y + (size_t)r0g * NOUT + cc) = v;
            }
            if (r1g < M) {
                float2 v;
                v.x = acc[0][mt][nt][2] + bx; v.y = acc[0][mt][nt][3] + by;
                *(float2*)(CS + (size_t)r1g * NOUT + cc) = v;
                v.x = acc[1][mt][nt][2]; v.y = acc[1][mt][nt][3];
                *(float2*)(g_y + (size_t)r1g * NOUT + cc) = v;
            }
        }
    }
}

// ---------------- fused aggregate + relu + A-fragment emission (layers 0/1) ----------------
template <int OSEL>
__global__ __launch_bounds__(512) void agg_frag_kernel()
{
    __shared__ float sh[16][132];
    const float4* yv = (const float4*)g_y;
    const float* self = (OSEL == 1) ? g_h0 : g_h1;

    int rb = blockIdx.x;
    int tid = threadIdx.x, w = tid >> 5, lane = tid & 31;
    int node = rb * 16 + w;

    float4 o = make_float4(0.f, 0.f, 0.f, 0.f);
    if (node < NN) {
        int s = g_offs[node], e = g_offs[node + 1];
        float4 acc = make_float4(0.f, 0.f, 0.f, 0.f);
        int i = s;
        for (; i + 3 < e; i += 4) {          // 4-edge unroll for MLP
            int s0 = g_srcs[i], s1 = g_srcs[i + 1], s2 = g_srcs[i + 2], s3 = g_srcs[i + 3];
            float4 v0 = yv[(size_t)s0 * 32 + lane];
            float4 v1 = yv[(size_t)s1 * 32 + lane];
            float4 v2 = yv[(size_t)s2 * 32 + lane];
            float4 v3 = yv[(size_t)s3 * 32 + lane];
            acc.x += (v0.x + v1.x) + (v2.x + v3.x);
            acc.y += (v0.y + v1.y) + (v2.y + v3.y);
            acc.z += (v0.z + v1.z) + (v2.z + v3.z);
            acc.w += (v0.w + v1.w) + (v2.w + v3.w);
        }
        for (; i < e; i++) {
            int s0 = g_srcs[i];
            float4 v0 = yv[(size_t)s0 * 32 + lane];
            acc.x += v0.x; acc.y += v0.y; acc.z += v0.z; acc.w += v0.w;
        }
        float wg = g_invdeg[node];
        float4 sf = ((const float4*)self)[(size_t)node * 32 + lane];
        o.x = fmaxf(sf.x + wg * acc.x, 0.f);
        o.y = fmaxf(sf.y + wg * acc.y, 0.f);
        o.z = fmaxf(sf.z + wg * acc.z, 0.f);
        o.w = fmaxf(sf.w + wg * acc.w, 0.f);
    }
    *(float4*)&sh[w][lane * 4] = o;
    __syncthreads();

    if (tid < 256) {
        int ks = tid >> 5, lf = tid & 31;
        int r0 = lf >> 2, r1 = r0 + 8;
        int cp0 = ks * 8 + (lf & 3), cp1 = cp0 + 4;
        uint4 h, l;
        pack2(sh[r0][cp0 * 2], sh[r0][cp0 * 2 + 1], h.x, l.x);
        pack2(sh[r1][cp0 * 2], sh[r1][cp0 * 2 + 1], h.y, l.y);
        pack2(sh[r0][cp1 * 2], sh[r0][cp1 * 2 + 1], h.z, l.z);
        pack2(sh[r1][cp1 * 2], sh[r1][cp1 * 2 + 1], h.w, l.w);
        size_t idx = (size_t)(rb * 8 + ks) * 32 + lf;
        g_afh[idx] = h;
        g_afl[idx] = l;
    }
}

// ---------------- final aggregate (D=64, writes d_out, no relu) ----------------
__global__ void agg_final_kernel(float* __restrict__ out)
{
    const float4* yv = (const float4*)g_y;
    const int CH = 16;
    int gt   = blockIdx.x * blockDim.x + threadIdx.x;
    int warp = gt >> 5;
    int lane = gt & 31;
    int node = warp * 2 + lane / CH;
    int c    = lane % CH;
    if (node >= NN) return;

    int s = g_offs[node], e = g_offs[node + 1];
    float4 acc = make_float4(0.f, 0.f, 0.f, 0.f);
    int i = s;
    for (; i + 3 < e; i += 4) {
        int s0 = g_srcs[i], s1 = g_srcs[i + 1], s2 = g_srcs[i + 2], s3 = g_srcs[i + 3];
        float4 v0 = yv[(size_t)s0 * CH + c];
        float4 v1 = yv[(size_t)s1 * CH + c];
        float4 v2 = yv[(size_t)s2 * CH + c];
        float4 v3 = yv[(size_t)s3 * CH + c];
        acc.x += (v0.x + v1.x) + (v2.x + v3.x);
        acc.y += (v0.y + v1.y) + (v2.y + v3.y);
        acc.z += (v0.z + v1.z) + (v2.z + v3.z);
        acc.w += (v0.w + v1.w) + (v2.w + v3.w);
    }
    for (; i < e; i++) {
        int s0 = g_srcs[i];
        float4 v0 = yv[(size_t)s0 * CH + c];
        acc.x += v0.x; acc.y += v0.y; acc.z += v0.z; acc.w += v0.w;
    }
    float w = g_invdeg[node];
    float4* op = (float4*)out + (size_t)node * CH + c;
    float4 o = *op;
    o.x += w * acc.x; o.y += w * acc.y; o.z += w * acc.z; o.w += w * acc.w;
    *op = o;
}

// ---------------- launch ----------------
extern "C" void kernel_launch(void* const* d_in, const int* in_sizes, int n_in,
                              void* d_out, int out_size)
{
    const float* x   = (const float*)d_in[0];
    const void*  ei  = d_in[1];
    const float* Ws0 = (const float*)d_in[2];
    const float* Wn0 = (const float*)d_in[3];
    const float* b0  = (const float*)d_in[4];
    const float* Ws1 = (const float*)d_in[5];
    const float* Wn1 = (const float*)d_in[6];
    const float* b1  = (const float*)d_in[7];
    const float* Ws2 = (const float*)d_in[8];
    const float* Wn2 = (const float*)d_in[9];
    const float* b2  = (const float*)d_in[10];
    float* out = (float*)d_out;

    const int tb = 256;

    // fork-join: CSR build overlaps conv+GEMM0 on a side stream
    cudaStream_t s2;
    cudaStreamCreateWithFlags(&s2, cudaStreamNonBlocking);
    cudaEvent_t evF, evJ;
    cudaEventCreateWithFlags(&evF, cudaEventDisableTiming);
    cudaEventCreateWithFlags(&evJ, cudaEventDisableTiming);

    init_flag_kernel<<<1, 1>>>();
    detect_kernel<<<(2 * NE + tb - 1) / tb, tb>>>(ei);
    cudaEventRecord(evF, 0);
    cudaStreamWaitEvent(s2, evF, 0);

    // side stream: CSR build
    zero_count_kernel<<<(NN + tb - 1) / tb, tb, 0, s2>>>();
    hist_kernel<<<(NE + tb - 1) / tb, tb, 0, s2>>>(ei);
    scan1_kernel<<<SCAN_NB, SCAN_THR, 0, s2>>>();
    scan2_kernel<<<1, 128, 0, s2>>>();
    scan3_kernel<<<SCAN_NB, SCAN_THR, 0, s2>>>();
    fill_kernel<<<(NE + tb - 1) / tb, tb, 0, s2>>>(ei);
    cudaEventRecord(evJ, s2);

    // main stream: conversions + layer-0 GEMM (overlapped with CSR)
    conv_x_frag_kernel<<<NRB, 256>>>(x);
    conv_w_frag_kernel<<<40, 256>>>(Ws0, Wn0, Ws1, Wn1, Ws2, Wn2);
    sgemm_mma_kernel<128, WF_S0, WF_N0, 1><<<391, 512>>>(b0, nullptr, NN);
    cudaStreamWaitEvent(0, evJ, 0);

    agg_frag_kernel<1><<<NRB, 512>>>();
    sgemm_mma_kernel<128, WF_S1, WF_N1, 2><<<391, 512>>>(b1, nullptr, NN);
    agg_frag_kernel<2><<<NRB, 512>>>();
    sgemm_mma_kernel<64, WF_S2, WF_N2, 0><<<391, 512>>>(b2, out, NN);
    agg_final_kernel<<<(NN * 16 + 255) / 256, 256>>>(out);
}

// round 16
// speedup vs baseline: 5.6827x; 1.0082x over previous
#include <cuda_runtime.h>
#include <cuda_bf16.h>
#include <cstdint>

static const int NN = 50000;
static const int NE = 600000;
static const int NRB = 3128;                 // ceil(50048/16) 16-row blocks
static const int NFRAG = NRB * 256;          // uint4 A-fragment groups per buffer

// ---------------- scratch ----------------
__device__ float g_h0[NN * 128];
__device__ float g_h1[NN * 128];
__device__ float g_y[NN * 128];
__device__ uint4 g_afh[NFRAG];               // A fragments hi
__device__ uint4 g_afl[NFRAG];               // A fragments lo
__device__ uint4 g_wfh[10240];               // B fragments hi (all 6 matrices)
__device__ uint4 g_wfl[10240];               // B fragments lo
__device__ float g_invdeg[NN];
__device__ int   g_count[NN];
__device__ int   g_offs[NN + 1];
__device__ int   g_cursor[NN];
__device__ int   g_srcs[NE];
__device__ int   g_is64;
__device__ int   g_bsum[128];
__device__ int   g_bbase[128];

// B-fragment offsets (uint4 units)
static const int WF_S0 = 0;
static const int WF_N0 = 2048;
static const int WF_S1 = 4096;
static const int WF_N1 = 6144;
static const int WF_S2 = 8192;
static const int WF_N2 = 9216;

__device__ __forceinline__ float* sel_out(int SEL, float* ext) {
    if (SEL == 1) return g_h0;
    if (SEL == 2) return g_h1;
    return ext;
}
__device__ __forceinline__ int edge_at(const void* ei, int i) {
    if (g_is64) return (int)((const long long*)ei)[i];
    return ((const int*)ei)[i];
}
__device__ __forceinline__ void mma_bf16(float* c, const uint32_t* a, const uint32_t* b) {
    asm volatile(
        "mma.sync.aligned.m16n8k16.row.col.f32.bf16.bf16.f32 "
        "{%0,%1,%2,%3}, {%4,%5,%6,%7}, {%8,%9}, {%0,%1,%2,%3};"
        : "+f"(c[0]), "+f"(c[1]), "+f"(c[2]), "+f"(c[3])
        : "r"(a[0]), "r"(a[1]), "r"(a[2]), "r"(a[3]), "r"(b[0]), "r"(b[1]));
}
__device__ __forceinline__ void split_bf16(float v, __nv_bfloat16& h, __nv_bfloat16& l) {
    h = __float2bfloat16(v);
    l = __float2bfloat16(v - __bfloat162float(h));
}
__device__ __forceinline__ void pack2(float a, float b, uint32_t& hw, uint32_t& lw) {
    __nv_bfloat16 ha, la, hb, lb;
    split_bf16(a, ha, la);
    split_bf16(b, hb, lb);
    __nv_bfloat162 ph; ph.x = ha; ph.y = hb;
    __nv_bfloat162 pl; pl.x = la; pl.y = lb;
    hw = *(uint32_t*)&ph;
    lw = *(uint32_t*)&pl;
}

// ---------------- dtype probe ----------------
__global__ void init_flag_kernel() { g_is64 = 1; }
__global__ void detect_kernel(const void* ei) {
    int i = blockIdx.x * blockDim.x + threadIdx.x;
    int bad = 0;
    if (i < 2 * NE) {
        long long v = ((const long long*)ei)[i];
        bad = (v < 0 || v >= NN) ? 1 : 0;
    }
    if (__syncthreads_or(bad)) {
        if (threadIdx.x == 0) g_is64 = 0;
    }
}

// ---------------- combined conv: x -> A frags, W* -> B frags (one launch) ----------------
__global__ void conv_all_kernel(const float* __restrict__ x,
                                const float* __restrict__ W0s, const float* __restrict__ W0n,
                                const float* __restrict__ W1s, const float* __restrict__ W1n,
                                const float* __restrict__ W2s, const float* __restrict__ W2n)
{
    if (blockIdx.x < NRB) {
        // ---- x -> A fragments ----
        const float2* src = (const float2*)x;
        int i = blockIdx.x * 256 + threadIdx.x;
        int rb = i >> 8, ks = (i >> 5) & 7, lane = i & 31;
        int r0 = rb * 16 + (lane >> 2), r1 = r0 + 8;
        int cp0 = ks * 8 + (lane & 3), cp1 = cp0 + 4;
        const float2 z = make_float2(0.f, 0.f);
        float2 v00 = (r0 < NN) ? src[(size_t)r0 * 64 + cp0] : z;
        float2 v10 = (r1 < NN) ? src[(size_t)r1 * 64 + cp0] : z;
        float2 v01 = (r0 < NN) ? src[(size_t)r0 * 64 + cp1] : z;
        float2 v11 = (r1 < NN) ? src[(size_t)r1 * 64 + cp1] : z;
        uint4 h, l;
        pack2(v00.x, v00.y, h.x, l.x);
        pack2(v10.x, v10.y, h.y, l.y);
        pack2(v01.x, v01.y, h.z, l.z);
        pack2(v11.x, v11.y, h.w, l.w);
        g_afh[i] = h;
        g_afl[i] = l;
    } else {
        // ---- weights -> B fragments ----
        int i = (blockIdx.x - NRB) * 256 + threadIdx.x;   // 0..10239
        if (i >= 10240) return;
        const float* src;
        int off, N;
        if      (i < 2048) { src = W0s; off = WF_S0; N = 128; }
        else if (i < 4096) { src = W0n; off = WF_N0; N = 128; }
        else if (i < 6144) { src = W1s; off = WF_S1; N = 128; }
        else if (i < 8192) { src = W1n; off = WF_N1; N = 128; }
        else if (i < 9216) { src = W2s; off = WF_S2; N = 64;  }
        else               { src = W2n; off = WF_N2; N = 64;  }
        int j = i - off;
        int lane = j & 31, ks = (j >> 5) & 7, n16 = j >> 8;
        int nE = n16 * 16 + (lane >> 2), nO = nE + 8;
        int k0 = ks * 16 + (lane & 3) * 2;
        uint4 h, l;
        pack2(src[(size_t)k0 * N + nE],       src[(size_t)(k0 + 1) * N + nE], h.x, l.x);
        pack2(src[(size_t)(k0 + 8) * N + nE], src[(size_t)(k0 + 9) * N + nE], h.y, l.y);
        pack2(src[(size_t)k0 * N + nO],       src[(size_t)(k0 + 1) * N + nO], h.z, l.z);
        pack2(src[(size_t)(k0 + 8) * N + nO], src[(size_t)(k0 + 9) * N + nO], h.w, l.w);
        g_wfh[i] = h;
        g_wfl[i] = l;
    }
}

// ---------------- CSR build ----------------
__global__ void zero_count_kernel() {
    int i = blockIdx.x * blockDim.x + threadIdx.x;
    if (i < NN) g_count[i] = 0;
}
__global__ void hist_kernel(const void* ei) {
    int i = blockIdx.x * blockDim.x + threadIdx.x;
    if (i < NE) {
        int d = edge_at(ei, NE + i);
        d = min(max(d, 0), NN - 1);
        atomicAdd(&g_count[d], 1);
    }
}

static const int SCAN_SEG = 512;
static const int SCAN_THR = 256;
static const int SCAN_NB  = (NN + SCAN_SEG - 1) / SCAN_SEG;  // 98

__global__ void scan1_kernel() {
    __shared__ int red[SCAN_THR];
    int b = blockIdx.x, t = threadIdx.x;
    int i0 = b * SCAN_SEG + 2 * t, i1 = i0 + 1;
    int s = 0;
    if (i0 < NN) s += g_count[i0];
    if (i1 < NN) s += g_count[i1];
    red[t] = s;
    __syncthreads();
    for (int d = SCAN_THR / 2; d > 0; d >>= 1) {
        if (t < d) red[t] += red[t + d];
        __syncthreads();
    }
    if (t == 0) g_bsum[b] = red[0];
}
__global__ void scan2_kernel() {
    __shared__ int sh[128];
    int t = threadIdx.x;
    sh[t] = (t < SCAN_NB) ? g_bsum[t] : 0;
    __syncthreads();
    for (int d = 1; d < 128; d <<= 1) {
        int v = sh[t];
        int u = (t >= d) ? sh[t - d] : 0;
        __syncthreads();
        sh[t] = v + u;
        __syncthreads();
    }
    if (t < SCAN_NB) g_bbase[t] = sh[t] - g_bsum[t];
    if (t == 127) g_offs[NN] = sh[127];
}
__global__ void scan3_kernel() {
    __shared__ int sh[SCAN_THR];
    int b = blockIdx.x, t = threadIdx.x;
    int i0 = b * SCAN_SEG + 2 * t, i1 = i0 + 1;
    int c0 = (i0 < NN) ? g_count[i0] : 0;
    int c1 = (i1 < NN) ? g_count[i1] : 0;
    int s = c0 + c1;
    sh[t] = s;
    __syncthreads();
    for (int d = 1; d < SCAN_THR; d <<= 1) {
        int v = sh[t];
        int u = (t >= d) ? sh[t - d] : 0;
        __syncthreads();
        sh[t] = v + u;
        __syncthreads();
    }
    int tb = g_bbase[b] + sh[t] - s;
    if (i0 < NN) { g_offs[i0] = tb;      g_cursor[i0] = tb;      g_invdeg[i0] = 1.0f / fmaxf((float)c0, 1.0f); }
    if (i1 < NN) { g_offs[i1] = tb + c0; g_cursor[i1] = tb + c0; g_invdeg[i1] = 1.0f / fmaxf((float)c1, 1.0f); }
}
__global__ void fill_kernel(const void* ei) {
    int i = blockIdx.x * blockDim.x + threadIdx.x;
    if (i < NE) {
        int s = edge_at(ei, i);
        int d = edge_at(ei, NE + i);
        s = min(max(s, 0), NN - 1);
        d = min(max(d, 0), NN - 1);
        int p = atomicAdd(&g_cursor[d], 1);
        g_srcs[p] = s;
    }
}

// ---------------- dual-accumulator HMMA GEMM, A-fragment double buffering ----------------
// grid (391). One CTA -> both outputs for 128 rows x NOUT cols.
template <int NOUT, int LOFF_S, int LOFF_N, int CSEL_S>
__global__ __launch_bounds__(512, 1) void sgemm_mma_kernel(
    const float* __restrict__ bias, float* __restrict__ Cext, int M)
{
    const int NT = NOUT / 32;
    float* CS = sel_out(CSEL_S, Cext);

    int tid = threadIdx.x, wid = tid >> 5, lane = tid & 31;
    int row0 = blockIdx.x * 128;
    int wm = wid & 3, wn = wid >> 2;
    int mrow = wm * 32;
    int ncol = wn * (NT * 8);
    int rbB = blockIdx.x * 8 + wm * 2;
    int n16_0 = ncol >> 4;

    float acc[2][2][NT][4];
#pragma unroll
    for (int mx = 0; mx < 2; mx++)
#pragma unroll
        for (int mt = 0; mt < 2; mt++)
#pragma unroll
            for (int nt = 0; nt < NT; nt++)
#pragma unroll
                for (int q = 0; q < 4; q++) acc[mx][mt][nt][q] = 0.f;

    size_t aBase0 = (size_t)(rbB + 0) * 8 * 32 + lane;
    size_t aBase1 = (size_t)(rbB + 1) * 8 * 32 + lane;

    // double-buffered A fragments
    uint4 ah0[2], ah1[2], al0[2], al1[2];
    ah0[0] = g_afh[aBase0];
    ah1[0] = g_afh[aBase1];
    al0[0] = g_afl[aBase0];
    al1[0] = g_afl[aBase1];

#pragma unroll
    for (int ks = 0; ks < 8; ks++) {
        int cur = ks & 1, nxt = cur ^ 1;
        if (ks < 7) {
            ah0[nxt] = g_afh[aBase0 + (ks + 1) * 32];
            ah1[nxt] = g_afh[aBase1 + (ks + 1) * 32];
            al0[nxt] = g_afl[aBase0 + (ks + 1) * 32];
            al1[nxt] = g_afl[aBase1 + (ks + 1) * 32];
        }
        const uint32_t* ah[2] = { (const uint32_t*)&ah0[cur], (const uint32_t*)&ah1[cur] };
        const uint32_t* al[2] = { (const uint32_t*)&al0[cur], (const uint32_t*)&al1[cur] };
#pragma unroll
        for (int p = 0; p < NT / 2; p++) {
            size_t bidx = (size_t)((n16_0 + p) * 8 + ks) * 32 + lane;
#pragma unroll
            for (int mx = 0; mx < 2; mx++) {
                int loff = mx ? LOFF_N : LOFF_S;
                uint4 BH = g_wfh[loff + bidx];
                uint4 BL = g_wfl[loff + bidx];
                const uint32_t* bh = (const uint32_t*)&BH;
                const uint32_t* bl = (const uint32_t*)&BL;
#pragma unroll
                for (int mt = 0; mt < 2; mt++)
#pragma unroll
                    for (int h = 0; h < 2; h++) {
                        float* a = acc[mx][mt][2 * p + h];
                        mma_bf16(a, ah[mt], &bh[h * 2]);
                        mma_bf16(a, ah[mt], &bl[h * 2]);
                        mma_bf16(a, al[mt], &bh[h * 2]);
                    }
            }
        }
    }

    // ---- epilogue: both outputs ----
#pragma unroll
    for (int mt = 0; mt < 2; mt++) {
        int r0g = row0 + mrow + mt * 16 + (lane >> 2);
        int r1g = r0g + 8;
#pragma unroll
        for (int nt = 0; nt < NT; nt++) {
            int cc = ncol + nt * 8 + (lane & 3) * 2;
            float bx = bias ? bias[cc] : 0.f;
            float by = bias ? bias[cc + 1] : 0.f;
            if (r0g < M) {
                float2 v;
                v.x = acc[0][mt][nt][0] + bx; v.y = acc[0][mt][nt][1] + by;
                *(float2*)(CS + (size_t)r0g * NOUT + cc) = v;
                v.x = acc[1][mt][nt][0]; v.y = acc[1][mt][nt][1];
                *(float2*)(g_y + (size_t)r0g * NOUT + cc) = v;
            }
            if (r1g < M) {
                float2 v;
                v.x = acc[0][mt][nt][2] + bx; v.y = acc[0][mt][nt][3] + by;
                *(float2*)(CS + (size_t)r1g * NOUT + cc) = v;
                v.x = acc[1][mt][nt][2]; v.y = acc[1][mt][nt][3];
                *(float2*)(g_y + (size_t)r1g * NOUT + cc) = v;
            }
        }
    }
}

// ---------------- fused aggregate + relu + A-fragment emission (layers 0/1) ----------------
template <int OSEL>
__global__ __launch_bounds__(512) void agg_frag_kernel()
{
    __shared__ float sh[16][132];
    const float4* yv = (const float4*)g_y;
    const float* self = (OSEL == 1) ? g_h0 : g_h1;

    int rb = blockIdx.x;
    int tid = threadIdx.x, w = tid >> 5, lane = tid & 31;
    int node = rb * 16 + w;

    float4 o = make_float4(0.f, 0.f, 0.f, 0.f);
    if (node < NN) {
        int s = g_offs[node], e = g_offs[node + 1];
        float4 acc = make_float4(0.f, 0.f, 0.f, 0.f);
        int i = s;
        for (; i + 3 < e; i += 4) {
            int s0 = g_srcs[i], s1 = g_srcs[i + 1], s2 = g_srcs[i + 2], s3 = g_srcs[i + 3];
            float4 v0 = yv[(size_t)s0 * 32 + lane];
            float4 v1 = yv[(size_t)s1 * 32 + lane];
            float4 v2 = yv[(size_t)s2 * 32 + lane];
            float4 v3 = yv[(size_t)s3 * 32 + lane];
            acc.x += (v0.x + v1.x) + (v2.x + v3.x);
            acc.y += (v0.y + v1.y) + (v2.y + v3.y);
            acc.z += (v0.z + v1.z) + (v2.z + v3.z);
            acc.w += (v0.w + v1.w) + (v2.w + v3.w);
        }
        for (; i < e; i++) {
            int s0 = g_srcs[i];
            float4 v0 = yv[(size_t)s0 * 32 + lane];
            acc.x += v0.x; acc.y += v0.y; acc.z += v0.z; acc.w += v0.w;
        }
        float wg = g_invdeg[node];
        float4 sf = ((const float4*)self)[(size_t)node * 32 + lane];
        o.x = fmaxf(sf.x + wg * acc.x, 0.f);
        o.y = fmaxf(sf.y + wg * acc.y, 0.f);
        o.z = fmaxf(sf.z + wg * acc.z, 0.f);
        o.w = fmaxf(sf.w + wg * acc.w, 0.f);
    }
    *(float4*)&sh[w][lane * 4] = o;
    __syncthreads();

    if (tid < 256) {
        int ks = tid >> 5, lf = tid & 31;
        int r0 = lf >> 2, r1 = r0 + 8;
        int cp0 = ks * 8 + (lf & 3), cp1 = cp0 + 4;
        uint4 h, l;
        pack2(sh[r0][cp0 * 2], sh[r0][cp0 * 2 + 1], h.x, l.x);
        pack2(sh[r1][cp0 * 2], sh[r1][cp0 * 2 + 1], h.y, l.y);
        pack2(sh[r0][cp1 * 2], sh[r0][cp1 * 2 + 1], h.z, l.z);
        pack2(sh[r1][cp1 * 2], sh[r1][cp1 * 2 + 1], h.w, l.w);
        size_t idx = (size_t)(rb * 8 + ks) * 32 + lf;
        g_afh[idx] = h;
        g_afl[idx] = l;
    }
}

// ---------------- final aggregate (D=64, writes d_out, no relu) ----------------
__global__ void agg_final_kernel(float* __restrict__ out)
{
    const float4* yv = (const float4*)g_y;
    const int CH = 16;
    int gt   = blockIdx.x * blockDim.x + threadIdx.x;
    int warp = gt >> 5;
    int lane = gt & 31;
    int node = warp * 2 + lane / CH;
    int c    = lane % CH;
    if (node >= NN) return;

    int s = g_offs[node], e = g_offs[node + 1];
    float4 acc = make_float4(0.f, 0.f, 0.f, 0.f);
    int i = s;
    for (; i + 3 < e; i += 4) {
        int s0 = g_srcs[i], s1 = g_srcs[i + 1], s2 = g_srcs[i + 2], s3 = g_srcs[i + 3];
        float4 v0 = yv[(size_t)s0 * CH + c];
        float4 v1 = yv[(size_t)s1 * CH + c];
        float4 v2 = yv[(size_t)s2 * CH + c];
        float4 v3 = yv[(size_t)s3 * CH + c];
        acc.x += (v0.x + v1.x) + (v2.x + v3.x);
        acc.y += (v0.y + v1.y) + (v2.y + v3.y);
        acc.z += (v0.z + v1.z) + (v2.z + v3.z);
        acc.w += (v0.w + v1.w) + (v2.w + v3.w);
    }
    for (; i < e; i++) {
        int s0 = g_srcs[i];
        float4 v0 = yv[(size_t)s0 * CH + c];
        acc.x += v0.x; acc.y += v0.y; acc.z += v0.z; acc.w += v0.w;
    }
    float w = g_invdeg[node];
    float4* op = (float4*)out + (size_t)node * CH + c;
    float4 o = *op;
    o.x += w * acc.x; o.y += w * acc.y; o.z += w * acc.z; o.w += w * acc.w;
    *op = o;
}

// ---------------- launch ----------------
extern "C" void kernel_launch(void* const* d_in, const int* in_sizes, int n_in,
                              void* d_out, int out_size)
{
    const float* x   = (const float*)d_in[0];
    const void*  ei  = d_in[1];
    const float* Ws0 = (const float*)d_in[2];
    const float* Wn0 = (const float*)d_in[3];
    const float* b0  = (const float*)d_in[4];
    const float* Ws1 = (const float*)d_in[5];
    const float* Wn1 = (const float*)d_in[6];
    const float* b1  = (const float*)d_in[7];
    const float* Ws2 = (const float*)d_in[8];
    const float* Wn2 = (const float*)d_in[9];
    const float* b2  = (const float*)d_in[10];
    float* out = (float*)d_out;

    const int tb = 256;

    // fork-join: CSR build overlaps conv+GEMM0 on a side stream
    cudaStream_t s2;
    cudaStreamCreateWithFlags(&s2, cudaStreamNonBlocking);
    cudaEvent_t evF, evJ;
    cudaEventCreateWithFlags(&evF, cudaEventDisableTiming);
    cudaEventCreateWithFlags(&evJ, cudaEventDisableTiming);

    init_flag_kernel<<<1, 1>>>();
    detect_kernel<<<(2 * NE + tb - 1) / tb, tb>>>(ei);
    cudaEventRecord(evF, 0);
    cudaStreamWaitEvent(s2, evF, 0);

    // side stream: CSR build
    zero_count_kernel<<<(NN + tb - 1) / tb, tb, 0, s2>>>();
    hist_kernel<<<(NE + tb - 1) / tb, tb, 0, s2>>>(ei);
    scan1_kernel<<<SCAN_NB, SCAN_THR, 0, s2>>>();
    scan2_kernel<<<1, 128, 0, s2>>>();
    scan3_kernel<<<SCAN_NB, SCAN_THR, 0, s2>>>();
    fill_kernel<<<(NE + tb - 1) / tb, tb, 0, s2>>>(ei);
    cudaEventRecord(evJ, s2);

    // main stream: combined conversions + layer-0 GEMM (overlapped with CSR)
    conv_all_kernel<<<NRB + 40, 256>>>(x, Ws0, Wn0, Ws1, Wn1, Ws2, Wn2);
    sgemm_mma_kernel<128, WF_S0, WF_N0, 1><<<391, 512>>>(b0, nullptr, NN);
    cudaStreamWaitEvent(0, evJ, 0);

    agg_frag_kernel<1><<<NRB, 512>>>();
    sgemm_mma_kernel<128, WF_S1, WF_N1, 2><<<391, 512>>>(b1, nullptr, NN);
    agg_frag_kernel<2><<<NRB, 512>>>();
    sgemm_mma_kernel<64, WF_S2, WF_N2, 0><<<391, 512>>>(b2, out, NN);
    agg_final_kernel<<<(NN * 16 + 255) / 256, 256>>>(out);
}